// round 3
// baseline (speedup 1.0000x reference)
#include <cuda_runtime.h>
#include <cuda_bf16.h>
#include <cstdint>

#define N_LAYER  4
#define D_MODEL  1024
#define D_STATE  128
#define D_CONV   4
#define HEADDIM  64
#define NHEADS   32
#define D_INNER  2048
#define CONV_DIM 2304         // D_INNER + 2*D_STATE
#define D_IN_PROJ 4384        // 2*D_INNER + 2*D_STATE + NHEADS
#define LSEQ     1024
#define VOCAB    50288
#define EPS      1e-5f

// ---------------- scratch (static device globals; no allocation) -------------
__device__ float g_x  [LSEQ * D_MODEL];    // residual stream
__device__ float g_zx [LSEQ * D_IN_PROJ];  // in_proj output
__device__ float g_xbc[LSEQ * CONV_DIM];   // conv+silu output
__device__ float g_dt [LSEQ * NHEADS];     // softplus dt
__device__ float g_y  [LSEQ * D_INNER];    // ssd output

// bf16 hi/lo split storage
__device__ __nv_bfloat16 g_emb_hi [VOCAB * D_MODEL];
__device__ __nv_bfloat16 g_emb_lo [VOCAB * D_MODEL];
__device__ __nv_bfloat16 g_inw_hi [N_LAYER * D_IN_PROJ * D_MODEL];
__device__ __nv_bfloat16 g_inw_lo [N_LAYER * D_IN_PROJ * D_MODEL];
__device__ __nv_bfloat16 g_outw_hi[N_LAYER * D_MODEL * D_INNER];
__device__ __nv_bfloat16 g_outw_lo[N_LAYER * D_MODEL * D_INNER];
__device__ __nv_bfloat16 g_u_hi   [LSEQ * D_MODEL];
__device__ __nv_bfloat16 g_u_lo   [LSEQ * D_MODEL];
__device__ __nv_bfloat16 g_t2_hi  [LSEQ * D_INNER];
__device__ __nv_bfloat16 g_t2_lo  [LSEQ * D_INNER];

// ---------------- fp32 -> bf16 hi/lo split -----------------------------------
__global__ void split_kernel(const float4* __restrict__ in,
                             __nv_bfloat162* __restrict__ hi,
                             __nv_bfloat162* __restrict__ lo, int n4) {
    int i = blockIdx.x * blockDim.x + threadIdx.x;
    if (i >= n4) return;
    float4 v = in[i];
    __nv_bfloat162 h01 = __floats2bfloat162_rn(v.x, v.y);
    __nv_bfloat162 h23 = __floats2bfloat162_rn(v.z, v.w);
    hi[2 * i]     = h01;
    hi[2 * i + 1] = h23;
    lo[2 * i]     = __floats2bfloat162_rn(v.x - __low2float(h01), v.y - __high2float(h01));
    lo[2 * i + 1] = __floats2bfloat162_rn(v.z - __low2float(h23), v.w - __high2float(h23));
}

// ---------------- embedding gather ------------------------------------------
__global__ void embed_kernel(const int* __restrict__ ids,
                             const float* __restrict__ emb,
                             float* __restrict__ x) {
    int idx = blockIdx.x * blockDim.x + threadIdx.x;
    if (idx >= LSEQ * D_MODEL) return;
    int t = idx >> 10;
    int d = idx & 1023;
    x[idx] = emb[(size_t)ids[t] * D_MODEL + d];
}

// ---------------- rmsnorm (optionally gated); outputs bf16 hi/lo -------------
__global__ void rmsnorm_kernel(const float* __restrict__ x, int xs,
                               const float* __restrict__ w,
                               const float* z, int zs,
                               __nv_bfloat16* __restrict__ out_hi,
                               __nv_bfloat16* __restrict__ out_lo, int D) {
    __shared__ float buf[2048];
    __shared__ float red[8];
    __shared__ float s_scale;
    int t = blockIdx.x;
    int tid = threadIdx.x;

    float ss = 0.f;
    for (int c = tid; c < D; c += blockDim.x) {
        float v = x[(size_t)t * xs + c];
        if (z) {
            float zz = z[(size_t)t * zs + c];
            v *= zz / (1.f + expf(-zz));
        }
        buf[c] = v;
        ss += v * v;
    }
    #pragma unroll
    for (int o = 16; o; o >>= 1) ss += __shfl_xor_sync(0xffffffffu, ss, o);
    if ((tid & 31) == 0) red[tid >> 5] = ss;
    __syncthreads();
    if (tid < 32) {
        float v = (tid < 8) ? red[tid] : 0.f;
        #pragma unroll
        for (int o = 4; o; o >>= 1) v += __shfl_xor_sync(0xffffffffu, v, o);
        if (tid == 0) s_scale = rsqrtf(v / (float)D + EPS);
    }
    __syncthreads();
    float sc = s_scale;
    for (int c = tid; c < D; c += blockDim.x) {
        float v = buf[c] * sc * w[c];
        __nv_bfloat16 h = __float2bfloat16(v);
        out_hi[(size_t)t * D + c] = h;
        out_lo[(size_t)t * D + c] = __float2bfloat16(v - __bfloat162float(h));
    }
}

// ---------------- dt = softplus(raw + bias) ----------------------------------
__global__ void dt_kernel(const float* __restrict__ zx,
                          const float* __restrict__ dt_bias,
                          float* __restrict__ dt) {
    int idx = blockIdx.x * blockDim.x + threadIdx.x;
    if (idx >= LSEQ * NHEADS) return;
    int t = idx >> 5;
    int h = idx & 31;
    float v = zx[(size_t)t * D_IN_PROJ + (D_INNER + CONV_DIM) + h] + dt_bias[h];
    dt[idx] = (v > 20.f) ? v : log1pf(expf(v));
}

// ---------------- depthwise causal conv (width 4) + silu ---------------------
__global__ void conv_kernel(const float* __restrict__ zx,
                            const float* __restrict__ w,
                            const float* __restrict__ b,
                            float* __restrict__ out) {
    int idx = blockIdx.x * blockDim.x + threadIdx.x;
    if (idx >= LSEQ * CONV_DIM) return;
    int t = idx / CONV_DIM;
    int c = idx - t * CONV_DIM;
    float acc = b[c];
    const float* wc = w + c * 4;
    #pragma unroll
    for (int j = 0; j < 4; ++j) {
        int tt = t - 3 + j;
        if (tt >= 0) acc += zx[(size_t)tt * D_IN_PROJ + D_INNER + c] * wc[j];
    }
    out[idx] = acc / (1.f + expf(-acc));   // silu
}

// ---------------- SSD sequential recurrence ----------------------------------
__global__ void ssd_kernel(const float* __restrict__ xbc,
                           const float* __restrict__ dt,
                           const float* __restrict__ A_log,
                           const float* __restrict__ D_p,
                           float* __restrict__ y) {
    int h  = blockIdx.x >> 3;
    int pg = blockIdx.x & 7;
    int tid = threadIdx.x;
    int w = tid >> 5;           // p within group
    int l = tid & 31;           // lane -> n base
    int p = pg * 8 + w;

    __shared__ float Bs[128], Cs[128];

    float h0 = 0.f, h1 = 0.f, h2 = 0.f, h3 = 0.f;
    float Ah = -expf(A_log[h]);
    float Dh = D_p[h];

    for (int t = 0; t < LSEQ; ++t) {
        const float* row = xbc + (size_t)t * CONV_DIM;
        __syncthreads();
        if (tid < 128) Bs[tid] = row[D_INNER + tid];
        else           Cs[tid - 128] = row[D_INNER + D_STATE + (tid - 128)];
        __syncthreads();

        float dtv  = dt[t * NHEADS + h];
        float e    = expf(Ah * dtv);
        float xraw = row[h * HEADDIM + p];
        float xv   = xraw * dtv;

        float acc;
        h0 = e * h0 + Bs[l      ] * xv;
        h1 = e * h1 + Bs[l + 32 ] * xv;
        h2 = e * h2 + Bs[l + 64 ] * xv;
        h3 = e * h3 + Bs[l + 96 ] * xv;
        acc  = Cs[l      ] * h0;
        acc += Cs[l + 32 ] * h1;
        acc += Cs[l + 64 ] * h2;
        acc += Cs[l + 96 ] * h3;
        #pragma unroll
        for (int o = 16; o; o >>= 1) acc += __shfl_xor_sync(0xffffffffu, acc, o);
        if (l == 0) y[(size_t)t * D_INNER + h * HEADDIM + p] = acc + xraw * Dh;
    }
}

// =============================================================================
// bf16x3 tensor-core GEMM (NT), pre-split inputs, 4-stage cp.async pipeline.
// C[m,n] = sum_k A[m,k]*B[n,k] (+ add), A/B given as bf16 hi+lo pairs.
// BM=128, BN=128, BK=32, 256 threads (8 warps: 4 in M x 2 in N).
// grid = (M/BM, ceil(N/BN)) so consecutive blocks share a B tile (L2 reuse).
// =============================================================================
#define BM 128
#define BN 128
#define BKK 32
#define LDSB 40            // padded smem stride (80B) -> conflict-free ldmatrix
#define STG 4
#define TILE_E (BM * LDSB) // elems per sub-array per stage
#define GEMM_SMEM (STG * 4 * TILE_E * 2)  // bytes = 160 KB

#define LDSM4(R, addr) asm volatile( \
    "ldmatrix.sync.aligned.m8n8.x4.shared.b16 {%0,%1,%2,%3}, [%4];" \
    : "=r"((R)[0]),"=r"((R)[1]),"=r"((R)[2]),"=r"((R)[3]) : "r"(addr))
#define LDSM2(R, addr) asm volatile( \
    "ldmatrix.sync.aligned.m8n8.x2.shared.b16 {%0,%1}, [%2];" \
    : "=r"((R)[0]),"=r"((R)[1]) : "r"(addr))
#define MMA_BF16(acc, a, b) asm volatile( \
    "mma.sync.aligned.m16n8k16.row.col.f32.bf16.bf16.f32 " \
    "{%0,%1,%2,%3},{%4,%5,%6,%7},{%8,%9},{%0,%1,%2,%3};" \
    : "+f"((acc)[0]),"+f"((acc)[1]),"+f"((acc)[2]),"+f"((acc)[3]) \
    : "r"((a)[0]),"r"((a)[1]),"r"((a)[2]),"r"((a)[3]),"r"((b)[0]),"r"((b)[1]))

__device__ __forceinline__ uint32_t smem_u32(const void* p) {
    return (uint32_t)__cvta_generic_to_shared(p);
}
__device__ __forceinline__ void cpa16(uint32_t dst, const void* src, int sz) {
    asm volatile("cp.async.ca.shared.global [%0], [%1], 16, %2;"
                 :: "r"(dst), "l"(src), "r"(sz));
}

__global__ __launch_bounds__(256) void gemm_bf16x3(
    const __nv_bfloat16* __restrict__ Ahi, const __nv_bfloat16* __restrict__ Alo,
    const __nv_bfloat16* __restrict__ Bhi, const __nv_bfloat16* __restrict__ Blo,
    const float* add, float* __restrict__ C, int M, int N, int K) {
    extern __shared__ __nv_bfloat16 smem[];

    int tid  = threadIdx.x;
    int wid  = tid >> 5, lane = tid & 31;
    int wm   = wid & 3;
    int wn   = wid >> 2;
    int bm   = blockIdx.x * BM;
    int bn   = blockIdx.y * BN;

    // ---- async load mapping: 2 threads per row, 16 elems (32B) each ----
    int lrow = tid >> 1;
    int lk   = (tid & 1) * 16;
    const __nv_bfloat16* gA0 = Ahi + (size_t)(bm + lrow) * K + lk;
    const __nv_bfloat16* gA1 = Alo + (size_t)(bm + lrow) * K + lk;
    int brow  = bn + lrow;
    int bok   = (brow < N) ? 16 : 0;
    int browc = (brow < N) ? brow : (N - 1);
    const __nv_bfloat16* gB0 = Bhi + (size_t)browc * K + lk;
    const __nv_bfloat16* gB1 = Blo + (size_t)browc * K + lk;
    uint32_t sbase = smem_u32(smem);
    uint32_t soff  = (uint32_t)(lrow * LDSB + lk) * 2;

    #define ISSUE(t, s) do {                                                   \
        uint32_t d = sbase + (uint32_t)(s) * (4 * TILE_E * 2) + soff;          \
        const __nv_bfloat16* a0 = gA0 + (size_t)(t) * BKK;                     \
        const __nv_bfloat16* a1 = gA1 + (size_t)(t) * BKK;                     \
        const __nv_bfloat16* b0 = gB0 + (size_t)(t) * BKK;                     \
        const __nv_bfloat16* b1 = gB1 + (size_t)(t) * BKK;                     \
        cpa16(d,                    a0,     16);                               \
        cpa16(d + 16,               a0 + 8, 16);                               \
        cpa16(d + TILE_E * 2,       a1,     16);                               \
        cpa16(d + TILE_E * 2 + 16,  a1 + 8, 16);                               \
        cpa16(d + 2 * TILE_E * 2,      b0,     bok);                           \
        cpa16(d + 2 * TILE_E * 2 + 16, b0 + 8, bok);                           \
        cpa16(d + 3 * TILE_E * 2,      b1,     bok);                           \
        cpa16(d + 3 * TILE_E * 2 + 16, b1 + 8, bok);                           \
    } while (0)

    float acc[2][8][4];
    #pragma unroll
    for (int i = 0; i < 2; ++i)
        #pragma unroll
        for (int j = 0; j < 8; ++j)
            #pragma unroll
            for (int q = 0; q < 4; ++q) acc[i][j][q] = 0.f;

    int T = K / BKK;
    #pragma unroll
    for (int s = 0; s < STG - 1; ++s) {
        if (s < T) ISSUE(s, s);
        asm volatile("cp.async.commit_group;");
    }

    int mrow      = wm * 32 + (lane & 15);
    int acol_half = ((lane >> 4) << 3);
    int nrow_base = wn * 64 + (lane & 7);
    int bcol_half = ((lane >> 3) & 1) << 3;

    for (int it = 0; it < T; ++it) {
        asm volatile("cp.async.wait_group %0;" :: "n"(STG - 2));
        __syncthreads();
        if (it + STG - 1 < T) ISSUE(it + STG - 1, (it + STG - 1) & 3);
        asm volatile("cp.async.commit_group;");

        const __nv_bfloat16* sAhi = smem + (size_t)(it & 3) * (4 * TILE_E);
        const __nv_bfloat16* sAlo = sAhi + TILE_E;
        const __nv_bfloat16* sBhi = sAhi + 2 * TILE_E;
        const __nv_bfloat16* sBlo = sAhi + 3 * TILE_E;

        #pragma unroll
        for (int ks = 0; ks < 2; ++ks) {
            int kb = ks * 16;
            uint32_t ahi[2][4], alo[2][4];
            #pragma unroll
            for (int mi = 0; mi < 2; ++mi) {
                int off = (mrow + mi * 16) * LDSB + kb + acol_half;
                LDSM4(ahi[mi], smem_u32(&sAhi[off]));
                LDSM4(alo[mi], smem_u32(&sAlo[off]));
            }
            uint32_t bhi[8][2], blo[8][2];
            #pragma unroll
            for (int ni = 0; ni < 8; ++ni) {
                int off = (nrow_base + ni * 8) * LDSB + kb + bcol_half;
                LDSM2(bhi[ni], smem_u32(&sBhi[off]));
                LDSM2(blo[ni], smem_u32(&sBlo[off]));
            }
            #pragma unroll
            for (int mi = 0; mi < 2; ++mi)
                #pragma unroll
                for (int ni = 0; ni < 8; ++ni) {
                    MMA_BF16(acc[mi][ni], ahi[mi], bhi[ni]);
                    MMA_BF16(acc[mi][ni], ahi[mi], blo[ni]);
                    MMA_BF16(acc[mi][ni], alo[mi], bhi[ni]);
                }
        }
    }

    // --- epilogue ---
    int g = lane >> 2, t4 = lane & 3;
    #pragma unroll
    for (int mi = 0; mi < 2; ++mi) {
        int r0 = bm + wm * 32 + mi * 16 + g;
        #pragma unroll
        for (int ni = 0; ni < 8; ++ni) {
            int col = bn + wn * 64 + ni * 8 + t4 * 2;
            if (col < N) {     // N even, col even -> covers col+1 too
                float2 v0 = make_float2(acc[mi][ni][0], acc[mi][ni][1]);
                float2 v1 = make_float2(acc[mi][ni][2], acc[mi][ni][3]);
                if (add) {
                    float2 a0 = *(const float2*)(add + (size_t)r0 * N + col);
                    float2 a1 = *(const float2*)(add + (size_t)(r0 + 8) * N + col);
                    v0.x += a0.x; v0.y += a0.y;
                    v1.x += a1.x; v1.y += a1.y;
                }
                *(float2*)(C + (size_t)r0 * N + col)       = v0;
                *(float2*)(C + (size_t)(r0 + 8) * N + col) = v1;
            }
        }
    }
}

// ---------------- orchestration ----------------------------------------------
extern "C" void kernel_launch(void* const* d_in, const int* in_sizes, int n_in,
                              void* d_out, int out_size) {
    const int*   ids       = (const int*)  d_in[0];
    const float* emb       = (const float*)d_in[1];
    const float* norm_ws   = (const float*)d_in[2];
    const float* in_ws     = (const float*)d_in[3];
    const float* conv_ws   = (const float*)d_in[4];
    const float* conv_bs   = (const float*)d_in[5];
    const float* dt_biases = (const float*)d_in[6];
    const float* A_logs    = (const float*)d_in[7];
    const float* Ds        = (const float*)d_in[8];
    const float* gnorm_ws  = (const float*)d_in[9];
    const float* out_ws    = (const float*)d_in[10];
    const float* norm_f_w  = (const float*)d_in[11];
    float* out = (float*)d_out;

    float *x, *zx, *xbc, *dtb, *y;
    cudaGetSymbolAddress((void**)&x,   g_x);
    cudaGetSymbolAddress((void**)&zx,  g_zx);
    cudaGetSymbolAddress((void**)&xbc, g_xbc);
    cudaGetSymbolAddress((void**)&dtb, g_dt);
    cudaGetSymbolAddress((void**)&y,   g_y);

    __nv_bfloat16 *emb_hi, *emb_lo, *inw_hi, *inw_lo, *outw_hi, *outw_lo;
    __nv_bfloat16 *u_hi, *u_lo, *t2_hi, *t2_lo;
    cudaGetSymbolAddress((void**)&emb_hi,  g_emb_hi);
    cudaGetSymbolAddress((void**)&emb_lo,  g_emb_lo);
    cudaGetSymbolAddress((void**)&inw_hi,  g_inw_hi);
    cudaGetSymbolAddress((void**)&inw_lo,  g_inw_lo);
    cudaGetSymbolAddress((void**)&outw_hi, g_outw_hi);
    cudaGetSymbolAddress((void**)&outw_lo, g_outw_lo);
    cudaGetSymbolAddress((void**)&u_hi,    g_u_hi);
    cudaGetSymbolAddress((void**)&u_lo,    g_u_lo);
    cudaGetSymbolAddress((void**)&t2_hi,   g_t2_hi);
    cudaGetSymbolAddress((void**)&t2_lo,   g_t2_lo);

    cudaFuncSetAttribute(gemm_bf16x3,
                         cudaFuncAttributeMaxDynamicSharedMemorySize, GEMM_SMEM);

    // ---- pre-split weights/embedding to bf16 hi/lo ----
    {
        int n4 = VOCAB * D_MODEL / 4;
        split_kernel<<<(n4 + 255) / 256, 256>>>(
            (const float4*)emb, (__nv_bfloat162*)emb_hi, (__nv_bfloat162*)emb_lo, n4);
        n4 = N_LAYER * D_IN_PROJ * D_MODEL / 4;
        split_kernel<<<(n4 + 255) / 256, 256>>>(
            (const float4*)in_ws, (__nv_bfloat162*)inw_hi, (__nv_bfloat162*)inw_lo, n4);
        n4 = N_LAYER * D_MODEL * D_INNER / 4;
        split_kernel<<<(n4 + 255) / 256, 256>>>(
            (const float4*)out_ws, (__nv_bfloat162*)outw_hi, (__nv_bfloat162*)outw_lo, n4);
    }

    embed_kernel<<<(LSEQ * D_MODEL + 255) / 256, 256>>>(ids, emb, x);

    for (int i = 0; i < N_LAYER; ++i) {
        rmsnorm_kernel<<<LSEQ, 256>>>(x, D_MODEL, norm_ws + (size_t)i * D_MODEL,
                                      nullptr, 0, u_hi, u_lo, D_MODEL);
        // in_proj
        gemm_bf16x3<<<dim3(LSEQ / BM, (D_IN_PROJ + BN - 1) / BN), 256, GEMM_SMEM>>>(
            u_hi, u_lo,
            inw_hi + (size_t)i * D_IN_PROJ * D_MODEL,
            inw_lo + (size_t)i * D_IN_PROJ * D_MODEL,
            nullptr, zx, LSEQ, D_IN_PROJ, D_MODEL);
        dt_kernel<<<(LSEQ * NHEADS + 255) / 256, 256>>>(
            zx, dt_biases + (size_t)i * NHEADS, dtb);
        conv_kernel<<<(LSEQ * CONV_DIM + 255) / 256, 256>>>(
            zx, conv_ws + (size_t)i * CONV_DIM * D_CONV,
            conv_bs + (size_t)i * CONV_DIM, xbc);
        ssd_kernel<<<NHEADS * 8, 256>>>(
            xbc, dtb, A_logs + (size_t)i * NHEADS, Ds + (size_t)i * NHEADS, y);
        rmsnorm_kernel<<<LSEQ, 256>>>(y, D_INNER, gnorm_ws + (size_t)i * D_INNER,
                                      zx, D_IN_PROJ, t2_hi, t2_lo, D_INNER);
        // out_proj + residual
        gemm_bf16x3<<<dim3(LSEQ / BM, D_MODEL / BN), 256, GEMM_SMEM>>>(
            t2_hi, t2_lo,
            outw_hi + (size_t)i * D_MODEL * D_INNER,
            outw_lo + (size_t)i * D_MODEL * D_INNER,
            x, x, LSEQ, D_MODEL, D_INNER);
    }

    // final norm + logits
    rmsnorm_kernel<<<LSEQ, 256>>>(x, D_MODEL, norm_f_w, nullptr, 0,
                                  u_hi, u_lo, D_MODEL);
    gemm_bf16x3<<<dim3(LSEQ / BM, (VOCAB + BN - 1) / BN), 256, GEMM_SMEM>>>(
        u_hi, u_lo, emb_hi, emb_lo, nullptr, out, LSEQ, VOCAB, D_MODEL);
}

// round 5
// speedup vs baseline: 1.2940x; 1.2940x over previous
#include <cuda_runtime.h>
#include <cuda_bf16.h>
#include <cuda_fp16.h>
#include <cstdint>

#define N_LAYER  4
#define D_MODEL  1024
#define D_STATE  128
#define D_CONV   4
#define HEADDIM  64
#define NHEADS   32
#define D_INNER  2048
#define CONV_DIM 2304         // D_INNER + 2*D_STATE
#define D_IN_PROJ 4384        // 2*D_INNER + 2*D_STATE + NHEADS
#define LSEQ     1024
#define VOCAB    50288
#define EPS      1e-5f

// ---------------- scratch (static device globals; no allocation) -------------
__device__ float g_x  [LSEQ * D_MODEL];
__device__ float g_zx [LSEQ * D_IN_PROJ];
__device__ float g_xbc[LSEQ * CONV_DIM];
__device__ float g_dt [LSEQ * NHEADS];
__device__ float g_y  [LSEQ * D_INNER];

// split storage (raw 16-bit; interpreted as bf16 or fp16 per use)
__device__ unsigned short g_emb_h [VOCAB * D_MODEL];              // fp16 (hi only)
__device__ unsigned short g_inw_hi [N_LAYER * D_IN_PROJ * D_MODEL]; // bf16
__device__ unsigned short g_inw_lo [N_LAYER * D_IN_PROJ * D_MODEL];
__device__ unsigned short g_outw_hi[N_LAYER * D_MODEL * D_INNER];   // bf16
__device__ unsigned short g_outw_lo[N_LAYER * D_MODEL * D_INNER];
__device__ unsigned short g_u_hi  [LSEQ * D_MODEL];   // bf16 (layers) / fp16 (final)
__device__ unsigned short g_u_lo  [LSEQ * D_MODEL];
__device__ unsigned short g_t2_hi [LSEQ * D_INNER];   // bf16
__device__ unsigned short g_t2_lo [LSEQ * D_INNER];

// ---------------- fp32 -> bf16 hi/lo split -----------------------------------
__global__ void split_bf16_kernel(const float4* __restrict__ in,
                                  __nv_bfloat162* __restrict__ hi,
                                  __nv_bfloat162* __restrict__ lo, int n4) {
    int i = blockIdx.x * blockDim.x + threadIdx.x;
    if (i >= n4) return;
    float4 v = in[i];
    __nv_bfloat162 h01 = __floats2bfloat162_rn(v.x, v.y);
    __nv_bfloat162 h23 = __floats2bfloat162_rn(v.z, v.w);
    hi[2 * i]     = h01;
    hi[2 * i + 1] = h23;
    lo[2 * i]     = __floats2bfloat162_rn(v.x - __low2float(h01), v.y - __high2float(h01));
    lo[2 * i + 1] = __floats2bfloat162_rn(v.z - __low2float(h23), v.w - __high2float(h23));
}

// ---------------- fp32 -> fp16 (single) ---------------------------------------
__global__ void cvt_half_kernel(const float4* __restrict__ in,
                                __half2* __restrict__ out, int n4) {
    int i = blockIdx.x * blockDim.x + threadIdx.x;
    if (i >= n4) return;
    float4 v = in[i];
    out[2 * i]     = __floats2half2_rn(v.x, v.y);
    out[2 * i + 1] = __floats2half2_rn(v.z, v.w);
}

// ---------------- embedding gather ------------------------------------------
__global__ void embed_kernel(const int* __restrict__ ids,
                             const float* __restrict__ emb,
                             float* __restrict__ x) {
    int idx = blockIdx.x * blockDim.x + threadIdx.x;
    if (idx >= LSEQ * D_MODEL) return;
    int t = idx >> 10;
    int d = idx & 1023;
    x[idx] = emb[(size_t)ids[t] * D_MODEL + d];
}

// ---------------- rmsnorm (optionally gated); outputs hi/lo pair -------------
template<typename T>
__global__ void rmsnorm_kernel(const float* __restrict__ x, int xs,
                               const float* __restrict__ w,
                               const float* z, int zs,
                               unsigned short* __restrict__ out_hi,
                               unsigned short* __restrict__ out_lo, int D) {
    __shared__ float buf[2048];
    __shared__ float red[8];
    __shared__ float s_scale;
    int t = blockIdx.x;
    int tid = threadIdx.x;

    float ss = 0.f;
    for (int c = tid; c < D; c += blockDim.x) {
        float v = x[(size_t)t * xs + c];
        if (z) {
            float zz = z[(size_t)t * zs + c];
            v *= zz / (1.f + expf(-zz));
        }
        buf[c] = v;
        ss += v * v;
    }
    #pragma unroll
    for (int o = 16; o; o >>= 1) ss += __shfl_xor_sync(0xffffffffu, ss, o);
    if ((tid & 31) == 0) red[tid >> 5] = ss;
    __syncthreads();
    if (tid < 32) {
        float v = (tid < 8) ? red[tid] : 0.f;
        #pragma unroll
        for (int o = 4; o; o >>= 1) v += __shfl_xor_sync(0xffffffffu, v, o);
        if (tid == 0) s_scale = rsqrtf(v / (float)D + EPS);
    }
    __syncthreads();
    float sc = s_scale;
    for (int c = tid; c < D; c += blockDim.x) {
        float v = buf[c] * sc * w[c];
        T h = (T)v;
        float hf = (float)h;
        T l = (T)(v - hf);
        out_hi[(size_t)t * D + c] = *(unsigned short*)&h;
        out_lo[(size_t)t * D + c] = *(unsigned short*)&l;
    }
}

// ---------------- dt = softplus(raw + bias) ----------------------------------
__global__ void dt_kernel(const float* __restrict__ zx,
                          const float* __restrict__ dt_bias,
                          float* __restrict__ dt) {
    int idx = blockIdx.x * blockDim.x + threadIdx.x;
    if (idx >= LSEQ * NHEADS) return;
    int t = idx >> 5;
    int h = idx & 31;
    float v = zx[(size_t)t * D_IN_PROJ + (D_INNER + CONV_DIM) + h] + dt_bias[h];
    dt[idx] = (v > 20.f) ? v : log1pf(expf(v));
}

// ---------------- depthwise causal conv (width 4) + silu ---------------------
__global__ void conv_kernel(const float* __restrict__ zx,
                            const float* __restrict__ w,
                            const float* __restrict__ b,
                            float* __restrict__ out) {
    int idx = blockIdx.x * blockDim.x + threadIdx.x;
    if (idx >= LSEQ * CONV_DIM) return;
    int t = idx / CONV_DIM;
    int c = idx - t * CONV_DIM;
    float acc = b[c];
    const float* wc = w + c * 4;
    #pragma unroll
    for (int j = 0; j < 4; ++j) {
        int tt = t - 3 + j;
        if (tt >= 0) acc += zx[(size_t)tt * D_IN_PROJ + D_INNER + c] * wc[j];
    }
    out[idx] = acc / (1.f + expf(-acc));
}

// ---------------- SSD scan: warp per (h,p), no smem, reg ring prefetch -------
__global__ void ssd_kernel(const float* __restrict__ xbc,
                           const float* __restrict__ dt,
                           const float* __restrict__ A_log,
                           const float* __restrict__ D_p,
                           float* __restrict__ y) {
    int gw   = (blockIdx.x * blockDim.x + threadIdx.x) >> 5;  // 0..2047
    int lane = threadIdx.x & 31;
    int h = gw >> 6;          // head
    int p = gw & 63;          // channel within head

    float Ah = -expf(A_log[h]);
    float Dh = D_p[h];
    float hs0 = 0.f, hs1 = 0.f, hs2 = 0.f, hs3 = 0.f;

    float rB[3][4], rC[3][4], rX[3], rDT[3];
    #pragma unroll
    for (int s = 0; s < 3; ++s) {
        const float* row = xbc + (size_t)s * CONV_DIM;
        #pragma unroll
        for (int j = 0; j < 4; ++j) {
            rB[s][j] = __ldg(row + D_INNER + lane + 32 * j);
            rC[s][j] = __ldg(row + D_INNER + D_STATE + lane + 32 * j);
        }
        rX[s]  = __ldg(row + h * HEADDIM + p);
        rDT[s] = __ldg(dt + s * NHEADS + h);
    }

    for (int t0 = 0; t0 < LSEQ; t0 += 3) {
        #pragma unroll
        for (int s = 0; s < 3; ++s) {
            int t = t0 + s;
            if (t >= LSEQ) break;
            float dtv  = rDT[s];
            float xraw = rX[s];
            float e  = __expf(Ah * dtv);
            float xd = xraw * dtv;
            float acc;
            hs0 = e * hs0 + rB[s][0] * xd;
            hs1 = e * hs1 + rB[s][1] * xd;
            hs2 = e * hs2 + rB[s][2] * xd;
            hs3 = e * hs3 + rB[s][3] * xd;
            acc  = rC[s][0] * hs0;
            acc += rC[s][1] * hs1;
            acc += rC[s][2] * hs2;
            acc += rC[s][3] * hs3;
            #pragma unroll
            for (int o = 16; o; o >>= 1) acc += __shfl_xor_sync(0xffffffffu, acc, o);
            if (lane == 0)
                y[(size_t)t * D_INNER + h * HEADDIM + p] = acc + xraw * Dh;

            int tn = t + 3;
            if (tn > LSEQ - 1) tn = LSEQ - 1;
            const float* row = xbc + (size_t)tn * CONV_DIM;
            #pragma unroll
            for (int j = 0; j < 4; ++j) {
                rB[s][j] = __ldg(row + D_INNER + lane + 32 * j);
                rC[s][j] = __ldg(row + D_INNER + D_STATE + lane + 32 * j);
            }
            rX[s]  = __ldg(row + h * HEADDIM + p);
            rDT[s] = __ldg(dt + tn * NHEADS + h);
        }
    }
}

// =============================================================================
// Split-precision tensor-core GEMM (NT): C[m,n] = sum_k A[m,k]*B[n,k] (+ add)
// KIND=0: bf16, 3 passes (Ahi*Bhi + Alo*Bhi + Ahi*Blo)
// KIND=1: fp16, 2 passes (Ahi*Bhi + Alo*Bhi), B single-precision fp16
// BM=128, BN=128, BK=32, 256 threads (8 warps: 4 in M x 2 in N).
// =============================================================================
#define BM 128
#define BN 128
#define BKK 32
#define LDSB 40   // padded smem stride in 16-bit elems (80 B): conflict-free

#define LDSM4(R, addr) asm volatile( \
    "ldmatrix.sync.aligned.m8n8.x4.shared.b16 {%0,%1,%2,%3}, [%4];" \
    : "=r"((R)[0]),"=r"((R)[1]),"=r"((R)[2]),"=r"((R)[3]) : "r"(addr))
#define LDSM2(R, addr) asm volatile( \
    "ldmatrix.sync.aligned.m8n8.x2.shared.b16 {%0,%1}, [%2];" \
    : "=r"((R)[0]),"=r"((R)[1]) : "r"(addr))

__device__ __forceinline__ uint32_t smem_u32(const void* p) {
    return (uint32_t)__cvta_generic_to_shared(p);
}

template<int KIND>
__device__ __forceinline__ void mma16816(float* acc, const uint32_t* a,
                                         const uint32_t* b) {
    if (KIND == 0) {
        asm volatile(
            "mma.sync.aligned.m16n8k16.row.col.f32.bf16.bf16.f32 "
            "{%0,%1,%2,%3},{%4,%5,%6,%7},{%8,%9},{%0,%1,%2,%3};"
            : "+f"(acc[0]), "+f"(acc[1]), "+f"(acc[2]), "+f"(acc[3])
            : "r"(a[0]), "r"(a[1]), "r"(a[2]), "r"(a[3]), "r"(b[0]), "r"(b[1]));
    } else {
        asm volatile(
            "mma.sync.aligned.m16n8k16.row.col.f32.f16.f16.f32 "
            "{%0,%1,%2,%3},{%4,%5,%6,%7},{%8,%9},{%0,%1,%2,%3};"
            : "+f"(acc[0]), "+f"(acc[1]), "+f"(acc[2]), "+f"(acc[3])
            : "r"(a[0]), "r"(a[1]), "r"(a[2]), "r"(a[3]), "r"(b[0]), "r"(b[1]));
    }
}

template<int KIND>
__global__ __launch_bounds__(256) void gemm_mma(
    const unsigned short* __restrict__ Ahi, const unsigned short* __restrict__ Alo,
    const unsigned short* __restrict__ Bhi, const unsigned short* __restrict__ Blo,
    const float* add, float* __restrict__ C, int M, int N, int K) {
    __shared__ unsigned short sAhi[BM * LDSB], sAlo[BM * LDSB];
    __shared__ unsigned short sBhi[BN * LDSB];
    __shared__ unsigned short sBlo[(KIND == 0 ? BN : 8) * LDSB];

    int tid  = threadIdx.x;
    int wid  = tid >> 5, lane = tid & 31;
    int wm   = wid & 3;
    int wn   = wid >> 2;
    int bm   = blockIdx.x * BM;
    int bn   = blockIdx.y * BN;

    float acc[2][8][4];
    #pragma unroll
    for (int i = 0; i < 2; ++i)
        #pragma unroll
        for (int j = 0; j < 8; ++j)
            #pragma unroll
            for (int q = 0; q < 4; ++q) acc[i][j][q] = 0.f;

    int lr = tid >> 1;             // 0..127
    int lk = (tid & 1) * 16;       // 0 or 16
    int brow  = bn + lr;
    int browc = (brow < N) ? brow : 0;

    int mrow      = wm * 32 + (lane & 15);
    int acol_half = ((lane >> 4) << 3);
    int nrow_base = wn * 64 + (lane & 7);
    int bcol_half = ((lane >> 3) & 1) << 3;

    for (int k0 = 0; k0 < K; k0 += BKK) {
        // ---- stage tile into smem ----
        {
            const unsigned short* pa0 = Ahi + (size_t)(bm + lr) * K + k0 + lk;
            const unsigned short* pa1 = Alo + (size_t)(bm + lr) * K + k0 + lk;
            const unsigned short* pb0 = Bhi + (size_t)browc * K + k0 + lk;
            *(uint4*)&sAhi[lr * LDSB + lk]     = *(const uint4*)pa0;
            *(uint4*)&sAhi[lr * LDSB + lk + 8] = *(const uint4*)(pa0 + 8);
            *(uint4*)&sAlo[lr * LDSB + lk]     = *(const uint4*)pa1;
            *(uint4*)&sAlo[lr * LDSB + lk + 8] = *(const uint4*)(pa1 + 8);
            *(uint4*)&sBhi[lr * LDSB + lk]     = *(const uint4*)pb0;
            *(uint4*)&sBhi[lr * LDSB + lk + 8] = *(const uint4*)(pb0 + 8);
            if (KIND == 0) {
                const unsigned short* pb1 = Blo + (size_t)browc * K + k0 + lk;
                *(uint4*)&sBlo[lr * LDSB + lk]     = *(const uint4*)pb1;
                *(uint4*)&sBlo[lr * LDSB + lk + 8] = *(const uint4*)(pb1 + 8);
            }
        }
        __syncthreads();

        #pragma unroll
        for (int ks = 0; ks < 2; ++ks) {
            int kb = ks * 16;
            uint32_t ahi[2][4], alo[2][4];
            #pragma unroll
            for (int mi = 0; mi < 2; ++mi) {
                int off = (mrow + mi * 16) * LDSB + kb + acol_half;
                LDSM4(ahi[mi], smem_u32(&sAhi[off]));
                LDSM4(alo[mi], smem_u32(&sAlo[off]));
            }
            uint32_t bhi[8][2], blo[8][2];
            #pragma unroll
            for (int ni = 0; ni < 8; ++ni) {
                int off = (nrow_base + ni * 8) * LDSB + kb + bcol_half;
                LDSM2(bhi[ni], smem_u32(&sBhi[off]));
                if (KIND == 0) LDSM2(blo[ni], smem_u32(&sBlo[off]));
            }
            #pragma unroll
            for (int mi = 0; mi < 2; ++mi)
                #pragma unroll
                for (int ni = 0; ni < 8; ++ni) {
                    mma16816<KIND>(acc[mi][ni], ahi[mi], bhi[ni]);
                    mma16816<KIND>(acc[mi][ni], alo[mi], bhi[ni]);
                    if (KIND == 0) mma16816<KIND>(acc[mi][ni], ahi[mi], blo[ni]);
                }
        }
        __syncthreads();
    }

    // --- epilogue ---
    int g = lane >> 2, t4 = lane & 3;
    #pragma unroll
    for (int mi = 0; mi < 2; ++mi) {
        int r0 = bm + wm * 32 + mi * 16 + g;
        #pragma unroll
        for (int ni = 0; ni < 8; ++ni) {
            int col = bn + wn * 64 + ni * 8 + t4 * 2;
            if (col < N) {     // N even, col even -> covers col+1 too
                float2 v0 = make_float2(acc[mi][ni][0], acc[mi][ni][1]);
                float2 v1 = make_float2(acc[mi][ni][2], acc[mi][ni][3]);
                if (add) {
                    float2 a0 = *(const float2*)(add + (size_t)r0 * N + col);
                    float2 a1 = *(const float2*)(add + (size_t)(r0 + 8) * N + col);
                    v0.x += a0.x; v0.y += a0.y;
                    v1.x += a1.x; v1.y += a1.y;
                }
                *(float2*)(C + (size_t)r0 * N + col)       = v0;
                *(float2*)(C + (size_t)(r0 + 8) * N + col) = v1;
            }
        }
    }
}

// ---------------- orchestration ----------------------------------------------
extern "C" void kernel_launch(void* const* d_in, const int* in_sizes, int n_in,
                              void* d_out, int out_size) {
    const int*   ids       = (const int*)  d_in[0];
    const float* emb       = (const float*)d_in[1];
    const float* norm_ws   = (const float*)d_in[2];
    const float* in_ws     = (const float*)d_in[3];
    const float* conv_ws   = (const float*)d_in[4];
    const float* conv_bs   = (const float*)d_in[5];
    const float* dt_biases = (const float*)d_in[6];
    const float* A_logs    = (const float*)d_in[7];
    const float* Ds        = (const float*)d_in[8];
    const float* gnorm_ws  = (const float*)d_in[9];
    const float* out_ws    = (const float*)d_in[10];
    const float* norm_f_w  = (const float*)d_in[11];
    float* out = (float*)d_out;

    float *x, *zx, *xbc, *dtb, *y;
    cudaGetSymbolAddress((void**)&x,   g_x);
    cudaGetSymbolAddress((void**)&zx,  g_zx);
    cudaGetSymbolAddress((void**)&xbc, g_xbc);
    cudaGetSymbolAddress((void**)&dtb, g_dt);
    cudaGetSymbolAddress((void**)&y,   g_y);

    unsigned short *emb_h, *inw_hi, *inw_lo, *outw_hi, *outw_lo;
    unsigned short *u_hi, *u_lo, *t2_hi, *t2_lo;
    cudaGetSymbolAddress((void**)&emb_h,   g_emb_h);
    cudaGetSymbolAddress((void**)&inw_hi,  g_inw_hi);
    cudaGetSymbolAddress((void**)&inw_lo,  g_inw_lo);
    cudaGetSymbolAddress((void**)&outw_hi, g_outw_hi);
    cudaGetSymbolAddress((void**)&outw_lo, g_outw_lo);
    cudaGetSymbolAddress((void**)&u_hi,    g_u_hi);
    cudaGetSymbolAddress((void**)&u_lo,    g_u_lo);
    cudaGetSymbolAddress((void**)&t2_hi,   g_t2_hi);
    cudaGetSymbolAddress((void**)&t2_lo,   g_t2_lo);

    // (0) embed
    embed_kernel<<<(LSEQ * D_MODEL + 255) / 256, 256>>>(ids, emb, x);
    // (1) pre-norm layer 0
    rmsnorm_kernel<__nv_bfloat16><<<LSEQ, 256>>>(
        x, D_MODEL, norm_ws, nullptr, 0, u_hi, u_lo, D_MODEL);
    // (2) split in_ws (all layers)
    {
        int n4 = N_LAYER * D_IN_PROJ * D_MODEL / 4;
        split_bf16_kernel<<<(n4 + 255) / 256, 256>>>(
            (const float4*)in_ws, (__nv_bfloat162*)inw_hi, (__nv_bfloat162*)inw_lo, n4);
    }
    // (3) in_proj layer 0  <-- ncu-profiled slot
    gemm_mma<0><<<dim3(LSEQ / BM, (D_IN_PROJ + BN - 1) / BN), 256>>>(
        u_hi, u_lo, inw_hi, inw_lo, nullptr, zx, LSEQ, D_IN_PROJ, D_MODEL);
    // (4) split out_ws (all layers)
    {
        int n4 = N_LAYER * D_MODEL * D_INNER / 4;
        split_bf16_kernel<<<(n4 + 255) / 256, 256>>>(
            (const float4*)out_ws, (__nv_bfloat162*)outw_hi, (__nv_bfloat162*)outw_lo, n4);
    }
    // (5) emb -> fp16
    {
        int n4 = VOCAB * D_MODEL / 4;
        cvt_half_kernel<<<(n4 + 255) / 256, 256>>>(
            (const float4*)emb, (__half2*)emb_h, n4);
    }

    for (int i = 0; i < N_LAYER; ++i) {
        if (i > 0) {
            rmsnorm_kernel<__nv_bfloat16><<<LSEQ, 256>>>(
                x, D_MODEL, norm_ws + (size_t)i * D_MODEL, nullptr, 0,
                u_hi, u_lo, D_MODEL);
            gemm_mma<0><<<dim3(LSEQ / BM, (D_IN_PROJ + BN - 1) / BN), 256>>>(
                u_hi, u_lo,
                inw_hi + (size_t)i * D_IN_PROJ * D_MODEL,
                inw_lo + (size_t)i * D_IN_PROJ * D_MODEL,
                nullptr, zx, LSEQ, D_IN_PROJ, D_MODEL);
        }
        dt_kernel<<<(LSEQ * NHEADS + 255) / 256, 256>>>(
            zx, dt_biases + (size_t)i * NHEADS, dtb);
        conv_kernel<<<(LSEQ * CONV_DIM + 255) / 256, 256>>>(
            zx, conv_ws + (size_t)i * CONV_DIM * D_CONV,
            conv_bs + (size_t)i * CONV_DIM, xbc);
        ssd_kernel<<<512, 128>>>(
            xbc, dtb, A_logs + (size_t)i * NHEADS, Ds + (size_t)i * NHEADS, y);
        rmsnorm_kernel<__nv_bfloat16><<<LSEQ, 256>>>(
            y, D_INNER, gnorm_ws + (size_t)i * D_INNER,
            zx, D_IN_PROJ, t2_hi, t2_lo, D_INNER);
        gemm_mma<0><<<dim3(LSEQ / BM, D_MODEL / BN), 256>>>(
            t2_hi, t2_lo,
            outw_hi + (size_t)i * D_MODEL * D_INNER,
            outw_lo + (size_t)i * D_MODEL * D_INNER,
            x, x, LSEQ, D_MODEL, D_INNER);
    }

    // final norm (fp16 split) + fp16 2-pass logits
    rmsnorm_kernel<__half><<<LSEQ, 256>>>(
        x, D_MODEL, norm_f_w, nullptr, 0, u_hi, u_lo, D_MODEL);
    gemm_mma<1><<<dim3(LSEQ / BM, (VOCAB + BN - 1) / BN), 256>>>(
        u_hi, u_lo, emb_h, emb_h, nullptr, out, LSEQ, VOCAB, D_MODEL);
}

// round 6
// speedup vs baseline: 1.5289x; 1.1815x over previous
#include <cuda_runtime.h>
#include <cuda_bf16.h>
#include <cuda_fp16.h>
#include <cstdint>

#define N_LAYER  4
#define D_MODEL  1024
#define D_STATE  128
#define D_CONV   4
#define HEADDIM  64
#define NHEADS   32
#define D_INNER  2048
#define CONV_DIM 2304         // D_INNER + 2*D_STATE
#define D_IN_PROJ 4384        // 2*D_INNER + 2*D_STATE + NHEADS
#define LSEQ     1024
#define VOCAB    50288
#define EPS      1e-5f

// ---------------- scratch (static device globals; no allocation) -------------
__device__ float g_x  [LSEQ * D_MODEL];
__device__ float g_zx [LSEQ * D_IN_PROJ];
__device__ float g_xbc[LSEQ * CONV_DIM];
__device__ float g_dt [LSEQ * NHEADS];
__device__ float g_y  [LSEQ * D_INNER];

// split storage (raw 16-bit; interpreted as bf16 or fp16 per use)
__device__ unsigned short g_emb_h  [VOCAB * D_MODEL];               // fp16
__device__ unsigned short g_inw_hi [N_LAYER * D_IN_PROJ * D_MODEL]; // bf16
__device__ unsigned short g_inw_lo [N_LAYER * D_IN_PROJ * D_MODEL];
__device__ unsigned short g_outw_hi[N_LAYER * D_MODEL * D_INNER];   // bf16
__device__ unsigned short g_outw_lo[N_LAYER * D_MODEL * D_INNER];
__device__ unsigned short g_u_hi  [LSEQ * D_MODEL];   // bf16 (layers) / fp16 (final)
__device__ unsigned short g_u_lo  [LSEQ * D_MODEL];
__device__ unsigned short g_t2_hi [LSEQ * D_INNER];   // bf16
__device__ unsigned short g_t2_lo [LSEQ * D_INNER];

// ---------------- fp32 -> bf16 hi/lo split -----------------------------------
__global__ void split_bf16_kernel(const float4* __restrict__ in,
                                  __nv_bfloat162* __restrict__ hi,
                                  __nv_bfloat162* __restrict__ lo, int n4) {
    int i = blockIdx.x * blockDim.x + threadIdx.x;
    if (i >= n4) return;
    float4 v = in[i];
    __nv_bfloat162 h01 = __floats2bfloat162_rn(v.x, v.y);
    __nv_bfloat162 h23 = __floats2bfloat162_rn(v.z, v.w);
    hi[2 * i]     = h01;
    hi[2 * i + 1] = h23;
    lo[2 * i]     = __floats2bfloat162_rn(v.x - __low2float(h01), v.y - __high2float(h01));
    lo[2 * i + 1] = __floats2bfloat162_rn(v.z - __low2float(h23), v.w - __high2float(h23));
}

// ---------------- fp32 -> fp16 (single) ---------------------------------------
__global__ void cvt_half_kernel(const float4* __restrict__ in,
                                __half2* __restrict__ out, int n4) {
    int i = blockIdx.x * blockDim.x + threadIdx.x;
    if (i >= n4) return;
    float4 v = in[i];
    out[2 * i]     = __floats2half2_rn(v.x, v.y);
    out[2 * i + 1] = __floats2half2_rn(v.z, v.w);
}

// ---------------- embedding gather ------------------------------------------
__global__ void embed_kernel(const int* __restrict__ ids,
                             const float* __restrict__ emb,
                             float* __restrict__ x) {
    int idx = blockIdx.x * blockDim.x + threadIdx.x;
    if (idx >= LSEQ * D_MODEL) return;
    int t = idx >> 10;
    int d = idx & 1023;
    x[idx] = emb[(size_t)ids[t] * D_MODEL + d];
}

// ---------------- rmsnorm (optionally gated); outputs hi/lo pair -------------
template<typename T>
__global__ void rmsnorm_kernel(const float* __restrict__ x, int xs,
                               const float* __restrict__ w,
                               const float* z, int zs,
                               unsigned short* __restrict__ out_hi,
                               unsigned short* __restrict__ out_lo, int D) {
    __shared__ float buf[2048];
    __shared__ float red[8];
    __shared__ float s_scale;
    int t = blockIdx.x;
    int tid = threadIdx.x;

    float ss = 0.f;
    for (int c = tid; c < D; c += blockDim.x) {
        float v = x[(size_t)t * xs + c];
        if (z) {
            float zz = z[(size_t)t * zs + c];
            v *= zz / (1.f + expf(-zz));
        }
        buf[c] = v;
        ss += v * v;
    }
    #pragma unroll
    for (int o = 16; o; o >>= 1) ss += __shfl_xor_sync(0xffffffffu, ss, o);
    if ((tid & 31) == 0) red[tid >> 5] = ss;
    __syncthreads();
    if (tid < 32) {
        float v = (tid < 8) ? red[tid] : 0.f;
        #pragma unroll
        for (int o = 4; o; o >>= 1) v += __shfl_xor_sync(0xffffffffu, v, o);
        if (tid == 0) s_scale = rsqrtf(v / (float)D + EPS);
    }
    __syncthreads();
    float sc = s_scale;
    for (int c = tid; c < D; c += blockDim.x) {
        float v = buf[c] * sc * w[c];
        T h = (T)v;
        float hf = (float)h;
        T l = (T)(v - hf);
        out_hi[(size_t)t * D + c] = *(unsigned short*)&h;
        out_lo[(size_t)t * D + c] = *(unsigned short*)&l;
    }
}

// ---------------- dt = softplus(raw + bias) ----------------------------------
__global__ void dt_kernel(const float* __restrict__ zx,
                          const float* __restrict__ dt_bias,
                          float* __restrict__ dt) {
    int idx = blockIdx.x * blockDim.x + threadIdx.x;
    if (idx >= LSEQ * NHEADS) return;
    int t = idx >> 5;
    int h = idx & 31;
    float v = zx[(size_t)t * D_IN_PROJ + (D_INNER + CONV_DIM) + h] + dt_bias[h];
    dt[idx] = (v > 20.f) ? v : log1pf(expf(v));
}

// ---------------- depthwise causal conv (width 4) + silu ---------------------
__global__ void conv_kernel(const float* __restrict__ zx,
                            const float* __restrict__ w,
                            const float* __restrict__ b,
                            float* __restrict__ out) {
    int idx = blockIdx.x * blockDim.x + threadIdx.x;
    if (idx >= LSEQ * CONV_DIM) return;
    int t = idx / CONV_DIM;
    int c = idx - t * CONV_DIM;
    float acc = b[c];
    const float* wc = w + c * 4;
    #pragma unroll
    for (int j = 0; j < 4; ++j) {
        int tt = t - 3 + j;
        if (tt >= 0) acc += zx[(size_t)tt * D_IN_PROJ + D_INNER + c] * wc[j];
    }
    out[idx] = acc / (1.f + expf(-acc));
}

// ---------------- SSD scan: warp per (h,p), no smem, reg ring prefetch -------
__global__ void ssd_kernel(const float* __restrict__ xbc,
                           const float* __restrict__ dt,
                           const float* __restrict__ A_log,
                           const float* __restrict__ D_p,
                           float* __restrict__ y) {
    int gw   = (blockIdx.x * blockDim.x + threadIdx.x) >> 5;
    int lane = threadIdx.x & 31;
    int h = gw >> 6;
    int p = gw & 63;

    float Ah = -expf(A_log[h]);
    float Dh = D_p[h];
    float hs0 = 0.f, hs1 = 0.f, hs2 = 0.f, hs3 = 0.f;

    float rB[3][4], rC[3][4], rX[3], rDT[3];
    #pragma unroll
    for (int s = 0; s < 3; ++s) {
        const float* row = xbc + (size_t)s * CONV_DIM;
        #pragma unroll
        for (int j = 0; j < 4; ++j) {
            rB[s][j] = __ldg(row + D_INNER + lane + 32 * j);
            rC[s][j] = __ldg(row + D_INNER + D_STATE + lane + 32 * j);
        }
        rX[s]  = __ldg(row + h * HEADDIM + p);
        rDT[s] = __ldg(dt + s * NHEADS + h);
    }

    for (int t0 = 0; t0 < LSEQ; t0 += 3) {
        #pragma unroll
        for (int s = 0; s < 3; ++s) {
            int t = t0 + s;
            if (t >= LSEQ) break;
            float dtv  = rDT[s];
            float xraw = rX[s];
            float e  = __expf(Ah * dtv);
            float xd = xraw * dtv;
            float acc;
            hs0 = e * hs0 + rB[s][0] * xd;
            hs1 = e * hs1 + rB[s][1] * xd;
            hs2 = e * hs2 + rB[s][2] * xd;
            hs3 = e * hs3 + rB[s][3] * xd;
            acc  = rC[s][0] * hs0;
            acc += rC[s][1] * hs1;
            acc += rC[s][2] * hs2;
            acc += rC[s][3] * hs3;
            #pragma unroll
            for (int o = 16; o; o >>= 1) acc += __shfl_xor_sync(0xffffffffu, acc, o);
            if (lane == 0)
                y[(size_t)t * D_INNER + h * HEADDIM + p] = acc + xraw * Dh;

            int tn = t + 3;
            if (tn > LSEQ - 1) tn = LSEQ - 1;
            const float* row = xbc + (size_t)tn * CONV_DIM;
            #pragma unroll
            for (int j = 0; j < 4; ++j) {
                rB[s][j] = __ldg(row + D_INNER + lane + 32 * j);
                rC[s][j] = __ldg(row + D_INNER + D_STATE + lane + 32 * j);
            }
            rX[s]  = __ldg(row + h * HEADDIM + p);
            rDT[s] = __ldg(dt + tn * NHEADS + h);
        }
    }
}

// =============================================================================
// Split-precision tensor-core GEMM (NT): C[m,n] = sum_k A[m,k]*B[n,k] (+ add)
// KIND: 0 = bf16 mma, 1 = fp16 mma.
// NPASS: 3 = Ahi*Bhi + Alo*Bhi + Ahi*Blo; 2 = Ahi*Bhi + Alo*Bhi; 1 = Ahi*Bhi.
// BNT: 128 (warp tile 32x64) or 64 (warp tile 32x32).  BM=128, BK=32, 256 thr.
// =============================================================================
#define BM 128
#define BKK 32
#define LDSB 40   // padded smem stride (80 B): conflict-free ldmatrix

#define LDSM4(R, addr) asm volatile( \
    "ldmatrix.sync.aligned.m8n8.x4.shared.b16 {%0,%1,%2,%3}, [%4];" \
    : "=r"((R)[0]),"=r"((R)[1]),"=r"((R)[2]),"=r"((R)[3]) : "r"(addr))
#define LDSM2(R, addr) asm volatile( \
    "ldmatrix.sync.aligned.m8n8.x2.shared.b16 {%0,%1}, [%2];" \
    : "=r"((R)[0]),"=r"((R)[1]) : "r"(addr))

__device__ __forceinline__ uint32_t smem_u32(const void* p) {
    return (uint32_t)__cvta_generic_to_shared(p);
}

template<int KIND>
__device__ __forceinline__ void mma16816(float* acc, const uint32_t* a,
                                         const uint32_t* b) {
    if (KIND == 0) {
        asm volatile(
            "mma.sync.aligned.m16n8k16.row.col.f32.bf16.bf16.f32 "
            "{%0,%1,%2,%3},{%4,%5,%6,%7},{%8,%9},{%0,%1,%2,%3};"
            : "+f"(acc[0]), "+f"(acc[1]), "+f"(acc[2]), "+f"(acc[3])
            : "r"(a[0]), "r"(a[1]), "r"(a[2]), "r"(a[3]), "r"(b[0]), "r"(b[1]));
    } else {
        asm volatile(
            "mma.sync.aligned.m16n8k16.row.col.f32.f16.f16.f32 "
            "{%0,%1,%2,%3},{%4,%5,%6,%7},{%8,%9},{%0,%1,%2,%3};"
            : "+f"(acc[0]), "+f"(acc[1]), "+f"(acc[2]), "+f"(acc[3])
            : "r"(a[0]), "r"(a[1]), "r"(a[2]), "r"(a[3]), "r"(b[0]), "r"(b[1]));
    }
}

template<int KIND, int BNT, int NPASS>
__global__ __launch_bounds__(256) void gemm_mma(
    const unsigned short* __restrict__ Ahi, const unsigned short* __restrict__ Alo,
    const unsigned short* __restrict__ Bhi, const unsigned short* __restrict__ Blo,
    const float* add, float* __restrict__ C, int M, int N, int K) {
    constexpr int NI = BNT / 16;          // mma n-tiles per warp strip
    __shared__ unsigned short sAhi[BM * LDSB];
    __shared__ unsigned short sAlo[(NPASS >= 2 ? BM : 8) * LDSB];
    __shared__ unsigned short sBhi[BNT * LDSB];
    __shared__ unsigned short sBlo[(NPASS == 3 ? BNT : 8) * LDSB];

    int tid  = threadIdx.x;
    int wid  = tid >> 5, lane = tid & 31;
    int wm   = wid & 3;
    int wn   = wid >> 2;
    int bm   = blockIdx.x * BM;
    int bn   = blockIdx.y * BNT;

    float acc[2][NI][4];
    #pragma unroll
    for (int i = 0; i < 2; ++i)
        #pragma unroll
        for (int j = 0; j < NI; ++j)
            #pragma unroll
            for (int q = 0; q < 4; ++q) acc[i][j][q] = 0.f;

    // A load map: 2 threads/row, 16 elems each
    int lrA = tid >> 1;
    int lkA = (tid & 1) * 16;
    // B load map
    int lrB, lkB;
    if (BNT == 128) { lrB = tid >> 1; lkB = (tid & 1) * 16; }
    else           { lrB = tid >> 2; lkB = (tid & 3) * 8;  }
    int brow  = bn + lrB;
    int browc = (brow < N) ? brow : 0;

    int mrow      = wm * 32 + (lane & 15);
    int acol_half = ((lane >> 4) << 3);
    int nrow_base = wn * (BNT / 2) + (lane & 7);
    int bcol_half = ((lane >> 3) & 1) << 3;

    for (int k0 = 0; k0 < K; k0 += BKK) {
        {
            const unsigned short* pa0 = Ahi + (size_t)(bm + lrA) * K + k0 + lkA;
            *(uint4*)&sAhi[lrA * LDSB + lkA]     = *(const uint4*)pa0;
            *(uint4*)&sAhi[lrA * LDSB + lkA + 8] = *(const uint4*)(pa0 + 8);
            if (NPASS >= 2) {
                const unsigned short* pa1 = Alo + (size_t)(bm + lrA) * K + k0 + lkA;
                *(uint4*)&sAlo[lrA * LDSB + lkA]     = *(const uint4*)pa1;
                *(uint4*)&sAlo[lrA * LDSB + lkA + 8] = *(const uint4*)(pa1 + 8);
            }
            const unsigned short* pb0 = Bhi + (size_t)browc * K + k0 + lkB;
            if (BNT == 128) {
                *(uint4*)&sBhi[lrB * LDSB + lkB]     = *(const uint4*)pb0;
                *(uint4*)&sBhi[lrB * LDSB + lkB + 8] = *(const uint4*)(pb0 + 8);
            } else {
                *(uint4*)&sBhi[lrB * LDSB + lkB]     = *(const uint4*)pb0;
            }
            if (NPASS == 3) {
                const unsigned short* pb1 = Blo + (size_t)browc * K + k0 + lkB;
                if (BNT == 128) {
                    *(uint4*)&sBlo[lrB * LDSB + lkB]     = *(const uint4*)pb1;
                    *(uint4*)&sBlo[lrB * LDSB + lkB + 8] = *(const uint4*)(pb1 + 8);
                } else {
                    *(uint4*)&sBlo[lrB * LDSB + lkB]     = *(const uint4*)pb1;
                }
            }
        }
        __syncthreads();

        #pragma unroll
        for (int ks = 0; ks < 2; ++ks) {
            int kb = ks * 16;
            uint32_t ahi[2][4], alo[2][4];
            #pragma unroll
            for (int mi = 0; mi < 2; ++mi) {
                int off = (mrow + mi * 16) * LDSB + kb + acol_half;
                LDSM4(ahi[mi], smem_u32(&sAhi[off]));
                if (NPASS >= 2) LDSM4(alo[mi], smem_u32(&sAlo[off]));
            }
            uint32_t bhi[NI][2], blo[NI][2];
            #pragma unroll
            for (int ni = 0; ni < NI; ++ni) {
                int off = (nrow_base + ni * 8) * LDSB + kb + bcol_half;
                LDSM2(bhi[ni], smem_u32(&sBhi[off]));
                if (NPASS == 3) LDSM2(blo[ni], smem_u32(&sBlo[off]));
            }
            #pragma unroll
            for (int mi = 0; mi < 2; ++mi)
                #pragma unroll
                for (int ni = 0; ni < NI; ++ni) {
                    mma16816<KIND>(acc[mi][ni], ahi[mi], bhi[ni]);
                    if (NPASS >= 2) mma16816<KIND>(acc[mi][ni], alo[mi], bhi[ni]);
                    if (NPASS == 3) mma16816<KIND>(acc[mi][ni], ahi[mi], blo[ni]);
                }
        }
        __syncthreads();
    }

    // --- epilogue ---
    int g = lane >> 2, t4 = lane & 3;
    #pragma unroll
    for (int mi = 0; mi < 2; ++mi) {
        int r0 = bm + wm * 32 + mi * 16 + g;
        #pragma unroll
        for (int ni = 0; ni < NI; ++ni) {
            int col = bn + wn * (BNT / 2) + ni * 8 + t4 * 2;
            if (col < N) {     // N even, col even -> covers col+1 too
                float2 v0 = make_float2(acc[mi][ni][0], acc[mi][ni][1]);
                float2 v1 = make_float2(acc[mi][ni][2], acc[mi][ni][3]);
                if (add) {
                    float2 a0 = *(const float2*)(add + (size_t)r0 * N + col);
                    float2 a1 = *(const float2*)(add + (size_t)(r0 + 8) * N + col);
                    v0.x += a0.x; v0.y += a0.y;
                    v1.x += a1.x; v1.y += a1.y;
                }
                *(float2*)(C + (size_t)r0 * N + col)       = v0;
                *(float2*)(C + (size_t)(r0 + 8) * N + col) = v1;
            }
        }
    }
}

// ---------------- orchestration ----------------------------------------------
extern "C" void kernel_launch(void* const* d_in, const int* in_sizes, int n_in,
                              void* d_out, int out_size) {
    const int*   ids       = (const int*)  d_in[0];
    const float* emb       = (const float*)d_in[1];
    const float* norm_ws   = (const float*)d_in[2];
    const float* in_ws     = (const float*)d_in[3];
    const float* conv_ws   = (const float*)d_in[4];
    const float* conv_bs   = (const float*)d_in[5];
    const float* dt_biases = (const float*)d_in[6];
    const float* A_logs    = (const float*)d_in[7];
    const float* Ds        = (const float*)d_in[8];
    const float* gnorm_ws  = (const float*)d_in[9];
    const float* out_ws    = (const float*)d_in[10];
    const float* norm_f_w  = (const float*)d_in[11];
    float* out = (float*)d_out;

    float *x, *zx, *xbc, *dtb, *y;
    cudaGetSymbolAddress((void**)&x,   g_x);
    cudaGetSymbolAddress((void**)&zx,  g_zx);
    cudaGetSymbolAddress((void**)&xbc, g_xbc);
    cudaGetSymbolAddress((void**)&dtb, g_dt);
    cudaGetSymbolAddress((void**)&y,   g_y);

    unsigned short *emb_h, *inw_hi, *inw_lo, *outw_hi, *outw_lo;
    unsigned short *u_hi, *u_lo, *t2_hi, *t2_lo;
    cudaGetSymbolAddress((void**)&emb_h,   g_emb_h);
    cudaGetSymbolAddress((void**)&inw_hi,  g_inw_hi);
    cudaGetSymbolAddress((void**)&inw_lo,  g_inw_lo);
    cudaGetSymbolAddress((void**)&outw_hi, g_outw_hi);
    cudaGetSymbolAddress((void**)&outw_lo, g_outw_lo);
    cudaGetSymbolAddress((void**)&u_hi,    g_u_hi);
    cudaGetSymbolAddress((void**)&u_lo,    g_u_lo);
    cudaGetSymbolAddress((void**)&t2_hi,   g_t2_hi);
    cudaGetSymbolAddress((void**)&t2_lo,   g_t2_lo);

    // (0) embed
    embed_kernel<<<(LSEQ * D_MODEL + 255) / 256, 256>>>(ids, emb, x);
    // (1) pre-norm layer 0
    rmsnorm_kernel<__nv_bfloat16><<<LSEQ, 256>>>(
        x, D_MODEL, norm_ws, nullptr, 0, u_hi, u_lo, D_MODEL);
    // (2) split in_ws (all layers)
    {
        int n4 = N_LAYER * D_IN_PROJ * D_MODEL / 4;
        split_bf16_kernel<<<(n4 + 255) / 256, 256>>>(
            (const float4*)in_ws, (__nv_bfloat162*)inw_hi, (__nv_bfloat162*)inw_lo, n4);
    }
    // (3) in_proj layer 0
    gemm_mma<0, 128, 3><<<dim3(LSEQ / BM, (D_IN_PROJ + 127) / 128), 256>>>(
        u_hi, u_lo, inw_hi, inw_lo, nullptr, zx, LSEQ, D_IN_PROJ, D_MODEL);
    // (4) split out_ws (all layers)
    {
        int n4 = N_LAYER * D_MODEL * D_INNER / 4;
        split_bf16_kernel<<<(n4 + 255) / 256, 256>>>(
            (const float4*)out_ws, (__nv_bfloat162*)outw_hi, (__nv_bfloat162*)outw_lo, n4);
    }
    // (5) emb -> fp16
    {
        int n4 = VOCAB * D_MODEL / 4;
        cvt_half_kernel<<<(n4 + 255) / 256, 256>>>(
            (const float4*)emb, (__half2*)emb_h, n4);
    }

    for (int i = 0; i < N_LAYER; ++i) {
        if (i > 0) {
            rmsnorm_kernel<__nv_bfloat16><<<LSEQ, 256>>>(
                x, D_MODEL, norm_ws + (size_t)i * D_MODEL, nullptr, 0,
                u_hi, u_lo, D_MODEL);
            gemm_mma<0, 128, 3><<<dim3(LSEQ / BM, (D_IN_PROJ + 127) / 128), 256>>>(
                u_hi, u_lo,
                inw_hi + (size_t)i * D_IN_PROJ * D_MODEL,
                inw_lo + (size_t)i * D_IN_PROJ * D_MODEL,
                nullptr, zx, LSEQ, D_IN_PROJ, D_MODEL);
        }
        dt_kernel<<<(LSEQ * NHEADS + 255) / 256, 256>>>(
            zx, dt_biases + (size_t)i * NHEADS, dtb);
        conv_kernel<<<(LSEQ * CONV_DIM + 255) / 256, 256>>>(
            zx, conv_ws + (size_t)i * CONV_DIM * D_CONV,
            conv_bs + (size_t)i * CONV_DIM, xbc);
        ssd_kernel<<<512, 128>>>(
            xbc, dtb, A_logs + (size_t)i * NHEADS, Ds + (size_t)i * NHEADS, y);
        rmsnorm_kernel<__nv_bfloat16><<<LSEQ, 256>>>(
            y, D_INNER, gnorm_ws + (size_t)i * D_INNER,
            zx, D_IN_PROJ, t2_hi, t2_lo, D_INNER);
        // out_proj + residual: BN=64 tiles -> 128-block grid
        gemm_mma<0, 64, 3><<<dim3(LSEQ / BM, D_MODEL / 64), 256>>>(
            t2_hi, t2_lo,
            outw_hi + (size_t)i * D_MODEL * D_INNER,
            outw_lo + (size_t)i * D_MODEL * D_INNER,
            x, x, LSEQ, D_MODEL, D_INNER);
    }

    // final norm (fp16) + fp16 1-pass logits
    rmsnorm_kernel<__half><<<LSEQ, 256>>>(
        x, D_MODEL, norm_f_w, nullptr, 0, u_hi, u_lo, D_MODEL);
    gemm_mma<1, 128, 1><<<dim3(LSEQ / BM, (VOCAB + 127) / 128), 256>>>(
        u_hi, u_hi, emb_h, emb_h, nullptr, out, LSEQ, VOCAB, D_MODEL);
}

// round 8
// speedup vs baseline: 1.5490x; 1.0131x over previous
#include <cuda_runtime.h>
#include <cuda_bf16.h>
#include <cuda_fp16.h>
#include <cstdint>

#define N_LAYER  4
#define D_MODEL  1024
#define D_STATE  128
#define D_CONV   4
#define HEADDIM  64
#define NHEADS   32
#define D_INNER  2048
#define CONV_DIM 2304         // D_INNER + 2*D_STATE
#define D_IN_PROJ 4384        // 2*D_INNER + 2*D_STATE + NHEADS
#define LSEQ     1024
#define VOCAB    50288
#define EPS      1e-5f

// ---------------- scratch (static device globals; no allocation) -------------
__device__ float g_x  [LSEQ * D_MODEL];
__device__ float g_zx [LSEQ * D_IN_PROJ];
__device__ float g_xbc[LSEQ * CONV_DIM];
__device__ float g_dt [LSEQ * NHEADS];
__device__ float g_y  [LSEQ * D_INNER];

// split storage (raw 16-bit; interpreted as bf16 or fp16 per use)
__device__ unsigned short g_emb_h  [VOCAB * D_MODEL];               // fp16
__device__ unsigned short g_inw_hi [N_LAYER * D_IN_PROJ * D_MODEL]; // bf16
__device__ unsigned short g_inw_lo [N_LAYER * D_IN_PROJ * D_MODEL];
__device__ unsigned short g_outw_hi[N_LAYER * D_MODEL * D_INNER];   // bf16
__device__ unsigned short g_outw_lo[N_LAYER * D_MODEL * D_INNER];
__device__ unsigned short g_u_hi  [LSEQ * D_MODEL];
__device__ unsigned short g_u_lo  [LSEQ * D_MODEL];
__device__ unsigned short g_t2_hi [LSEQ * D_INNER];
__device__ unsigned short g_t2_lo [LSEQ * D_INNER];

// ---------------- fp32 -> bf16 hi/lo split -----------------------------------
__global__ void split_bf16_kernel(const float4* __restrict__ in,
                                  __nv_bfloat162* __restrict__ hi,
                                  __nv_bfloat162* __restrict__ lo, int n4) {
    int i = blockIdx.x * blockDim.x + threadIdx.x;
    if (i >= n4) return;
    float4 v = in[i];
    __nv_bfloat162 h01 = __floats2bfloat162_rn(v.x, v.y);
    __nv_bfloat162 h23 = __floats2bfloat162_rn(v.z, v.w);
    hi[2 * i]     = h01;
    hi[2 * i + 1] = h23;
    lo[2 * i]     = __floats2bfloat162_rn(v.x - __low2float(h01), v.y - __high2float(h01));
    lo[2 * i + 1] = __floats2bfloat162_rn(v.z - __low2float(h23), v.w - __high2float(h23));
}

// ---------------- fp32 -> fp16 (single) ---------------------------------------
__global__ void cvt_half_kernel(const float4* __restrict__ in,
                                __half2* __restrict__ out, int n4) {
    int i = blockIdx.x * blockDim.x + threadIdx.x;
    if (i >= n4) return;
    float4 v = in[i];
    out[2 * i]     = __floats2half2_rn(v.x, v.y);
    out[2 * i + 1] = __floats2half2_rn(v.z, v.w);
}

// ---------------- embedding gather ------------------------------------------
__global__ void embed_kernel(const int* __restrict__ ids,
                             const float* __restrict__ emb,
                             float* __restrict__ x) {
    int idx = blockIdx.x * blockDim.x + threadIdx.x;
    if (idx >= LSEQ * D_MODEL) return;
    int t = idx >> 10;
    int d = idx & 1023;
    x[idx] = emb[(size_t)ids[t] * D_MODEL + d];
}

// ---------------- rmsnorm (optionally gated); outputs hi/lo pair -------------
template<typename T>
__global__ void rmsnorm_kernel(const float* __restrict__ x, int xs,
                               const float* __restrict__ w,
                               const float* z, int zs,
                               unsigned short* __restrict__ out_hi,
                               unsigned short* __restrict__ out_lo, int D) {
    __shared__ float buf[2048];
    __shared__ float red[8];
    __shared__ float s_scale;
    int t = blockIdx.x;
    int tid = threadIdx.x;

    float ss = 0.f;
    for (int c = tid; c < D; c += blockDim.x) {
        float v = x[(size_t)t * xs + c];
        if (z) {
            float zz = z[(size_t)t * zs + c];
            v *= zz / (1.f + expf(-zz));
        }
        buf[c] = v;
        ss += v * v;
    }
    #pragma unroll
    for (int o = 16; o; o >>= 1) ss += __shfl_xor_sync(0xffffffffu, ss, o);
    if ((tid & 31) == 0) red[tid >> 5] = ss;
    __syncthreads();
    if (tid < 32) {
        float v = (tid < 8) ? red[tid] : 0.f;
        #pragma unroll
        for (int o = 4; o; o >>= 1) v += __shfl_xor_sync(0xffffffffu, v, o);
        if (tid == 0) s_scale = rsqrtf(v / (float)D + EPS);
    }
    __syncthreads();
    float sc = s_scale;
    for (int c = tid; c < D; c += blockDim.x) {
        float v = buf[c] * sc * w[c];
        T h = (T)v;
        float hf = (float)h;
        T l = (T)(v - hf);
        out_hi[(size_t)t * D + c] = *(unsigned short*)&h;
        out_lo[(size_t)t * D + c] = *(unsigned short*)&l;
    }
}

// ---------------- dt = softplus(raw + bias) ----------------------------------
__global__ void dt_kernel(const float* __restrict__ zx,
                          const float* __restrict__ dt_bias,
                          float* __restrict__ dt) {
    int idx = blockIdx.x * blockDim.x + threadIdx.x;
    if (idx >= LSEQ * NHEADS) return;
    int t = idx >> 5;
    int h = idx & 31;
    float v = zx[(size_t)t * D_IN_PROJ + (D_INNER + CONV_DIM) + h] + dt_bias[h];
    dt[idx] = (v > 20.f) ? v : log1pf(expf(v));
}

// ---------------- depthwise causal conv (width 4) + silu ---------------------
__global__ void conv_kernel(const float* __restrict__ zx,
                            const float* __restrict__ w,
                            const float* __restrict__ b,
                            float* __restrict__ out) {
    int idx = blockIdx.x * blockDim.x + threadIdx.x;
    if (idx >= LSEQ * CONV_DIM) return;
    int t = idx / CONV_DIM;
    int c = idx - t * CONV_DIM;
    float acc = b[c];
    const float* wc = w + c * 4;
    #pragma unroll
    for (int j = 0; j < 4; ++j) {
        int tt = t - 3 + j;
        if (tt >= 0) acc += zx[(size_t)tt * D_IN_PROJ + D_INNER + c] * wc[j];
    }
    out[idx] = acc / (1.f + expf(-acc));
}

// ---------------- SSD scan: warp per (h,p), float4 B/C loads -----------------
__global__ void ssd_kernel(const float* __restrict__ xbc,
                           const float* __restrict__ dt,
                           const float* __restrict__ A_log,
                           const float* __restrict__ D_p,
                           float* __restrict__ y) {
    int gw   = (blockIdx.x * blockDim.x + threadIdx.x) >> 5;
    int lane = threadIdx.x & 31;
    int h = gw >> 6;
    int p = gw & 63;

    float Ah = -expf(A_log[h]);
    float Dh = D_p[h];
    float hs0 = 0.f, hs1 = 0.f, hs2 = 0.f, hs3 = 0.f;

    float4 rB[3], rC[3];
    float rX[3], rDT[3];
    #pragma unroll
    for (int s = 0; s < 3; ++s) {
        const float* row = xbc + (size_t)s * CONV_DIM;
        rB[s] = __ldg((const float4*)(row + D_INNER) + lane);
        rC[s] = __ldg((const float4*)(row + D_INNER + D_STATE) + lane);
        rX[s]  = __ldg(row + h * HEADDIM + p);
        rDT[s] = __ldg(dt + s * NHEADS + h);
    }

    for (int t0 = 0; t0 < LSEQ; t0 += 3) {
        #pragma unroll
        for (int s = 0; s < 3; ++s) {
            int t = t0 + s;
            if (t >= LSEQ) break;
            float dtv  = rDT[s];
            float xraw = rX[s];
            float e  = __expf(Ah * dtv);
            float xd = xraw * dtv;
            float acc;
            hs0 = e * hs0 + rB[s].x * xd;
            hs1 = e * hs1 + rB[s].y * xd;
            hs2 = e * hs2 + rB[s].z * xd;
            hs3 = e * hs3 + rB[s].w * xd;
            acc  = rC[s].x * hs0;
            acc += rC[s].y * hs1;
            acc += rC[s].z * hs2;
            acc += rC[s].w * hs3;
            #pragma unroll
            for (int o = 16; o; o >>= 1) acc += __shfl_xor_sync(0xffffffffu, acc, o);
            if (lane == 0)
                y[(size_t)t * D_INNER + h * HEADDIM + p] = acc + xraw * Dh;

            int tn = t + 3;
            if (tn > LSEQ - 1) tn = LSEQ - 1;
            const float* row = xbc + (size_t)tn * CONV_DIM;
            rB[s] = __ldg((const float4*)(row + D_INNER) + lane);
            rC[s] = __ldg((const float4*)(row + D_INNER + D_STATE) + lane);
            rX[s]  = __ldg(row + h * HEADDIM + p);
            rDT[s] = __ldg(dt + tn * NHEADS + h);
        }
    }
}

// =============================================================================
// Split-precision tensor-core GEMM (NT): C[m,n] = sum_k A[m,k]*B[n,k] (+ add)
// KIND: 0 = bf16 mma, 1 = fp16 mma.
// NPASS: 3 = AhBh+AlBh+AhBl; 1 = AhBh.
// BNT: 128 (warp 32x64) or 64 (warp 32x32). BM=128, 256 threads.
// BK: 32 or 64 (K-tile depth; LDSB=BK+8 keeps ldmatrix conflict-free).
// Static smem, single buffer (proven R6 structure).
// =============================================================================
#define BM 128

#define LDSM4(R, addr) asm volatile( \
    "ldmatrix.sync.aligned.m8n8.x4.shared.b16 {%0,%1,%2,%3}, [%4];" \
    : "=r"((R)[0]),"=r"((R)[1]),"=r"((R)[2]),"=r"((R)[3]) : "r"(addr))
#define LDSM2(R, addr) asm volatile( \
    "ldmatrix.sync.aligned.m8n8.x2.shared.b16 {%0,%1}, [%2];" \
    : "=r"((R)[0]),"=r"((R)[1]) : "r"(addr))

__device__ __forceinline__ uint32_t smem_u32(const void* p) {
    return (uint32_t)__cvta_generic_to_shared(p);
}

template<int KIND>
__device__ __forceinline__ void mma16816(float* acc, const uint32_t* a,
                                         const uint32_t* b) {
    if (KIND == 0) {
        asm volatile(
            "mma.sync.aligned.m16n8k16.row.col.f32.bf16.bf16.f32 "
            "{%0,%1,%2,%3},{%4,%5,%6,%7},{%8,%9},{%0,%1,%2,%3};"
            : "+f"(acc[0]), "+f"(acc[1]), "+f"(acc[2]), "+f"(acc[3])
            : "r"(a[0]), "r"(a[1]), "r"(a[2]), "r"(a[3]), "r"(b[0]), "r"(b[1]));
    } else {
        asm volatile(
            "mma.sync.aligned.m16n8k16.row.col.f32.f16.f16.f32 "
            "{%0,%1,%2,%3},{%4,%5,%6,%7},{%8,%9},{%0,%1,%2,%3};"
            : "+f"(acc[0]), "+f"(acc[1]), "+f"(acc[2]), "+f"(acc[3])
            : "r"(a[0]), "r"(a[1]), "r"(a[2]), "r"(a[3]), "r"(b[0]), "r"(b[1]));
    }
}

template<int KIND, int BNT, int NPASS, int BK>
__global__ __launch_bounds__(256) void gemm_mma(
    const unsigned short* __restrict__ Ahi, const unsigned short* __restrict__ Alo,
    const unsigned short* __restrict__ Bhi, const unsigned short* __restrict__ Blo,
    const float* add, float* __restrict__ C, int M, int N, int K) {
    constexpr int NI   = BNT / 16;
    constexpr int LDSB = BK + 8;
    __shared__ unsigned short sAhi[BM * LDSB];
    __shared__ unsigned short sAlo[(NPASS >= 2 ? BM : 8) * LDSB];
    __shared__ unsigned short sBhi[BNT * LDSB];
    __shared__ unsigned short sBlo[(NPASS == 3 ? BNT : 8) * LDSB];

    int tid  = threadIdx.x;
    int wid  = tid >> 5, lane = tid & 31;
    int wm   = wid & 3;
    int wn   = wid >> 2;
    int bm   = blockIdx.x * BM;
    int bn   = blockIdx.y * BNT;

    float acc[2][NI][4];
    #pragma unroll
    for (int i = 0; i < 2; ++i)
        #pragma unroll
        for (int j = 0; j < NI; ++j)
            #pragma unroll
            for (int q = 0; q < 4; ++q) acc[i][j][q] = 0.f;

    // A load map: 2 threads per row, BK/2 elems each (BK/16 uint4 chunks)
    int lrA = tid >> 1;
    int lkA = (tid & 1) * (BK / 2);
    // B load map
    int lrB, lkB;
    if (BNT == 128) { lrB = tid >> 1; lkB = (tid & 1) * (BK / 2); }
    else            { lrB = tid >> 2; lkB = (tid & 3) * (BK / 4); }
    int brow  = bn + lrB;
    int browc = (brow < N) ? brow : 0;

    int mrow      = wm * 32 + (lane & 15);
    int acol_half = ((lane >> 4) << 3);
    int nrow_base = wn * (BNT / 2) + (lane & 7);
    int bcol_half = ((lane >> 3) & 1) << 3;

    for (int k0 = 0; k0 < K; k0 += BK) {
        // ---- stage tile into smem (uint4 chunks of 8 elems) ----
        {
            const unsigned short* pa0 = Ahi + (size_t)(bm + lrA) * K + k0 + lkA;
            #pragma unroll
            for (int c = 0; c < BK / 16; ++c)
                *(uint4*)&sAhi[lrA * LDSB + lkA + c * 8] = *(const uint4*)(pa0 + c * 8);
            if (NPASS >= 2) {
                const unsigned short* pa1 = Alo + (size_t)(bm + lrA) * K + k0 + lkA;
                #pragma unroll
                for (int c = 0; c < BK / 16; ++c)
                    *(uint4*)&sAlo[lrA * LDSB + lkA + c * 8] = *(const uint4*)(pa1 + c * 8);
            }
            const unsigned short* pb0 = Bhi + (size_t)browc * K + k0 + lkB;
            if (BNT == 128) {
                #pragma unroll
                for (int c = 0; c < BK / 16; ++c)
                    *(uint4*)&sBhi[lrB * LDSB + lkB + c * 8] = *(const uint4*)(pb0 + c * 8);
            } else {
                #pragma unroll
                for (int c = 0; c < BK / 32; ++c)
                    *(uint4*)&sBhi[lrB * LDSB + lkB + c * 8] = *(const uint4*)(pb0 + c * 8);
            }
            if (NPASS == 3) {
                const unsigned short* pb1 = Blo + (size_t)browc * K + k0 + lkB;
                if (BNT == 128) {
                    #pragma unroll
                    for (int c = 0; c < BK / 16; ++c)
                        *(uint4*)&sBlo[lrB * LDSB + lkB + c * 8] = *(const uint4*)(pb1 + c * 8);
                } else {
                    #pragma unroll
                    for (int c = 0; c < BK / 32; ++c)
                        *(uint4*)&sBlo[lrB * LDSB + lkB + c * 8] = *(const uint4*)(pb1 + c * 8);
                }
            }
        }
        __syncthreads();

        #pragma unroll
        for (int ks = 0; ks < BK / 16; ++ks) {
            int kb = ks * 16;
            uint32_t ahi[2][4], alo[2][4];
            #pragma unroll
            for (int mi = 0; mi < 2; ++mi) {
                int off = (mrow + mi * 16) * LDSB + kb + acol_half;
                LDSM4(ahi[mi], smem_u32(&sAhi[off]));
                if (NPASS >= 2) LDSM4(alo[mi], smem_u32(&sAlo[off]));
            }
            uint32_t bhi[NI][2], blo[NI][2];
            #pragma unroll
            for (int ni = 0; ni < NI; ++ni) {
                int off = (nrow_base + ni * 8) * LDSB + kb + bcol_half;
                LDSM2(bhi[ni], smem_u32(&sBhi[off]));
                if (NPASS == 3) LDSM2(blo[ni], smem_u32(&sBlo[off]));
            }
            #pragma unroll
            for (int mi = 0; mi < 2; ++mi)
                #pragma unroll
                for (int ni = 0; ni < NI; ++ni) {
                    mma16816<KIND>(acc[mi][ni], ahi[mi], bhi[ni]);
                    if (NPASS >= 2) mma16816<KIND>(acc[mi][ni], alo[mi], bhi[ni]);
                    if (NPASS == 3) mma16816<KIND>(acc[mi][ni], ahi[mi], blo[ni]);
                }
        }
        __syncthreads();
    }

    // --- epilogue ---
    int g = lane >> 2, t4 = lane & 3;
    #pragma unroll
    for (int mi = 0; mi < 2; ++mi) {
        int r0 = bm + wm * 32 + mi * 16 + g;
        #pragma unroll
        for (int ni = 0; ni < NI; ++ni) {
            int col = bn + wn * (BNT / 2) + ni * 8 + t4 * 2;
            if (col < N) {     // N even, col even -> covers col+1 too
                float2 v0 = make_float2(acc[mi][ni][0], acc[mi][ni][1]);
                float2 v1 = make_float2(acc[mi][ni][2], acc[mi][ni][3]);
                if (add) {
                    float2 a0 = *(const float2*)(add + (size_t)r0 * N + col);
                    float2 a1 = *(const float2*)(add + (size_t)(r0 + 8) * N + col);
                    v0.x += a0.x; v0.y += a0.y;
                    v1.x += a1.x; v1.y += a1.y;
                }
                *(float2*)(C + (size_t)r0 * N + col)       = v0;
                *(float2*)(C + (size_t)(r0 + 8) * N + col) = v1;
            }
        }
    }
}

// ---------------- orchestration ----------------------------------------------
extern "C" void kernel_launch(void* const* d_in, const int* in_sizes, int n_in,
                              void* d_out, int out_size) {
    const int*   ids       = (const int*)  d_in[0];
    const float* emb       = (const float*)d_in[1];
    const float* norm_ws   = (const float*)d_in[2];
    const float* in_ws     = (const float*)d_in[3];
    const float* conv_ws   = (const float*)d_in[4];
    const float* conv_bs   = (const float*)d_in[5];
    const float* dt_biases = (const float*)d_in[6];
    const float* A_logs    = (const float*)d_in[7];
    const float* Ds        = (const float*)d_in[8];
    const float* gnorm_ws  = (const float*)d_in[9];
    const float* out_ws    = (const float*)d_in[10];
    const float* norm_f_w  = (const float*)d_in[11];
    float* out = (float*)d_out;

    float *x, *zx, *xbc, *dtb, *y;
    cudaGetSymbolAddress((void**)&x,   g_x);
    cudaGetSymbolAddress((void**)&zx,  g_zx);
    cudaGetSymbolAddress((void**)&xbc, g_xbc);
    cudaGetSymbolAddress((void**)&dtb, g_dt);
    cudaGetSymbolAddress((void**)&y,   g_y);

    unsigned short *emb_h, *inw_hi, *inw_lo, *outw_hi, *outw_lo;
    unsigned short *u_hi, *u_lo, *t2_hi, *t2_lo;
    cudaGetSymbolAddress((void**)&emb_h,   g_emb_h);
    cudaGetSymbolAddress((void**)&inw_hi,  g_inw_hi);
    cudaGetSymbolAddress((void**)&inw_lo,  g_inw_lo);
    cudaGetSymbolAddress((void**)&outw_hi, g_outw_hi);
    cudaGetSymbolAddress((void**)&outw_lo, g_outw_lo);
    cudaGetSymbolAddress((void**)&u_hi,    g_u_hi);
    cudaGetSymbolAddress((void**)&u_lo,    g_u_lo);
    cudaGetSymbolAddress((void**)&t2_hi,   g_t2_hi);
    cudaGetSymbolAddress((void**)&t2_lo,   g_t2_lo);

    // (0) embed
    embed_kernel<<<(LSEQ * D_MODEL + 255) / 256, 256>>>(ids, emb, x);
    // (1) pre-norm layer 0
    rmsnorm_kernel<__nv_bfloat16><<<LSEQ, 256>>>(
        x, D_MODEL, norm_ws, nullptr, 0, u_hi, u_lo, D_MODEL);
    // (2) split in_ws
    {
        int n4 = N_LAYER * D_IN_PROJ * D_MODEL / 4;
        split_bf16_kernel<<<(n4 + 255) / 256, 256>>>(
            (const float4*)in_ws, (__nv_bfloat162*)inw_hi, (__nv_bfloat162*)inw_lo, n4);
    }
    // (3) in_proj layer 0
    gemm_mma<0, 128, 3, 32><<<dim3(LSEQ / BM, (D_IN_PROJ + 127) / 128), 256>>>(
        u_hi, u_lo, inw_hi, inw_lo, nullptr, zx, LSEQ, D_IN_PROJ, D_MODEL);
    // (4) split out_ws
    {
        int n4 = N_LAYER * D_MODEL * D_INNER / 4;
        split_bf16_kernel<<<(n4 + 255) / 256, 256>>>(
            (const float4*)out_ws, (__nv_bfloat162*)outw_hi, (__nv_bfloat162*)outw_lo, n4);
    }
    // (5) emb -> fp16
    {
        int n4 = VOCAB * D_MODEL / 4;
        cvt_half_kernel<<<(n4 + 255) / 256, 256>>>(
            (const float4*)emb, (__half2*)emb_h, n4);
    }

    for (int i = 0; i < N_LAYER; ++i) {
        if (i > 0) {
            rmsnorm_kernel<__nv_bfloat16><<<LSEQ, 256>>>(
                x, D_MODEL, norm_ws + (size_t)i * D_MODEL, nullptr, 0,
                u_hi, u_lo, D_MODEL);
            gemm_mma<0, 128, 3, 32><<<dim3(LSEQ / BM, (D_IN_PROJ + 127) / 128), 256>>>(
                u_hi, u_lo,
                inw_hi + (size_t)i * D_IN_PROJ * D_MODEL,
                inw_lo + (size_t)i * D_IN_PROJ * D_MODEL,
                nullptr, zx, LSEQ, D_IN_PROJ, D_MODEL);
        }
        dt_kernel<<<(LSEQ * NHEADS + 255) / 256, 256>>>(
            zx, dt_biases + (size_t)i * NHEADS, dtb);
        conv_kernel<<<(LSEQ * CONV_DIM + 255) / 256, 256>>>(
            zx, conv_ws + (size_t)i * CONV_DIM * D_CONV,
            conv_bs + (size_t)i * CONV_DIM, xbc);
        ssd_kernel<<<512, 128>>>(
            xbc, dtb, A_logs + (size_t)i * NHEADS, Ds + (size_t)i * NHEADS, y);
        rmsnorm_kernel<__nv_bfloat16><<<LSEQ, 256>>>(
            y, D_INNER, gnorm_ws + (size_t)i * D_INNER,
            zx, D_IN_PROJ, t2_hi, t2_lo, D_INNER);
        gemm_mma<0, 64, 3, 32><<<dim3(LSEQ / BM, D_MODEL / 64), 256>>>(
            t2_hi, t2_lo,
            outw_hi + (size_t)i * D_MODEL * D_INNER,
            outw_lo + (size_t)i * D_MODEL * D_INNER,
            x, x, LSEQ, D_MODEL, D_INNER);
    }

    // final norm (fp16) + fp16 1-pass logits with BK=64 (half the barriers)
    rmsnorm_kernel<__half><<<LSEQ, 256>>>(
        x, D_MODEL, norm_f_w, nullptr, 0, u_hi, u_lo, D_MODEL);
    gemm_mma<1, 128, 1, 64><<<dim3(LSEQ / BM, (VOCAB + 127) / 128), 256>>>(
        u_hi, u_hi, emb_h, emb_h, nullptr, out, LSEQ, VOCAB, D_MODEL);
}

// round 9
// speedup vs baseline: 1.7130x; 1.1058x over previous
#include <cuda_runtime.h>
#include <cuda_bf16.h>
#include <cuda_fp16.h>
#include <cstdint>

#define N_LAYER  4
#define D_MODEL  1024
#define D_STATE  128
#define D_CONV   4
#define HEADDIM  64
#define NHEADS   32
#define D_INNER  2048
#define CONV_DIM 2304         // D_INNER + 2*D_STATE
#define D_IN_PROJ 4384        // 2*D_INNER + 2*D_STATE + NHEADS
#define LSEQ     1024
#define VOCAB    50288
#define EPS      1e-5f

// ---------------- scratch (static device globals; no allocation) -------------
__device__ float g_x  [LSEQ * D_MODEL];
__device__ float g_zx [LSEQ * D_IN_PROJ];
__device__ float g_xbc[LSEQ * CONV_DIM];
__device__ float g_dt [LSEQ * NHEADS];
__device__ float g_y  [LSEQ * D_INNER];

// fp16 storage (raw 16-bit)
__device__ unsigned short g_emb_h [VOCAB * D_MODEL];                // fp16
__device__ unsigned short g_inw_h [N_LAYER * D_IN_PROJ * D_MODEL];  // fp16
__device__ unsigned short g_outw_h[N_LAYER * D_MODEL * D_INNER];    // fp16
__device__ unsigned short g_u_hi  [LSEQ * D_MODEL];                 // fp16 hi
__device__ unsigned short g_u_lo  [LSEQ * D_MODEL];                 // fp16 lo
__device__ unsigned short g_t2_hi [LSEQ * D_INNER];
__device__ unsigned short g_t2_lo [LSEQ * D_INNER];

// ---------------- fp32 -> fp16 (single) ---------------------------------------
__global__ void cvt_half_kernel(const float4* __restrict__ in,
                                __half2* __restrict__ out, int n4) {
    int i = blockIdx.x * blockDim.x + threadIdx.x;
    if (i >= n4) return;
    float4 v = in[i];
    out[2 * i]     = __floats2half2_rn(v.x, v.y);
    out[2 * i + 1] = __floats2half2_rn(v.z, v.w);
}

// ---------------- embedding gather ------------------------------------------
__global__ void embed_kernel(const int* __restrict__ ids,
                             const float* __restrict__ emb,
                             float* __restrict__ x) {
    int idx = blockIdx.x * blockDim.x + threadIdx.x;
    if (idx >= LSEQ * D_MODEL) return;
    int t = idx >> 10;
    int d = idx & 1023;
    x[idx] = emb[(size_t)ids[t] * D_MODEL + d];
}

// ---------------- rmsnorm (optionally gated); outputs fp16 hi/lo -------------
__global__ void rmsnorm_kernel(const float* __restrict__ x, int xs,
                               const float* __restrict__ w,
                               const float* z, int zs,
                               unsigned short* __restrict__ out_hi,
                               unsigned short* __restrict__ out_lo, int D) {
    __shared__ float buf[2048];
    __shared__ float red[8];
    __shared__ float s_scale;
    int t = blockIdx.x;
    int tid = threadIdx.x;

    float ss = 0.f;
    for (int c = tid; c < D; c += blockDim.x) {
        float v = x[(size_t)t * xs + c];
        if (z) {
            float zz = z[(size_t)t * zs + c];
            v *= zz / (1.f + expf(-zz));
        }
        buf[c] = v;
        ss += v * v;
    }
    #pragma unroll
    for (int o = 16; o; o >>= 1) ss += __shfl_xor_sync(0xffffffffu, ss, o);
    if ((tid & 31) == 0) red[tid >> 5] = ss;
    __syncthreads();
    if (tid < 32) {
        float v = (tid < 8) ? red[tid] : 0.f;
        #pragma unroll
        for (int o = 4; o; o >>= 1) v += __shfl_xor_sync(0xffffffffu, v, o);
        if (tid == 0) s_scale = rsqrtf(v / (float)D + EPS);
    }
    __syncthreads();
    float sc = s_scale;
    for (int c = tid; c < D; c += blockDim.x) {
        float v = buf[c] * sc * w[c];
        __half h = __float2half_rn(v);
        __half l = __float2half_rn(v - __half2float(h));
        out_hi[(size_t)t * D + c] = *(unsigned short*)&h;
        out_lo[(size_t)t * D + c] = *(unsigned short*)&l;
    }
}

// ---- fused depthwise conv+silu (c < CONV_DIM) and dt softplus (else) --------
__global__ void convdt_kernel(const float* __restrict__ zx,
                              const float* __restrict__ w,
                              const float* __restrict__ b,
                              const float* __restrict__ dt_bias,
                              float* __restrict__ xbc,
                              float* __restrict__ dt) {
    int idx = blockIdx.x * blockDim.x + threadIdx.x;
    if (idx >= LSEQ * (CONV_DIM + NHEADS)) return;
    int t = idx / (CONV_DIM + NHEADS);
    int c = idx - t * (CONV_DIM + NHEADS);
    if (c < CONV_DIM) {
        float acc = b[c];
        const float* wc = w + c * 4;
        #pragma unroll
        for (int j = 0; j < 4; ++j) {
            int tt = t - 3 + j;
            if (tt >= 0) acc += zx[(size_t)tt * D_IN_PROJ + D_INNER + c] * wc[j];
        }
        xbc[(size_t)t * CONV_DIM + c] = acc / (1.f + expf(-acc));
    } else {
        int h = c - CONV_DIM;
        float v = zx[(size_t)t * D_IN_PROJ + (D_INNER + CONV_DIM) + h] + dt_bias[h];
        dt[t * NHEADS + h] = (v > 20.f) ? v : log1pf(expf(v));
    }
}

// ---------------- SSD scan: warp per (h,p), float4 B/C loads -----------------
__global__ void ssd_kernel(const float* __restrict__ xbc,
                           const float* __restrict__ dt,
                           const float* __restrict__ A_log,
                           const float* __restrict__ D_p,
                           float* __restrict__ y) {
    int gw   = (blockIdx.x * blockDim.x + threadIdx.x) >> 5;
    int lane = threadIdx.x & 31;
    int h = gw >> 6;
    int p = gw & 63;

    float Ah = -expf(A_log[h]);
    float Dh = D_p[h];
    float hs0 = 0.f, hs1 = 0.f, hs2 = 0.f, hs3 = 0.f;

    float4 rB[3], rC[3];
    float rX[3], rDT[3];
    #pragma unroll
    for (int s = 0; s < 3; ++s) {
        const float* row = xbc + (size_t)s * CONV_DIM;
        rB[s] = __ldg((const float4*)(row + D_INNER) + lane);
        rC[s] = __ldg((const float4*)(row + D_INNER + D_STATE) + lane);
        rX[s]  = __ldg(row + h * HEADDIM + p);
        rDT[s] = __ldg(dt + s * NHEADS + h);
    }

    for (int t0 = 0; t0 < LSEQ; t0 += 3) {
        #pragma unroll
        for (int s = 0; s < 3; ++s) {
            int t = t0 + s;
            if (t >= LSEQ) break;
            float dtv  = rDT[s];
            float xraw = rX[s];
            float e  = __expf(Ah * dtv);
            float xd = xraw * dtv;
            float acc;
            hs0 = e * hs0 + rB[s].x * xd;
            hs1 = e * hs1 + rB[s].y * xd;
            hs2 = e * hs2 + rB[s].z * xd;
            hs3 = e * hs3 + rB[s].w * xd;
            acc  = rC[s].x * hs0;
            acc += rC[s].y * hs1;
            acc += rC[s].z * hs2;
            acc += rC[s].w * hs3;
            #pragma unroll
            for (int o = 16; o; o >>= 1) acc += __shfl_xor_sync(0xffffffffu, acc, o);
            if (lane == 0)
                y[(size_t)t * D_INNER + h * HEADDIM + p] = acc + xraw * Dh;

            int tn = t + 3;
            if (tn > LSEQ - 1) tn = LSEQ - 1;
            const float* row = xbc + (size_t)tn * CONV_DIM;
            rB[s] = __ldg((const float4*)(row + D_INNER) + lane);
            rC[s] = __ldg((const float4*)(row + D_INNER + D_STATE) + lane);
            rX[s]  = __ldg(row + h * HEADDIM + p);
            rDT[s] = __ldg(dt + tn * NHEADS + h);
        }
    }
}

// =============================================================================
// fp16 split-precision tensor-core GEMM (NT): C[m,n] = sum_k A[m,k]*B[n,k]
// NPASS: 2 = Ahi*B + Alo*B (A exact to 22 bits, B single fp16); 1 = Ahi*B.
// BNT: 128 (warp 32x64) or 64 (warp 32x32). BM=128, 256 threads.
// BK: 32 or 64; LDSB = BK+8 (16B-aligned rows, conflict-free ldmatrix).
// Static smem, single buffer.
// =============================================================================
#define BM 128

#define LDSM4(R, addr) asm volatile( \
    "ldmatrix.sync.aligned.m8n8.x4.shared.b16 {%0,%1,%2,%3}, [%4];" \
    : "=r"((R)[0]),"=r"((R)[1]),"=r"((R)[2]),"=r"((R)[3]) : "r"(addr))
#define LDSM2(R, addr) asm volatile( \
    "ldmatrix.sync.aligned.m8n8.x2.shared.b16 {%0,%1}, [%2];" \
    : "=r"((R)[0]),"=r"((R)[1]) : "r"(addr))

__device__ __forceinline__ uint32_t smem_u32(const void* p) {
    return (uint32_t)__cvta_generic_to_shared(p);
}

__device__ __forceinline__ void mma_f16(float* acc, const uint32_t* a,
                                        const uint32_t* b) {
    asm volatile(
        "mma.sync.aligned.m16n8k16.row.col.f32.f16.f16.f32 "
        "{%0,%1,%2,%3},{%4,%5,%6,%7},{%8,%9},{%0,%1,%2,%3};"
        : "+f"(acc[0]), "+f"(acc[1]), "+f"(acc[2]), "+f"(acc[3])
        : "r"(a[0]), "r"(a[1]), "r"(a[2]), "r"(a[3]), "r"(b[0]), "r"(b[1]));
}

template<int BNT, int NPASS, int BK>
__global__ __launch_bounds__(256) void gemm_mma(
    const unsigned short* __restrict__ Ahi, const unsigned short* __restrict__ Alo,
    const unsigned short* __restrict__ Bh,
    const float* add, float* __restrict__ C, int M, int N, int K) {
    constexpr int NI   = BNT / 16;
    constexpr int LDSB = BK + 8;
    __shared__ unsigned short sAhi[BM * LDSB];
    __shared__ unsigned short sAlo[(NPASS >= 2 ? BM : 8) * LDSB];
    __shared__ unsigned short sBh [BNT * LDSB];

    int tid  = threadIdx.x;
    int wid  = tid >> 5, lane = tid & 31;
    int wm   = wid & 3;
    int wn   = wid >> 2;
    int bm   = blockIdx.x * BM;
    int bn   = blockIdx.y * BNT;

    float acc[2][NI][4];
    #pragma unroll
    for (int i = 0; i < 2; ++i)
        #pragma unroll
        for (int j = 0; j < NI; ++j)
            #pragma unroll
            for (int q = 0; q < 4; ++q) acc[i][j][q] = 0.f;

    // A: 2 threads/row, BK/2 elems each
    int lrA = tid >> 1;
    int lkA = (tid & 1) * (BK / 2);
    // B
    int lrB, lkB;
    if (BNT == 128) { lrB = tid >> 1; lkB = (tid & 1) * (BK / 2); }
    else            { lrB = tid >> 2; lkB = (tid & 3) * (BK / 4); }
    int brow  = bn + lrB;
    int browc = (brow < N) ? brow : 0;

    int mrow      = wm * 32 + (lane & 15);
    int acol_half = ((lane >> 4) << 3);
    int nrow_base = wn * (BNT / 2) + (lane & 7);
    int bcol_half = ((lane >> 3) & 1) << 3;

    for (int k0 = 0; k0 < K; k0 += BK) {
        {
            const unsigned short* pa0 = Ahi + (size_t)(bm + lrA) * K + k0 + lkA;
            #pragma unroll
            for (int c = 0; c < BK / 16; ++c)
                *(uint4*)&sAhi[lrA * LDSB + lkA + c * 8] = *(const uint4*)(pa0 + c * 8);
            if (NPASS >= 2) {
                const unsigned short* pa1 = Alo + (size_t)(bm + lrA) * K + k0 + lkA;
                #pragma unroll
                for (int c = 0; c < BK / 16; ++c)
                    *(uint4*)&sAlo[lrA * LDSB + lkA + c * 8] = *(const uint4*)(pa1 + c * 8);
            }
            const unsigned short* pb0 = Bh + (size_t)browc * K + k0 + lkB;
            if (BNT == 128) {
                #pragma unroll
                for (int c = 0; c < BK / 16; ++c)
                    *(uint4*)&sBh[lrB * LDSB + lkB + c * 8] = *(const uint4*)(pb0 + c * 8);
            } else {
                #pragma unroll
                for (int c = 0; c < BK / 32; ++c)
                    *(uint4*)&sBh[lrB * LDSB + lkB + c * 8] = *(const uint4*)(pb0 + c * 8);
            }
        }
        __syncthreads();

        #pragma unroll
        for (int ks = 0; ks < BK / 16; ++ks) {
            int kb = ks * 16;
            uint32_t ahi[2][4], alo[2][4];
            #pragma unroll
            for (int mi = 0; mi < 2; ++mi) {
                int off = (mrow + mi * 16) * LDSB + kb + acol_half;
                LDSM4(ahi[mi], smem_u32(&sAhi[off]));
                if (NPASS >= 2) LDSM4(alo[mi], smem_u32(&sAlo[off]));
            }
            uint32_t bh[NI][2];
            #pragma unroll
            for (int ni = 0; ni < NI; ++ni) {
                int off = (nrow_base + ni * 8) * LDSB + kb + bcol_half;
                LDSM2(bh[ni], smem_u32(&sBh[off]));
            }
            #pragma unroll
            for (int mi = 0; mi < 2; ++mi)
                #pragma unroll
                for (int ni = 0; ni < NI; ++ni) {
                    mma_f16(acc[mi][ni], ahi[mi], bh[ni]);
                    if (NPASS >= 2) mma_f16(acc[mi][ni], alo[mi], bh[ni]);
                }
        }
        __syncthreads();
    }

    // --- epilogue ---
    int g = lane >> 2, t4 = lane & 3;
    #pragma unroll
    for (int mi = 0; mi < 2; ++mi) {
        int r0 = bm + wm * 32 + mi * 16 + g;
        #pragma unroll
        for (int ni = 0; ni < NI; ++ni) {
            int col = bn + wn * (BNT / 2) + ni * 8 + t4 * 2;
            if (col < N) {     // N even, col even -> covers col+1 too
                float2 v0 = make_float2(acc[mi][ni][0], acc[mi][ni][1]);
                float2 v1 = make_float2(acc[mi][ni][2], acc[mi][ni][3]);
                if (add) {
                    float2 a0 = *(const float2*)(add + (size_t)r0 * N + col);
                    float2 a1 = *(const float2*)(add + (size_t)(r0 + 8) * N + col);
                    v0.x += a0.x; v0.y += a0.y;
                    v1.x += a1.x; v1.y += a1.y;
                }
                *(float2*)(C + (size_t)r0 * N + col)       = v0;
                *(float2*)(C + (size_t)(r0 + 8) * N + col) = v1;
            }
        }
    }
}

// ---------------- orchestration ----------------------------------------------
extern "C" void kernel_launch(void* const* d_in, const int* in_sizes, int n_in,
                              void* d_out, int out_size) {
    const int*   ids       = (const int*)  d_in[0];
    const float* emb       = (const float*)d_in[1];
    const float* norm_ws   = (const float*)d_in[2];
    const float* in_ws     = (const float*)d_in[3];
    const float* conv_ws   = (const float*)d_in[4];
    const float* conv_bs   = (const float*)d_in[5];
    const float* dt_biases = (const float*)d_in[6];
    const float* A_logs    = (const float*)d_in[7];
    const float* Ds        = (const float*)d_in[8];
    const float* gnorm_ws  = (const float*)d_in[9];
    const float* out_ws    = (const float*)d_in[10];
    const float* norm_f_w  = (const float*)d_in[11];
    float* out = (float*)d_out;

    float *x, *zx, *xbc, *dtb, *y;
    cudaGetSymbolAddress((void**)&x,   g_x);
    cudaGetSymbolAddress((void**)&zx,  g_zx);
    cudaGetSymbolAddress((void**)&xbc, g_xbc);
    cudaGetSymbolAddress((void**)&dtb, g_dt);
    cudaGetSymbolAddress((void**)&y,   g_y);

    unsigned short *emb_h, *inw_h, *outw_h, *u_hi, *u_lo, *t2_hi, *t2_lo;
    cudaGetSymbolAddress((void**)&emb_h,  g_emb_h);
    cudaGetSymbolAddress((void**)&inw_h,  g_inw_h);
    cudaGetSymbolAddress((void**)&outw_h, g_outw_h);
    cudaGetSymbolAddress((void**)&u_hi,   g_u_hi);
    cudaGetSymbolAddress((void**)&u_lo,   g_u_lo);
    cudaGetSymbolAddress((void**)&t2_hi,  g_t2_hi);
    cudaGetSymbolAddress((void**)&t2_lo,  g_t2_lo);

    // (0) embed
    embed_kernel<<<(LSEQ * D_MODEL + 255) / 256, 256>>>(ids, emb, x);
    // (1) pre-norm layer 0
    rmsnorm_kernel<<<LSEQ, 256>>>(x, D_MODEL, norm_ws, nullptr, 0,
                                  u_hi, u_lo, D_MODEL);
    // (2) cvt in_ws -> fp16
    {
        int n4 = N_LAYER * D_IN_PROJ * D_MODEL / 4;
        cvt_half_kernel<<<(n4 + 255) / 256, 256>>>(
            (const float4*)in_ws, (__half2*)inw_h, n4);
    }
    // (3) in_proj layer 0  <-- profiled slot (fp16 2-pass)
    gemm_mma<128, 2, 32><<<dim3(LSEQ / BM, (D_IN_PROJ + 127) / 128), 256>>>(
        u_hi, u_lo, inw_h, nullptr, zx, LSEQ, D_IN_PROJ, D_MODEL);
    // (4) cvt out_ws -> fp16
    {
        int n4 = N_LAYER * D_MODEL * D_INNER / 4;
        cvt_half_kernel<<<(n4 + 255) / 256, 256>>>(
            (const float4*)out_ws, (__half2*)outw_h, n4);
    }
    // (5) cvt emb -> fp16
    {
        int n4 = VOCAB * D_MODEL / 4;
        cvt_half_kernel<<<(n4 + 255) / 256, 256>>>(
            (const float4*)emb, (__half2*)emb_h, n4);
    }

    for (int i = 0; i < N_LAYER; ++i) {
        if (i > 0) {
            rmsnorm_kernel<<<LSEQ, 256>>>(
                x, D_MODEL, norm_ws + (size_t)i * D_MODEL, nullptr, 0,
                u_hi, u_lo, D_MODEL);
            gemm_mma<128, 2, 32><<<dim3(LSEQ / BM, (D_IN_PROJ + 127) / 128), 256>>>(
                u_hi, u_lo, inw_h + (size_t)i * D_IN_PROJ * D_MODEL,
                nullptr, zx, LSEQ, D_IN_PROJ, D_MODEL);
        }
        convdt_kernel<<<(LSEQ * (CONV_DIM + NHEADS) + 255) / 256, 256>>>(
            zx, conv_ws + (size_t)i * CONV_DIM * D_CONV,
            conv_bs + (size_t)i * CONV_DIM,
            dt_biases + (size_t)i * NHEADS, xbc, dtb);
        ssd_kernel<<<512, 128>>>(
            xbc, dtb, A_logs + (size_t)i * NHEADS, Ds + (size_t)i * NHEADS, y);
        rmsnorm_kernel<<<LSEQ, 256>>>(
            y, D_INNER, gnorm_ws + (size_t)i * D_INNER,
            zx, D_IN_PROJ, t2_hi, t2_lo, D_INNER);
        // out_proj + residual: fp16 2-pass, BK=64
        gemm_mma<64, 2, 64><<<dim3(LSEQ / BM, D_MODEL / 64), 256>>>(
            t2_hi, t2_lo, outw_h + (size_t)i * D_MODEL * D_INNER,
            x, x, LSEQ, D_MODEL, D_INNER);
    }

    // final norm + fp16 1-pass logits
    rmsnorm_kernel<<<LSEQ, 256>>>(x, D_MODEL, norm_f_w, nullptr, 0,
                                  u_hi, u_lo, D_MODEL);
    gemm_mma<128, 1, 64><<<dim3(LSEQ / BM, (VOCAB + 127) / 128), 256>>>(
        u_hi, u_hi, emb_h, nullptr, out, LSEQ, VOCAB, D_MODEL);
}

// round 10
// speedup vs baseline: 1.7330x; 1.0117x over previous
#include <cuda_runtime.h>
#include <cuda_bf16.h>
#include <cuda_fp16.h>
#include <cstdint>

#define N_LAYER  4
#define D_MODEL  1024
#define D_STATE  128
#define D_CONV   4
#define HEADDIM  64
#define NHEADS   32
#define D_INNER  2048
#define CONV_DIM 2304         // D_INNER + 2*D_STATE
#define D_IN_PROJ 4384        // 2*D_INNER + 2*D_STATE + NHEADS
#define LSEQ     1024
#define VOCAB    50288
#define EPS      1e-5f

// ---------------- scratch (static device globals; no allocation) -------------
__device__ float g_x  [LSEQ * D_MODEL];
__device__ float g_zx [LSEQ * D_IN_PROJ];
__device__ float g_xbc[LSEQ * CONV_DIM];
__device__ float g_dt [LSEQ * NHEADS];
__device__ float g_y  [LSEQ * D_INNER];

// fp16 storage (raw 16-bit)
__device__ unsigned short g_emb_h [VOCAB * D_MODEL];                // fp16
__device__ unsigned short g_inw_h [N_LAYER * D_IN_PROJ * D_MODEL];  // fp16
__device__ unsigned short g_outw_h[N_LAYER * D_MODEL * D_INNER];    // fp16
__device__ unsigned short g_u_hi  [LSEQ * D_MODEL];                 // fp16 hi
__device__ unsigned short g_u_lo  [LSEQ * D_MODEL];                 // fp16 lo
__device__ unsigned short g_t2_hi [LSEQ * D_INNER];
__device__ unsigned short g_t2_lo [LSEQ * D_INNER];

// ---------------- fp32 -> fp16 (single) ---------------------------------------
__global__ void cvt_half_kernel(const float4* __restrict__ in,
                                __half2* __restrict__ out, int n4) {
    int i = blockIdx.x * blockDim.x + threadIdx.x;
    if (i >= n4) return;
    float4 v = in[i];
    out[2 * i]     = __floats2half2_rn(v.x, v.y);
    out[2 * i + 1] = __floats2half2_rn(v.z, v.w);
}

// ---------------- embedding gather ------------------------------------------
__global__ void embed_kernel(const int* __restrict__ ids,
                             const float* __restrict__ emb,
                             float* __restrict__ x) {
    int idx = blockIdx.x * blockDim.x + threadIdx.x;
    if (idx >= LSEQ * D_MODEL) return;
    int t = idx >> 10;
    int d = idx & 1023;
    x[idx] = emb[(size_t)ids[t] * D_MODEL + d];
}

// ---------------- rmsnorm (optionally gated); outputs fp16 hi/lo -------------
__global__ void rmsnorm_kernel(const float* __restrict__ x, int xs,
                               const float* __restrict__ w,
                               const float* z, int zs,
                               unsigned short* __restrict__ out_hi,
                               unsigned short* __restrict__ out_lo, int D) {
    __shared__ float buf[2048];
    __shared__ float red[8];
    __shared__ float s_scale;
    int t = blockIdx.x;
    int tid = threadIdx.x;

    float ss = 0.f;
    for (int c = tid; c < D; c += blockDim.x) {
        float v = x[(size_t)t * xs + c];
        if (z) {
            float zz = z[(size_t)t * zs + c];
            v *= zz / (1.f + expf(-zz));
        }
        buf[c] = v;
        ss += v * v;
    }
    #pragma unroll
    for (int o = 16; o; o >>= 1) ss += __shfl_xor_sync(0xffffffffu, ss, o);
    if ((tid & 31) == 0) red[tid >> 5] = ss;
    __syncthreads();
    if (tid < 32) {
        float v = (tid < 8) ? red[tid] : 0.f;
        #pragma unroll
        for (int o = 4; o; o >>= 1) v += __shfl_xor_sync(0xffffffffu, v, o);
        if (tid == 0) s_scale = rsqrtf(v / (float)D + EPS);
    }
    __syncthreads();
    float sc = s_scale;
    for (int c = tid; c < D; c += blockDim.x) {
        float v = buf[c] * sc * w[c];
        __half h = __float2half_rn(v);
        __half l = __float2half_rn(v - __half2float(h));
        out_hi[(size_t)t * D + c] = *(unsigned short*)&h;
        out_lo[(size_t)t * D + c] = *(unsigned short*)&l;
    }
}

// ---- fused depthwise conv+silu (c < CONV_DIM) and dt softplus (else) --------
__global__ void convdt_kernel(const float* __restrict__ zx,
                              const float* __restrict__ w,
                              const float* __restrict__ b,
                              const float* __restrict__ dt_bias,
                              float* __restrict__ xbc,
                              float* __restrict__ dt) {
    int idx = blockIdx.x * blockDim.x + threadIdx.x;
    if (idx >= LSEQ * (CONV_DIM + NHEADS)) return;
    int t = idx / (CONV_DIM + NHEADS);
    int c = idx - t * (CONV_DIM + NHEADS);
    if (c < CONV_DIM) {
        float acc = b[c];
        const float* wc = w + c * 4;
        #pragma unroll
        for (int j = 0; j < 4; ++j) {
            int tt = t - 3 + j;
            if (tt >= 0) acc += zx[(size_t)tt * D_IN_PROJ + D_INNER + c] * wc[j];
        }
        xbc[(size_t)t * CONV_DIM + c] = acc / (1.f + expf(-acc));
    } else {
        int h = c - CONV_DIM;
        float v = zx[(size_t)t * D_IN_PROJ + (D_INNER + CONV_DIM) + h] + dt_bias[h];
        dt[t * NHEADS + h] = (v > 20.f) ? v : log1pf(expf(v));
    }
}

// ------- SSD scan: warp per (h, p-pair); B/C/dt/exp amortized over 2 ch ------
__global__ void ssd_kernel(const float* __restrict__ xbc,
                           const float* __restrict__ dt,
                           const float* __restrict__ A_log,
                           const float* __restrict__ D_p,
                           float* __restrict__ y) {
    int gw   = (blockIdx.x * blockDim.x + threadIdx.x) >> 5;  // 0..1023
    int lane = threadIdx.x & 31;
    int h  = gw >> 5;            // head (32 warps per head)
    int p0 = (gw & 31) * 2;      // even channel; p1 = p0 + 1

    float Ah = -expf(A_log[h]);
    float Dh = D_p[h];
    float a0 = 0.f, a1 = 0.f, a2 = 0.f, a3 = 0.f;   // state, channel p0
    float b0 = 0.f, b1 = 0.f, b2 = 0.f, b3 = 0.f;   // state, channel p1

    float4 rB[3], rC[3];
    float2 rX[3];
    float  rDT[3];
    #pragma unroll
    for (int s = 0; s < 3; ++s) {
        const float* row = xbc + (size_t)s * CONV_DIM;
        rB[s] = __ldg((const float4*)(row + D_INNER) + lane);
        rC[s] = __ldg((const float4*)(row + D_INNER + D_STATE) + lane);
        rX[s] = __ldg((const float2*)(row + h * HEADDIM) + (p0 >> 1));
        rDT[s] = __ldg(dt + s * NHEADS + h);
    }

    for (int t0 = 0; t0 < LSEQ; t0 += 3) {
        #pragma unroll
        for (int s = 0; s < 3; ++s) {
            int t = t0 + s;
            if (t >= LSEQ) break;
            float dtv = rDT[s];
            float e   = __expf(Ah * dtv);
            float x0  = rX[s].x, x1 = rX[s].y;
            float xd0 = x0 * dtv, xd1 = x1 * dtv;

            a0 = e * a0 + rB[s].x * xd0;
            a1 = e * a1 + rB[s].y * xd0;
            a2 = e * a2 + rB[s].z * xd0;
            a3 = e * a3 + rB[s].w * xd0;
            b0 = e * b0 + rB[s].x * xd1;
            b1 = e * b1 + rB[s].y * xd1;
            b2 = e * b2 + rB[s].z * xd1;
            b3 = e * b3 + rB[s].w * xd1;

            float acc0 = rC[s].x * a0 + rC[s].y * a1 + rC[s].z * a2 + rC[s].w * a3;
            float acc1 = rC[s].x * b0 + rC[s].y * b1 + rC[s].z * b2 + rC[s].w * b3;
            #pragma unroll
            for (int o = 16; o; o >>= 1) {
                acc0 += __shfl_xor_sync(0xffffffffu, acc0, o);
                acc1 += __shfl_xor_sync(0xffffffffu, acc1, o);
            }
            if (lane == 0) {
                float2 yo = make_float2(acc0 + x0 * Dh, acc1 + x1 * Dh);
                *(float2*)(y + (size_t)t * D_INNER + h * HEADDIM + p0) = yo;
            }

            int tn = t + 3;
            if (tn > LSEQ - 1) tn = LSEQ - 1;
            const float* row = xbc + (size_t)tn * CONV_DIM;
            rB[s] = __ldg((const float4*)(row + D_INNER) + lane);
            rC[s] = __ldg((const float4*)(row + D_INNER + D_STATE) + lane);
            rX[s] = __ldg((const float2*)(row + h * HEADDIM) + (p0 >> 1));
            rDT[s] = __ldg(dt + tn * NHEADS + h);
        }
    }
}

// =============================================================================
// fp16 split-precision tensor-core GEMM (NT): C[m,n] = sum_k A[m,k]*B[n,k]
// NPASS: 2 = Ahi*B + Alo*B (A exact to 22 bits); 1 = Ahi*B.
// BNT: 128 / 64 / 32 (warp n-strip = BNT/2). BM=128, 256 threads.
// BK: 32 or 64; LDSB = BK+8. Static smem, single buffer.
// =============================================================================
#define BM 128

#define LDSM4(R, addr) asm volatile( \
    "ldmatrix.sync.aligned.m8n8.x4.shared.b16 {%0,%1,%2,%3}, [%4];" \
    : "=r"((R)[0]),"=r"((R)[1]),"=r"((R)[2]),"=r"((R)[3]) : "r"(addr))
#define LDSM2(R, addr) asm volatile( \
    "ldmatrix.sync.aligned.m8n8.x2.shared.b16 {%0,%1}, [%2];" \
    : "=r"((R)[0]),"=r"((R)[1]) : "r"(addr))

__device__ __forceinline__ uint32_t smem_u32(const void* p) {
    return (uint32_t)__cvta_generic_to_shared(p);
}

__device__ __forceinline__ void mma_f16(float* acc, const uint32_t* a,
                                        const uint32_t* b) {
    asm volatile(
        "mma.sync.aligned.m16n8k16.row.col.f32.f16.f16.f32 "
        "{%0,%1,%2,%3},{%4,%5,%6,%7},{%8,%9},{%0,%1,%2,%3};"
        : "+f"(acc[0]), "+f"(acc[1]), "+f"(acc[2]), "+f"(acc[3])
        : "r"(a[0]), "r"(a[1]), "r"(a[2]), "r"(a[3]), "r"(b[0]), "r"(b[1]));
}

template<int BNT, int NPASS, int BK>
__global__ __launch_bounds__(256) void gemm_mma(
    const unsigned short* __restrict__ Ahi, const unsigned short* __restrict__ Alo,
    const unsigned short* __restrict__ Bh,
    const float* add, float* __restrict__ C, int M, int N, int K) {
    constexpr int NI   = BNT / 16;
    constexpr int LDSB = BK + 8;
    constexpr int CHB  = (BNT * BK) / 2048;   // uint4 chunks per thread for B
    __shared__ unsigned short sAhi[BM * LDSB];
    __shared__ unsigned short sAlo[(NPASS >= 2 ? BM : 8) * LDSB];
    __shared__ unsigned short sBh [BNT * LDSB];

    int tid  = threadIdx.x;
    int wid  = tid >> 5, lane = tid & 31;
    int wm   = wid & 3;
    int wn   = wid >> 2;
    int bm   = blockIdx.x * BM;
    int bn   = blockIdx.y * BNT;

    float acc[2][NI][4];
    #pragma unroll
    for (int i = 0; i < 2; ++i)
        #pragma unroll
        for (int j = 0; j < NI; ++j)
            #pragma unroll
            for (int q = 0; q < 4; ++q) acc[i][j][q] = 0.f;

    // A: 2 threads/row, BK/2 elems each
    int lrA = tid >> 1;
    int lkA = (tid & 1) * (BK / 2);
    // B: 256/BNT threads per row, CHB*8 elems each
    constexpr int TPR = 256 / BNT;
    int lrB = tid / TPR;
    int lkB = (tid % TPR) * (CHB * 8);
    int brow  = bn + lrB;
    int browc = (brow < N) ? brow : 0;

    int mrow      = wm * 32 + (lane & 15);
    int acol_half = ((lane >> 4) << 3);
    int nrow_base = wn * (BNT / 2) + (lane & 7);
    int bcol_half = ((lane >> 3) & 1) << 3;

    for (int k0 = 0; k0 < K; k0 += BK) {
        {
            const unsigned short* pa0 = Ahi + (size_t)(bm + lrA) * K + k0 + lkA;
            #pragma unroll
            for (int c = 0; c < BK / 16; ++c)
                *(uint4*)&sAhi[lrA * LDSB + lkA + c * 8] = *(const uint4*)(pa0 + c * 8);
            if (NPASS >= 2) {
                const unsigned short* pa1 = Alo + (size_t)(bm + lrA) * K + k0 + lkA;
                #pragma unroll
                for (int c = 0; c < BK / 16; ++c)
                    *(uint4*)&sAlo[lrA * LDSB + lkA + c * 8] = *(const uint4*)(pa1 + c * 8);
            }
            const unsigned short* pb0 = Bh + (size_t)browc * K + k0 + lkB;
            #pragma unroll
            for (int c = 0; c < CHB; ++c)
                *(uint4*)&sBh[lrB * LDSB + lkB + c * 8] = *(const uint4*)(pb0 + c * 8);
        }
        __syncthreads();

        #pragma unroll
        for (int ks = 0; ks < BK / 16; ++ks) {
            int kb = ks * 16;
            uint32_t ahi[2][4], alo[2][4];
            #pragma unroll
            for (int mi = 0; mi < 2; ++mi) {
                int off = (mrow + mi * 16) * LDSB + kb + acol_half;
                LDSM4(ahi[mi], smem_u32(&sAhi[off]));
                if (NPASS >= 2) LDSM4(alo[mi], smem_u32(&sAlo[off]));
            }
            uint32_t bh[NI][2];
            #pragma unroll
            for (int ni = 0; ni < NI; ++ni) {
                int off = (nrow_base + ni * 8) * LDSB + kb + bcol_half;
                LDSM2(bh[ni], smem_u32(&sBh[off]));
            }
            #pragma unroll
            for (int mi = 0; mi < 2; ++mi)
                #pragma unroll
                for (int ni = 0; ni < NI; ++ni) {
                    mma_f16(acc[mi][ni], ahi[mi], bh[ni]);
                    if (NPASS >= 2) mma_f16(acc[mi][ni], alo[mi], bh[ni]);
                }
        }
        __syncthreads();
    }

    // --- epilogue ---
    int g = lane >> 2, t4 = lane & 3;
    #pragma unroll
    for (int mi = 0; mi < 2; ++mi) {
        int r0 = bm + wm * 32 + mi * 16 + g;
        #pragma unroll
        for (int ni = 0; ni < NI; ++ni) {
            int col = bn + wn * (BNT / 2) + ni * 8 + t4 * 2;
            if (col < N) {     // N even, col even -> covers col+1 too
                float2 v0 = make_float2(acc[mi][ni][0], acc[mi][ni][1]);
                float2 v1 = make_float2(acc[mi][ni][2], acc[mi][ni][3]);
                if (add) {
                    float2 a0 = *(const float2*)(add + (size_t)r0 * N + col);
                    float2 a1 = *(const float2*)(add + (size_t)(r0 + 8) * N + col);
                    v0.x += a0.x; v0.y += a0.y;
                    v1.x += a1.x; v1.y += a1.y;
                }
                *(float2*)(C + (size_t)r0 * N + col)       = v0;
                *(float2*)(C + (size_t)(r0 + 8) * N + col) = v1;
            }
        }
    }
}

// ---------------- orchestration ----------------------------------------------
extern "C" void kernel_launch(void* const* d_in, const int* in_sizes, int n_in,
                              void* d_out, int out_size) {
    const int*   ids       = (const int*)  d_in[0];
    const float* emb       = (const float*)d_in[1];
    const float* norm_ws   = (const float*)d_in[2];
    const float* in_ws     = (const float*)d_in[3];
    const float* conv_ws   = (const float*)d_in[4];
    const float* conv_bs   = (const float*)d_in[5];
    const float* dt_biases = (const float*)d_in[6];
    const float* A_logs    = (const float*)d_in[7];
    const float* Ds        = (const float*)d_in[8];
    const float* gnorm_ws  = (const float*)d_in[9];
    const float* out_ws    = (const float*)d_in[10];
    const float* norm_f_w  = (const float*)d_in[11];
    float* out = (float*)d_out;

    float *x, *zx, *xbc, *dtb, *y;
    cudaGetSymbolAddress((void**)&x,   g_x);
    cudaGetSymbolAddress((void**)&zx,  g_zx);
    cudaGetSymbolAddress((void**)&xbc, g_xbc);
    cudaGetSymbolAddress((void**)&dtb, g_dt);
    cudaGetSymbolAddress((void**)&y,   g_y);

    unsigned short *emb_h, *inw_h, *outw_h, *u_hi, *u_lo, *t2_hi, *t2_lo;
    cudaGetSymbolAddress((void**)&emb_h,  g_emb_h);
    cudaGetSymbolAddress((void**)&inw_h,  g_inw_h);
    cudaGetSymbolAddress((void**)&outw_h, g_outw_h);
    cudaGetSymbolAddress((void**)&u_hi,   g_u_hi);
    cudaGetSymbolAddress((void**)&u_lo,   g_u_lo);
    cudaGetSymbolAddress((void**)&t2_hi,  g_t2_hi);
    cudaGetSymbolAddress((void**)&t2_lo,  g_t2_lo);

    // (0) embed
    embed_kernel<<<(LSEQ * D_MODEL + 255) / 256, 256>>>(ids, emb, x);
    // (1) pre-norm layer 0
    rmsnorm_kernel<<<LSEQ, 256>>>(x, D_MODEL, norm_ws, nullptr, 0,
                                  u_hi, u_lo, D_MODEL);
    // (2) cvt in_ws -> fp16
    {
        int n4 = N_LAYER * D_IN_PROJ * D_MODEL / 4;
        cvt_half_kernel<<<(n4 + 255) / 256, 256>>>(
            (const float4*)in_ws, (__half2*)inw_h, n4);
    }
    // (3) in_proj layer 0
    gemm_mma<128, 2, 32><<<dim3(LSEQ / BM, (D_IN_PROJ + 127) / 128), 256>>>(
        u_hi, u_lo, inw_h, nullptr, zx, LSEQ, D_IN_PROJ, D_MODEL);
    // (4) cvt out_ws -> fp16
    {
        int n4 = N_LAYER * D_MODEL * D_INNER / 4;
        cvt_half_kernel<<<(n4 + 255) / 256, 256>>>(
            (const float4*)out_ws, (__half2*)outw_h, n4);
    }
    // (5) cvt emb -> fp16
    {
        int n4 = VOCAB * D_MODEL / 4;
        cvt_half_kernel<<<(n4 + 255) / 256, 256>>>(
            (const float4*)emb, (__half2*)emb_h, n4);
    }

    for (int i = 0; i < N_LAYER; ++i) {
        if (i > 0) {
            rmsnorm_kernel<<<LSEQ, 256>>>(
                x, D_MODEL, norm_ws + (size_t)i * D_MODEL, nullptr, 0,
                u_hi, u_lo, D_MODEL);
            gemm_mma<128, 2, 32><<<dim3(LSEQ / BM, (D_IN_PROJ + 127) / 128), 256>>>(
                u_hi, u_lo, inw_h + (size_t)i * D_IN_PROJ * D_MODEL,
                nullptr, zx, LSEQ, D_IN_PROJ, D_MODEL);
        }
        convdt_kernel<<<(LSEQ * (CONV_DIM + NHEADS) + 255) / 256, 256>>>(
            zx, conv_ws + (size_t)i * CONV_DIM * D_CONV,
            conv_bs + (size_t)i * CONV_DIM,
            dt_biases + (size_t)i * NHEADS, xbc, dtb);
        ssd_kernel<<<256, 128>>>(
            xbc, dtb, A_logs + (size_t)i * NHEADS, Ds + (size_t)i * NHEADS, y);
        rmsnorm_kernel<<<LSEQ, 256>>>(
            y, D_INNER, gnorm_ws + (size_t)i * D_INNER,
            zx, D_IN_PROJ, t2_hi, t2_lo, D_INNER);
        // out_proj + residual: fp16 2-pass, BNT=32 (256-block grid), BK=64
        gemm_mma<32, 2, 64><<<dim3(LSEQ / BM, D_MODEL / 32), 256>>>(
            t2_hi, t2_lo, outw_h + (size_t)i * D_MODEL * D_INNER,
            x, x, LSEQ, D_MODEL, D_INNER);
    }

    // final norm + fp16 1-pass logits
    rmsnorm_kernel<<<LSEQ, 256>>>(x, D_MODEL, norm_f_w, nullptr, 0,
                                  u_hi, u_lo, D_MODEL);
    gemm_mma<128, 1, 64><<<dim3(LSEQ / BM, (VOCAB + 127) / 128), 256>>>(
        u_hi, u_hi, emb_h, nullptr, out, LSEQ, VOCAB, D_MODEL);
}

// round 11
// speedup vs baseline: 1.7539x; 1.0121x over previous
#include <cuda_runtime.h>
#include <cuda_bf16.h>
#include <cuda_fp16.h>
#include <cstdint>

#define N_LAYER  4
#define D_MODEL  1024
#define D_STATE  128
#define D_CONV   4
#define HEADDIM  64
#define NHEADS   32
#define D_INNER  2048
#define CONV_DIM 2304         // D_INNER + 2*D_STATE
#define D_IN_PROJ 4384        // 2*D_INNER + 2*D_STATE + NHEADS
#define LSEQ     1024
#define VOCAB    50288
#define EPS      1e-5f

// ---------------- scratch (static device globals; no allocation) -------------
__device__ float g_x  [LSEQ * D_MODEL];
__device__ float g_zx [LSEQ * D_IN_PROJ];
__device__ float g_xbc[LSEQ * CONV_DIM];
__device__ float g_dt [LSEQ * NHEADS];
__device__ float g_y  [LSEQ * D_INNER];

// fp16 storage (raw 16-bit)
__device__ unsigned short g_emb_h [VOCAB * D_MODEL];                // fp16
__device__ unsigned short g_inw_h [N_LAYER * D_IN_PROJ * D_MODEL];  // fp16
__device__ unsigned short g_outw_h[N_LAYER * D_MODEL * D_INNER];    // fp16
__device__ unsigned short g_u_hi  [LSEQ * D_MODEL];                 // fp16 hi
__device__ unsigned short g_u_lo  [LSEQ * D_MODEL];                 // fp16 lo
__device__ unsigned short g_t2_hi [LSEQ * D_INNER];
__device__ unsigned short g_t2_lo [LSEQ * D_INNER];

// ---------------- fp32 -> fp16 (single) ---------------------------------------
__global__ void cvt_half_kernel(const float4* __restrict__ in,
                                __half2* __restrict__ out, int n4) {
    int i = blockIdx.x * blockDim.x + threadIdx.x;
    if (i >= n4) return;
    float4 v = in[i];
    out[2 * i]     = __floats2half2_rn(v.x, v.y);
    out[2 * i + 1] = __floats2half2_rn(v.z, v.w);
}

// ---------------- embedding gather ------------------------------------------
__global__ void embed_kernel(const int* __restrict__ ids,
                             const float* __restrict__ emb,
                             float* __restrict__ x) {
    int idx = blockIdx.x * blockDim.x + threadIdx.x;
    if (idx >= LSEQ * D_MODEL) return;
    int t = idx >> 10;
    int d = idx & 1023;
    x[idx] = emb[(size_t)ids[t] * D_MODEL + d];
}

// ---------------- rmsnorm (optionally gated); outputs fp16 hi/lo -------------
__global__ void rmsnorm_kernel(const float* __restrict__ x, int xs,
                               const float* __restrict__ w,
                               const float* z, int zs,
                               unsigned short* __restrict__ out_hi,
                               unsigned short* __restrict__ out_lo, int D) {
    __shared__ float buf[2048];
    __shared__ float red[8];
    __shared__ float s_scale;
    int t = blockIdx.x;
    int tid = threadIdx.x;

    float ss = 0.f;
    for (int c = tid; c < D; c += blockDim.x) {
        float v = x[(size_t)t * xs + c];
        if (z) {
            float zz = z[(size_t)t * zs + c];
            v *= zz / (1.f + expf(-zz));
        }
        buf[c] = v;
        ss += v * v;
    }
    #pragma unroll
    for (int o = 16; o; o >>= 1) ss += __shfl_xor_sync(0xffffffffu, ss, o);
    if ((tid & 31) == 0) red[tid >> 5] = ss;
    __syncthreads();
    if (tid < 32) {
        float v = (tid < 8) ? red[tid] : 0.f;
        #pragma unroll
        for (int o = 4; o; o >>= 1) v += __shfl_xor_sync(0xffffffffu, v, o);
        if (tid == 0) s_scale = rsqrtf(v / (float)D + EPS);
    }
    __syncthreads();
    float sc = s_scale;
    for (int c = tid; c < D; c += blockDim.x) {
        float v = buf[c] * sc * w[c];
        __half h = __float2half_rn(v);
        __half l = __float2half_rn(v - __half2float(h));
        out_hi[(size_t)t * D + c] = *(unsigned short*)&h;
        out_lo[(size_t)t * D + c] = *(unsigned short*)&l;
    }
}

// ---- fused depthwise conv+silu (c < CONV_DIM) and dt softplus (else) --------
__global__ void convdt_kernel(const float* __restrict__ zx,
                              const float* __restrict__ w,
                              const float* __restrict__ b,
                              const float* __restrict__ dt_bias,
                              float* __restrict__ xbc,
                              float* __restrict__ dt) {
    int idx = blockIdx.x * blockDim.x + threadIdx.x;
    if (idx >= LSEQ * (CONV_DIM + NHEADS)) return;
    int t = idx / (CONV_DIM + NHEADS);
    int c = idx - t * (CONV_DIM + NHEADS);
    if (c < CONV_DIM) {
        float acc = b[c];
        const float* wc = w + c * 4;
        #pragma unroll
        for (int j = 0; j < 4; ++j) {
            int tt = t - 3 + j;
            if (tt >= 0) acc += zx[(size_t)tt * D_IN_PROJ + D_INNER + c] * wc[j];
        }
        xbc[(size_t)t * CONV_DIM + c] = acc / (1.f + expf(-acc));
    } else {
        int h = c - CONV_DIM;
        float v = zx[(size_t)t * D_IN_PROJ + (D_INNER + CONV_DIM) + h] + dt_bias[h];
        dt[t * NHEADS + h] = (v > 20.f) ? v : log1pf(expf(v));
    }
}

// ---- SSD scan: warp per (h, p-pair); smem-batched reduction (no SHFL) -------
// Scan phase: each lane keeps 4 states per channel, stores 4-wide partial dot
// to smem each step. Every 16 steps, lanes switch roles: lane=(ch,tt) sums 32
// partials (conflict-free, stride 33) and writes y. No per-step shuffle chain.
#define TB 16
__global__ void ssd_kernel(const float* __restrict__ xbc,
                           const float* __restrict__ dt,
                           const float* __restrict__ A_log,
                           const float* __restrict__ D_p,
                           float* __restrict__ y) {
    int wib  = threadIdx.x >> 5;                       // warp in block (0..3)
    int gw   = blockIdx.x * 4 + wib;                   // 0..1023
    int lane = threadIdx.x & 31;
    int h  = gw >> 5;            // head (32 warps per head)
    int p0 = (gw & 31) * 2;      // channel pair base

    __shared__ float sP[4][2 * TB * 33];               // per-warp partials
    float* P = sP[wib];

    float Ah = -expf(A_log[h]);
    float Dh = D_p[h];
    float dsel = (lane == 0) ? Dh : 0.f;   // fold x*D into lane-0 partial

    float a0 = 0.f, a1 = 0.f, a2 = 0.f, a3 = 0.f;      // states ch0
    float b0 = 0.f, b1 = 0.f, b2 = 0.f, b3 = 0.f;      // states ch1

    float4 rB[4], rC[4];
    float2 rX[4];
    float  rDT[4];
    #pragma unroll
    for (int s = 0; s < 4; ++s) {
        const float* row = xbc + (size_t)s * CONV_DIM;
        rB[s] = __ldg((const float4*)(row + D_INNER) + lane);
        rC[s] = __ldg((const float4*)(row + D_INNER + D_STATE) + lane);
        rX[s] = __ldg((const float2*)(row + h * HEADDIM) + (p0 >> 1));
        rDT[s] = __ldg(dt + s * NHEADS + h);
    }

    int rch = lane >> 4;          // reduction role: channel
    int rtt = lane & 15;          // reduction role: timestep within block
    float* rrow = P + (rch * TB + rtt) * 33;

    for (int t0 = 0; t0 < LSEQ; t0 += TB) {
        #pragma unroll
        for (int tt = 0; tt < TB; ++tt) {
            int t = t0 + tt;
            int s = t & 3;
            float dtv = rDT[s];
            float e   = __expf(Ah * dtv);
            float x0  = rX[s].x, x1 = rX[s].y;
            float xd0 = x0 * dtv, xd1 = x1 * dtv;
            float4 Bv = rB[s], Cv = rC[s];

            a0 = e * a0 + Bv.x * xd0;
            a1 = e * a1 + Bv.y * xd0;
            a2 = e * a2 + Bv.z * xd0;
            a3 = e * a3 + Bv.w * xd0;
            b0 = e * b0 + Bv.x * xd1;
            b1 = e * b1 + Bv.y * xd1;
            b2 = e * b2 + Bv.z * xd1;
            b3 = e * b3 + Bv.w * xd1;

            float part0 = Cv.x * a0 + Cv.y * a1 + Cv.z * a2 + Cv.w * a3 + x0 * dsel;
            float part1 = Cv.x * b0 + Cv.y * b1 + Cv.z * b2 + Cv.w * b3 + x1 * dsel;
            P[(0 * TB + tt) * 33 + lane] = part0;
            P[(1 * TB + tt) * 33 + lane] = part1;

            // prefetch row t+4 into the slot just consumed
            int tn = t + 4;
            if (tn > LSEQ - 1) tn = LSEQ - 1;
            const float* row = xbc + (size_t)tn * CONV_DIM;
            rB[s] = __ldg((const float4*)(row + D_INNER) + lane);
            rC[s] = __ldg((const float4*)(row + D_INNER + D_STATE) + lane);
            rX[s] = __ldg((const float2*)(row + h * HEADDIM) + (p0 >> 1));
            rDT[s] = __ldg(dt + tn * NHEADS + h);
        }
        __syncwarp();
        // reduction: lane (rch, rtt) sums 32 partials (pipelined LDS+FADD)
        {
            float s0 = 0.f, s1 = 0.f;
            #pragma unroll
            for (int j = 0; j < 32; j += 2) {
                s0 += rrow[j];
                s1 += rrow[j + 1];
            }
            y[(size_t)(t0 + rtt) * D_INNER + h * HEADDIM + p0 + rch] = s0 + s1;
        }
        __syncwarp();
    }
}

// =============================================================================
// fp16 split-precision tensor-core GEMM (NT): C[m,n] = sum_k A[m,k]*B[n,k]
// NPASS: 2 = Ahi*B + Alo*B (A exact to 22 bits); 1 = Ahi*B.
// BNT: 128 / 64 / 32 (warp n-strip = BNT/2). BM=128, 256 threads.
// BK: 32 or 64; LDSB = BK+8. Static smem, single buffer.
// =============================================================================
#define BM 128

#define LDSM4(R, addr) asm volatile( \
    "ldmatrix.sync.aligned.m8n8.x4.shared.b16 {%0,%1,%2,%3}, [%4];" \
    : "=r"((R)[0]),"=r"((R)[1]),"=r"((R)[2]),"=r"((R)[3]) : "r"(addr))
#define LDSM2(R, addr) asm volatile( \
    "ldmatrix.sync.aligned.m8n8.x2.shared.b16 {%0,%1}, [%2];" \
    : "=r"((R)[0]),"=r"((R)[1]) : "r"(addr))

__device__ __forceinline__ uint32_t smem_u32(const void* p) {
    return (uint32_t)__cvta_generic_to_shared(p);
}

__device__ __forceinline__ void mma_f16(float* acc, const uint32_t* a,
                                        const uint32_t* b) {
    asm volatile(
        "mma.sync.aligned.m16n8k16.row.col.f32.f16.f16.f32 "
        "{%0,%1,%2,%3},{%4,%5,%6,%7},{%8,%9},{%0,%1,%2,%3};"
        : "+f"(acc[0]), "+f"(acc[1]), "+f"(acc[2]), "+f"(acc[3])
        : "r"(a[0]), "r"(a[1]), "r"(a[2]), "r"(a[3]), "r"(b[0]), "r"(b[1]));
}

template<int BNT, int NPASS, int BK>
__global__ __launch_bounds__(256) void gemm_mma(
    const unsigned short* __restrict__ Ahi, const unsigned short* __restrict__ Alo,
    const unsigned short* __restrict__ Bh,
    const float* add, float* __restrict__ C, int M, int N, int K) {
    constexpr int NI   = BNT / 16;
    constexpr int LDSB = BK + 8;
    constexpr int CHB  = (BNT * BK) / 2048;   // uint4 chunks per thread for B
    __shared__ unsigned short sAhi[BM * LDSB];
    __shared__ unsigned short sAlo[(NPASS >= 2 ? BM : 8) * LDSB];
    __shared__ unsigned short sBh [BNT * LDSB];

    int tid  = threadIdx.x;
    int wid  = tid >> 5, lane = tid & 31;
    int wm   = wid & 3;
    int wn   = wid >> 2;
    int bm   = blockIdx.x * BM;
    int bn   = blockIdx.y * BNT;

    float acc[2][NI][4];
    #pragma unroll
    for (int i = 0; i < 2; ++i)
        #pragma unroll
        for (int j = 0; j < NI; ++j)
            #pragma unroll
            for (int q = 0; q < 4; ++q) acc[i][j][q] = 0.f;

    // A: 2 threads/row, BK/2 elems each
    int lrA = tid >> 1;
    int lkA = (tid & 1) * (BK / 2);
    // B: 256/BNT threads per row, CHB*8 elems each
    constexpr int TPR = 256 / BNT;
    int lrB = tid / TPR;
    int lkB = (tid % TPR) * (CHB * 8);
    int brow  = bn + lrB;
    int browc = (brow < N) ? brow : 0;

    int mrow      = wm * 32 + (lane & 15);
    int acol_half = ((lane >> 4) << 3);
    int nrow_base = wn * (BNT / 2) + (lane & 7);
    int bcol_half = ((lane >> 3) & 1) << 3;

    for (int k0 = 0; k0 < K; k0 += BK) {
        {
            const unsigned short* pa0 = Ahi + (size_t)(bm + lrA) * K + k0 + lkA;
            #pragma unroll
            for (int c = 0; c < BK / 16; ++c)
                *(uint4*)&sAhi[lrA * LDSB + lkA + c * 8] = *(const uint4*)(pa0 + c * 8);
            if (NPASS >= 2) {
                const unsigned short* pa1 = Alo + (size_t)(bm + lrA) * K + k0 + lkA;
                #pragma unroll
                for (int c = 0; c < BK / 16; ++c)
                    *(uint4*)&sAlo[lrA * LDSB + lkA + c * 8] = *(const uint4*)(pa1 + c * 8);
            }
            const unsigned short* pb0 = Bh + (size_t)browc * K + k0 + lkB;
            #pragma unroll
            for (int c = 0; c < CHB; ++c)
                *(uint4*)&sBh[lrB * LDSB + lkB + c * 8] = *(const uint4*)(pb0 + c * 8);
        }
        __syncthreads();

        #pragma unroll
        for (int ks = 0; ks < BK / 16; ++ks) {
            int kb = ks * 16;
            uint32_t ahi[2][4], alo[2][4];
            #pragma unroll
            for (int mi = 0; mi < 2; ++mi) {
                int off = (mrow + mi * 16) * LDSB + kb + acol_half;
                LDSM4(ahi[mi], smem_u32(&sAhi[off]));
                if (NPASS >= 2) LDSM4(alo[mi], smem_u32(&sAlo[off]));
            }
            uint32_t bh[NI][2];
            #pragma unroll
            for (int ni = 0; ni < NI; ++ni) {
                int off = (nrow_base + ni * 8) * LDSB + kb + bcol_half;
                LDSM2(bh[ni], smem_u32(&sBh[off]));
            }
            #pragma unroll
            for (int mi = 0; mi < 2; ++mi)
                #pragma unroll
                for (int ni = 0; ni < NI; ++ni) {
                    mma_f16(acc[mi][ni], ahi[mi], bh[ni]);
                    if (NPASS >= 2) mma_f16(acc[mi][ni], alo[mi], bh[ni]);
                }
        }
        __syncthreads();
    }

    // --- epilogue ---
    int g = lane >> 2, t4 = lane & 3;
    #pragma unroll
    for (int mi = 0; mi < 2; ++mi) {
        int r0 = bm + wm * 32 + mi * 16 + g;
        #pragma unroll
        for (int ni = 0; ni < NI; ++ni) {
            int col = bn + wn * (BNT / 2) + ni * 8 + t4 * 2;
            if (col < N) {     // N even, col even -> covers col+1 too
                float2 v0 = make_float2(acc[mi][ni][0], acc[mi][ni][1]);
                float2 v1 = make_float2(acc[mi][ni][2], acc[mi][ni][3]);
                if (add) {
                    float2 a0 = *(const float2*)(add + (size_t)r0 * N + col);
                    float2 a1 = *(const float2*)(add + (size_t)(r0 + 8) * N + col);
                    v0.x += a0.x; v0.y += a0.y;
                    v1.x += a1.x; v1.y += a1.y;
                }
                *(float2*)(C + (size_t)r0 * N + col)       = v0;
                *(float2*)(C + (size_t)(r0 + 8) * N + col) = v1;
            }
        }
    }
}

// ---------------- orchestration ----------------------------------------------
extern "C" void kernel_launch(void* const* d_in, const int* in_sizes, int n_in,
                              void* d_out, int out_size) {
    const int*   ids       = (const int*)  d_in[0];
    const float* emb       = (const float*)d_in[1];
    const float* norm_ws   = (const float*)d_in[2];
    const float* in_ws     = (const float*)d_in[3];
    const float* conv_ws   = (const float*)d_in[4];
    const float* conv_bs   = (const float*)d_in[5];
    const float* dt_biases = (const float*)d_in[6];
    const float* A_logs    = (const float*)d_in[7];
    const float* Ds        = (const float*)d_in[8];
    const float* gnorm_ws  = (const float*)d_in[9];
    const float* out_ws    = (const float*)d_in[10];
    const float* norm_f_w  = (const float*)d_in[11];
    float* out = (float*)d_out;

    float *x, *zx, *xbc, *dtb, *y;
    cudaGetSymbolAddress((void**)&x,   g_x);
    cudaGetSymbolAddress((void**)&zx,  g_zx);
    cudaGetSymbolAddress((void**)&xbc, g_xbc);
    cudaGetSymbolAddress((void**)&dtb, g_dt);
    cudaGetSymbolAddress((void**)&y,   g_y);

    unsigned short *emb_h, *inw_h, *outw_h, *u_hi, *u_lo, *t2_hi, *t2_lo;
    cudaGetSymbolAddress((void**)&emb_h,  g_emb_h);
    cudaGetSymbolAddress((void**)&inw_h,  g_inw_h);
    cudaGetSymbolAddress((void**)&outw_h, g_outw_h);
    cudaGetSymbolAddress((void**)&u_hi,   g_u_hi);
    cudaGetSymbolAddress((void**)&u_lo,   g_u_lo);
    cudaGetSymbolAddress((void**)&t2_hi,  g_t2_hi);
    cudaGetSymbolAddress((void**)&t2_lo,  g_t2_lo);

    // (0) embed
    embed_kernel<<<(LSEQ * D_MODEL + 255) / 256, 256>>>(ids, emb, x);
    // (1) pre-norm layer 0
    rmsnorm_kernel<<<LSEQ, 256>>>(x, D_MODEL, norm_ws, nullptr, 0,
                                  u_hi, u_lo, D_MODEL);
    // (2) cvt in_ws -> fp16
    {
        int n4 = N_LAYER * D_IN_PROJ * D_MODEL / 4;
        cvt_half_kernel<<<(n4 + 255) / 256, 256>>>(
            (const float4*)in_ws, (__half2*)inw_h, n4);
    }
    // (3) in_proj layer 0
    gemm_mma<128, 2, 32><<<dim3(LSEQ / BM, (D_IN_PROJ + 127) / 128), 256>>>(
        u_hi, u_lo, inw_h, nullptr, zx, LSEQ, D_IN_PROJ, D_MODEL);
    // (4) conv+dt layer 0
    convdt_kernel<<<(LSEQ * (CONV_DIM + NHEADS) + 255) / 256, 256>>>(
        zx, conv_ws, conv_bs, dt_biases, xbc, dtb);
    // (5) SSD layer 0  <-- profiled slot
    ssd_kernel<<<256, 128>>>(xbc, dtb, A_logs, Ds, y);
    // (6) cvt out_ws -> fp16
    {
        int n4 = N_LAYER * D_MODEL * D_INNER / 4;
        cvt_half_kernel<<<(n4 + 255) / 256, 256>>>(
            (const float4*)out_ws, (__half2*)outw_h, n4);
    }
    // (7) cvt emb -> fp16
    {
        int n4 = VOCAB * D_MODEL / 4;
        cvt_half_kernel<<<(n4 + 255) / 256, 256>>>(
            (const float4*)emb, (__half2*)emb_h, n4);
    }

    for (int i = 0; i < N_LAYER; ++i) {
        if (i > 0) {
            rmsnorm_kernel<<<LSEQ, 256>>>(
                x, D_MODEL, norm_ws + (size_t)i * D_MODEL, nullptr, 0,
                u_hi, u_lo, D_MODEL);
            gemm_mma<128, 2, 32><<<dim3(LSEQ / BM, (D_IN_PROJ + 127) / 128), 256>>>(
                u_hi, u_lo, inw_h + (size_t)i * D_IN_PROJ * D_MODEL,
                nullptr, zx, LSEQ, D_IN_PROJ, D_MODEL);
            convdt_kernel<<<(LSEQ * (CONV_DIM + NHEADS) + 255) / 256, 256>>>(
                zx, conv_ws + (size_t)i * CONV_DIM * D_CONV,
                conv_bs + (size_t)i * CONV_DIM,
                dt_biases + (size_t)i * NHEADS, xbc, dtb);
            ssd_kernel<<<256, 128>>>(
                xbc, dtb, A_logs + (size_t)i * NHEADS, Ds + (size_t)i * NHEADS, y);
        }
        rmsnorm_kernel<<<LSEQ, 256>>>(
            y, D_INNER, gnorm_ws + (size_t)i * D_INNER,
            zx, D_IN_PROJ, t2_hi, t2_lo, D_INNER);
        // out_proj + residual: fp16 2-pass, BNT=32 (256-block grid), BK=64
        gemm_mma<32, 2, 64><<<dim3(LSEQ / BM, D_MODEL / 32), 256>>>(
            t2_hi, t2_lo, outw_h + (size_t)i * D_MODEL * D_INNER,
            x, x, LSEQ, D_MODEL, D_INNER);
    }

    // final norm + fp16 1-pass logits
    rmsnorm_kernel<<<LSEQ, 256>>>(x, D_MODEL, norm_f_w, nullptr, 0,
                                  u_hi, u_lo, D_MODEL);
    gemm_mma<128, 1, 64><<<dim3(LSEQ / BM, (VOCAB + 127) / 128), 256>>>(
        u_hi, u_hi, emb_h, nullptr, out, LSEQ, VOCAB, D_MODEL);
}

// round 12
// speedup vs baseline: 1.8513x; 1.0555x over previous
#include <cuda_runtime.h>
#include <cuda_bf16.h>
#include <cuda_fp16.h>
#include <cstdint>

#define N_LAYER  4
#define D_MODEL  1024
#define D_STATE  128
#define D_CONV   4
#define HEADDIM  64
#define NHEADS   32
#define D_INNER  2048
#define CONV_DIM 2304         // D_INNER + 2*D_STATE
#define D_IN_PROJ 4384        // 2*D_INNER + 2*D_STATE + NHEADS
#define LSEQ     1024
#define VOCAB    50288
#define EPS      1e-5f

// ---------------- scratch (static device globals; no allocation) -------------
__device__ float g_x  [LSEQ * D_MODEL];
__device__ float g_zx [LSEQ * D_IN_PROJ];
__device__ float g_xbc[LSEQ * CONV_DIM];
__device__ float g_dt [LSEQ * NHEADS];
__device__ float g_y  [LSEQ * D_INNER];
__device__ float g_part[4 * LSEQ * D_MODEL];   // split-K partials (16 MB)

// fp16 storage (raw 16-bit)
__device__ unsigned short g_emb_h [VOCAB * D_MODEL];                // fp16
__device__ unsigned short g_inw_h [N_LAYER * D_IN_PROJ * D_MODEL];  // fp16
__device__ unsigned short g_outw_h[N_LAYER * D_MODEL * D_INNER];    // fp16
__device__ unsigned short g_u_hi  [LSEQ * D_MODEL];                 // fp16 hi
__device__ unsigned short g_u_lo  [LSEQ * D_MODEL];                 // fp16 lo
__device__ unsigned short g_t2_hi [LSEQ * D_INNER];
__device__ unsigned short g_t2_lo [LSEQ * D_INNER];

// ---------------- fp32 -> fp16 (single) ---------------------------------------
__global__ void cvt_half_kernel(const float4* __restrict__ in,
                                __half2* __restrict__ out, int n4) {
    int i = blockIdx.x * blockDim.x + threadIdx.x;
    if (i >= n4) return;
    float4 v = in[i];
    out[2 * i]     = __floats2half2_rn(v.x, v.y);
    out[2 * i + 1] = __floats2half2_rn(v.z, v.w);
}

// ---------------- embedding gather ------------------------------------------
__global__ void embed_kernel(const int* __restrict__ ids,
                             const float* __restrict__ emb,
                             float* __restrict__ x) {
    int idx = blockIdx.x * blockDim.x + threadIdx.x;
    if (idx >= LSEQ * D_MODEL) return;
    int t = idx >> 10;
    int d = idx & 1023;
    x[idx] = emb[(size_t)ids[t] * D_MODEL + d];
}

// ---------------- rmsnorm (optionally gated); outputs fp16 hi/lo -------------
__global__ void rmsnorm_kernel(const float* __restrict__ x, int xs,
                               const float* __restrict__ w,
                               const float* z, int zs,
                               unsigned short* __restrict__ out_hi,
                               unsigned short* __restrict__ out_lo, int D) {
    __shared__ float buf[2048];
    __shared__ float red[8];
    __shared__ float s_scale;
    int t = blockIdx.x;
    int tid = threadIdx.x;

    float ss = 0.f;
    for (int c = tid; c < D; c += blockDim.x) {
        float v = x[(size_t)t * xs + c];
        if (z) {
            float zz = z[(size_t)t * zs + c];
            v *= zz / (1.f + expf(-zz));
        }
        buf[c] = v;
        ss += v * v;
    }
    #pragma unroll
    for (int o = 16; o; o >>= 1) ss += __shfl_xor_sync(0xffffffffu, ss, o);
    if ((tid & 31) == 0) red[tid >> 5] = ss;
    __syncthreads();
    if (tid < 32) {
        float v = (tid < 8) ? red[tid] : 0.f;
        #pragma unroll
        for (int o = 4; o; o >>= 1) v += __shfl_xor_sync(0xffffffffu, v, o);
        if (tid == 0) s_scale = rsqrtf(v / (float)D + EPS);
    }
    __syncthreads();
    float sc = s_scale;
    for (int c = tid; c < D; c += blockDim.x) {
        float v = buf[c] * sc * w[c];
        __half h = __float2half_rn(v);
        __half l = __float2half_rn(v - __half2float(h));
        out_hi[(size_t)t * D + c] = *(unsigned short*)&h;
        out_lo[(size_t)t * D + c] = *(unsigned short*)&l;
    }
}

// ---- fused depthwise conv+silu (c < CONV_DIM) and dt softplus (else) --------
__global__ void convdt_kernel(const float* __restrict__ zx,
                              const float* __restrict__ w,
                              const float* __restrict__ b,
                              const float* __restrict__ dt_bias,
                              float* __restrict__ xbc,
                              float* __restrict__ dt) {
    int idx = blockIdx.x * blockDim.x + threadIdx.x;
    if (idx >= LSEQ * (CONV_DIM + NHEADS)) return;
    int t = idx / (CONV_DIM + NHEADS);
    int c = idx - t * (CONV_DIM + NHEADS);
    if (c < CONV_DIM) {
        float acc = b[c];
        const float* wc = w + c * 4;
        #pragma unroll
        for (int j = 0; j < 4; ++j) {
            int tt = t - 3 + j;
            if (tt >= 0) acc += zx[(size_t)tt * D_IN_PROJ + D_INNER + c] * wc[j];
        }
        xbc[(size_t)t * CONV_DIM + c] = acc / (1.f + expf(-acc));
    } else {
        int h = c - CONV_DIM;
        float v = zx[(size_t)t * D_IN_PROJ + (D_INNER + CONV_DIM) + h] + dt_bias[h];
        dt[t * NHEADS + h] = (v > 20.f) ? v : log1pf(expf(v));
    }
}

// ---- split-K reduction: x += p0 + p1 + p2 + p3 ------------------------------
__global__ void reduce4_kernel(const float4* __restrict__ p,
                               float4* __restrict__ x, int mn4) {
    int i = blockIdx.x * blockDim.x + threadIdx.x;
    if (i >= mn4) return;
    float4 a = p[i];
    float4 b = p[i + mn4];
    float4 c = p[i + 2 * mn4];
    float4 d = p[i + 3 * mn4];
    float4 v = x[i];
    v.x += (a.x + b.x) + (c.x + d.x);
    v.y += (a.y + b.y) + (c.y + d.y);
    v.z += (a.z + b.z) + (c.z + d.z);
    v.w += (a.w + b.w) + (c.w + d.w);
    x[i] = v;
}

// ---- SSD scan: warp per (h, p-pair); smem-batched reduction (no SHFL) -------
#define TB 16
__global__ void ssd_kernel(const float* __restrict__ xbc,
                           const float* __restrict__ dt,
                           const float* __restrict__ A_log,
                           const float* __restrict__ D_p,
                           float* __restrict__ y) {
    int wib  = threadIdx.x >> 5;
    int gw   = blockIdx.x * 4 + wib;
    int lane = threadIdx.x & 31;
    int h  = gw >> 5;
    int p0 = (gw & 31) * 2;

    __shared__ float sP[4][2 * TB * 33];
    float* P = sP[wib];

    float Ah = -expf(A_log[h]);
    float Dh = D_p[h];
    float dsel = (lane == 0) ? Dh : 0.f;

    float a0 = 0.f, a1 = 0.f, a2 = 0.f, a3 = 0.f;
    float b0 = 0.f, b1 = 0.f, b2 = 0.f, b3 = 0.f;

    float4 rB[4], rC[4];
    float2 rX[4];
    float  rDT[4];
    #pragma unroll
    for (int s = 0; s < 4; ++s) {
        const float* row = xbc + (size_t)s * CONV_DIM;
        rB[s] = __ldg((const float4*)(row + D_INNER) + lane);
        rC[s] = __ldg((const float4*)(row + D_INNER + D_STATE) + lane);
        rX[s] = __ldg((const float2*)(row + h * HEADDIM) + (p0 >> 1));
        rDT[s] = __ldg(dt + s * NHEADS + h);
    }

    int rch = lane >> 4;
    int rtt = lane & 15;
    float* rrow = P + (rch * TB + rtt) * 33;

    for (int t0 = 0; t0 < LSEQ; t0 += TB) {
        #pragma unroll
        for (int tt = 0; tt < TB; ++tt) {
            int t = t0 + tt;
            int s = t & 3;
            float dtv = rDT[s];
            float e   = __expf(Ah * dtv);
            float x0  = rX[s].x, x1 = rX[s].y;
            float xd0 = x0 * dtv, xd1 = x1 * dtv;
            float4 Bv = rB[s], Cv = rC[s];

            a0 = e * a0 + Bv.x * xd0;
            a1 = e * a1 + Bv.y * xd0;
            a2 = e * a2 + Bv.z * xd0;
            a3 = e * a3 + Bv.w * xd0;
            b0 = e * b0 + Bv.x * xd1;
            b1 = e * b1 + Bv.y * xd1;
            b2 = e * b2 + Bv.z * xd1;
            b3 = e * b3 + Bv.w * xd1;

            float part0 = Cv.x * a0 + Cv.y * a1 + Cv.z * a2 + Cv.w * a3 + x0 * dsel;
            float part1 = Cv.x * b0 + Cv.y * b1 + Cv.z * b2 + Cv.w * b3 + x1 * dsel;
            P[(0 * TB + tt) * 33 + lane] = part0;
            P[(1 * TB + tt) * 33 + lane] = part1;

            int tn = t + 4;
            if (tn > LSEQ - 1) tn = LSEQ - 1;
            const float* row = xbc + (size_t)tn * CONV_DIM;
            rB[s] = __ldg((const float4*)(row + D_INNER) + lane);
            rC[s] = __ldg((const float4*)(row + D_INNER + D_STATE) + lane);
            rX[s] = __ldg((const float2*)(row + h * HEADDIM) + (p0 >> 1));
            rDT[s] = __ldg(dt + tn * NHEADS + h);
        }
        __syncwarp();
        {
            float s0 = 0.f, s1 = 0.f;
            #pragma unroll
            for (int j = 0; j < 32; j += 2) {
                s0 += rrow[j];
                s1 += rrow[j + 1];
            }
            y[(size_t)(t0 + rtt) * D_INNER + h * HEADDIM + p0 + rch] = s0 + s1;
        }
        __syncwarp();
    }
}

// =============================================================================
// fp16 split-precision tensor-core GEMM (NT): C[m,n] = sum_k A[m,k]*B[n,k]
// NPASS: 2 = Ahi*B + Alo*B; 1 = Ahi*B.  BNT: 128/64/32. BM=128, 256 threads.
// lda = row stride of A/B (elems); K = extent per z-slice; kof = column offset
// per blockIdx.z (split-K; C advances by M*N per z).
// =============================================================================
#define BM 128

#define LDSM4(R, addr) asm volatile( \
    "ldmatrix.sync.aligned.m8n8.x4.shared.b16 {%0,%1,%2,%3}, [%4];" \
    : "=r"((R)[0]),"=r"((R)[1]),"=r"((R)[2]),"=r"((R)[3]) : "r"(addr))
#define LDSM2(R, addr) asm volatile( \
    "ldmatrix.sync.aligned.m8n8.x2.shared.b16 {%0,%1}, [%2];" \
    : "=r"((R)[0]),"=r"((R)[1]) : "r"(addr))

__device__ __forceinline__ uint32_t smem_u32(const void* p) {
    return (uint32_t)__cvta_generic_to_shared(p);
}

__device__ __forceinline__ void mma_f16(float* acc, const uint32_t* a,
                                        const uint32_t* b) {
    asm volatile(
        "mma.sync.aligned.m16n8k16.row.col.f32.f16.f16.f32 "
        "{%0,%1,%2,%3},{%4,%5,%6,%7},{%8,%9},{%0,%1,%2,%3};"
        : "+f"(acc[0]), "+f"(acc[1]), "+f"(acc[2]), "+f"(acc[3])
        : "r"(a[0]), "r"(a[1]), "r"(a[2]), "r"(a[3]), "r"(b[0]), "r"(b[1]));
}

template<int BNT, int NPASS, int BK>
__global__ __launch_bounds__(256) void gemm_mma(
    const unsigned short* __restrict__ Ahi, const unsigned short* __restrict__ Alo,
    const unsigned short* __restrict__ Bh,
    const float* add, float* __restrict__ C,
    int M, int N, int K, int lda, int kof) {
    constexpr int NI   = BNT / 16;
    constexpr int LDSB = BK + 8;
    constexpr int CHB  = (BNT * BK) / 2048;
    __shared__ unsigned short sAhi[BM * LDSB];
    __shared__ unsigned short sAlo[(NPASS >= 2 ? BM : 8) * LDSB];
    __shared__ unsigned short sBh [BNT * LDSB];

    // split-K: advance operand columns / output slab by blockIdx.z
    int z = blockIdx.z;
    Ahi += (size_t)z * kof;
    Alo += (size_t)z * kof;
    Bh  += (size_t)z * kof;
    C   += (size_t)z * M * (size_t)N;

    int tid  = threadIdx.x;
    int wid  = tid >> 5, lane = tid & 31;
    int wm   = wid & 3;
    int wn   = wid >> 2;
    int bm   = blockIdx.x * BM;
    int bn   = blockIdx.y * BNT;

    float acc[2][NI][4];
    #pragma unroll
    for (int i = 0; i < 2; ++i)
        #pragma unroll
        for (int j = 0; j < NI; ++j)
            #pragma unroll
            for (int q = 0; q < 4; ++q) acc[i][j][q] = 0.f;

    int lrA = tid >> 1;
    int lkA = (tid & 1) * (BK / 2);
    constexpr int TPR = 256 / BNT;
    int lrB = tid / TPR;
    int lkB = (tid % TPR) * (CHB * 8);
    int brow  = bn + lrB;
    int browc = (brow < N) ? brow : 0;

    int mrow      = wm * 32 + (lane & 15);
    int acol_half = ((lane >> 4) << 3);
    int nrow_base = wn * (BNT / 2) + (lane & 7);
    int bcol_half = ((lane >> 3) & 1) << 3;

    for (int k0 = 0; k0 < K; k0 += BK) {
        {
            const unsigned short* pa0 = Ahi + (size_t)(bm + lrA) * lda + k0 + lkA;
            #pragma unroll
            for (int c = 0; c < BK / 16; ++c)
                *(uint4*)&sAhi[lrA * LDSB + lkA + c * 8] = *(const uint4*)(pa0 + c * 8);
            if (NPASS >= 2) {
                const unsigned short* pa1 = Alo + (size_t)(bm + lrA) * lda + k0 + lkA;
                #pragma unroll
                for (int c = 0; c < BK / 16; ++c)
                    *(uint4*)&sAlo[lrA * LDSB + lkA + c * 8] = *(const uint4*)(pa1 + c * 8);
            }
            const unsigned short* pb0 = Bh + (size_t)browc * lda + k0 + lkB;
            #pragma unroll
            for (int c = 0; c < CHB; ++c)
                *(uint4*)&sBh[lrB * LDSB + lkB + c * 8] = *(const uint4*)(pb0 + c * 8);
        }
        __syncthreads();

        #pragma unroll
        for (int ks = 0; ks < BK / 16; ++ks) {
            int kb = ks * 16;
            uint32_t ahi[2][4], alo[2][4];
            #pragma unroll
            for (int mi = 0; mi < 2; ++mi) {
                int off = (mrow + mi * 16) * LDSB + kb + acol_half;
                LDSM4(ahi[mi], smem_u32(&sAhi[off]));
                if (NPASS >= 2) LDSM4(alo[mi], smem_u32(&sAlo[off]));
            }
            uint32_t bh[NI][2];
            #pragma unroll
            for (int ni = 0; ni < NI; ++ni) {
                int off = (nrow_base + ni * 8) * LDSB + kb + bcol_half;
                LDSM2(bh[ni], smem_u32(&sBh[off]));
            }
            #pragma unroll
            for (int mi = 0; mi < 2; ++mi)
                #pragma unroll
                for (int ni = 0; ni < NI; ++ni) {
                    mma_f16(acc[mi][ni], ahi[mi], bh[ni]);
                    if (NPASS >= 2) mma_f16(acc[mi][ni], alo[mi], bh[ni]);
                }
        }
        __syncthreads();
    }

    // --- epilogue ---
    int g = lane >> 2, t4 = lane & 3;
    #pragma unroll
    for (int mi = 0; mi < 2; ++mi) {
        int r0 = bm + wm * 32 + mi * 16 + g;
        #pragma unroll
        for (int ni = 0; ni < NI; ++ni) {
            int col = bn + wn * (BNT / 2) + ni * 8 + t4 * 2;
            if (col < N) {     // N even, col even -> covers col+1 too
                float2 v0 = make_float2(acc[mi][ni][0], acc[mi][ni][1]);
                float2 v1 = make_float2(acc[mi][ni][2], acc[mi][ni][3]);
                if (add) {
                    float2 a0 = *(const float2*)(add + (size_t)r0 * N + col);
                    float2 a1 = *(const float2*)(add + (size_t)(r0 + 8) * N + col);
                    v0.x += a0.x; v0.y += a0.y;
                    v1.x += a1.x; v1.y += a1.y;
                }
                *(float2*)(C + (size_t)r0 * N + col)       = v0;
                *(float2*)(C + (size_t)(r0 + 8) * N + col) = v1;
            }
        }
    }
}

// ---------------- orchestration ----------------------------------------------
extern "C" void kernel_launch(void* const* d_in, const int* in_sizes, int n_in,
                              void* d_out, int out_size) {
    const int*   ids       = (const int*)  d_in[0];
    const float* emb       = (const float*)d_in[1];
    const float* norm_ws   = (const float*)d_in[2];
    const float* in_ws     = (const float*)d_in[3];
    const float* conv_ws   = (const float*)d_in[4];
    const float* conv_bs   = (const float*)d_in[5];
    const float* dt_biases = (const float*)d_in[6];
    const float* A_logs    = (const float*)d_in[7];
    const float* Ds        = (const float*)d_in[8];
    const float* gnorm_ws  = (const float*)d_in[9];
    const float* out_ws    = (const float*)d_in[10];
    const float* norm_f_w  = (const float*)d_in[11];
    float* out = (float*)d_out;

    float *x, *zx, *xbc, *dtb, *y, *part;
    cudaGetSymbolAddress((void**)&x,    g_x);
    cudaGetSymbolAddress((void**)&zx,   g_zx);
    cudaGetSymbolAddress((void**)&xbc,  g_xbc);
    cudaGetSymbolAddress((void**)&dtb,  g_dt);
    cudaGetSymbolAddress((void**)&y,    g_y);
    cudaGetSymbolAddress((void**)&part, g_part);

    unsigned short *emb_h, *inw_h, *outw_h, *u_hi, *u_lo, *t2_hi, *t2_lo;
    cudaGetSymbolAddress((void**)&emb_h,  g_emb_h);
    cudaGetSymbolAddress((void**)&inw_h,  g_inw_h);
    cudaGetSymbolAddress((void**)&outw_h, g_outw_h);
    cudaGetSymbolAddress((void**)&u_hi,   g_u_hi);
    cudaGetSymbolAddress((void**)&u_lo,   g_u_lo);
    cudaGetSymbolAddress((void**)&t2_hi,  g_t2_hi);
    cudaGetSymbolAddress((void**)&t2_lo,  g_t2_lo);

    // (0) embed
    embed_kernel<<<(LSEQ * D_MODEL + 255) / 256, 256>>>(ids, emb, x);
    // (1) pre-norm layer 0
    rmsnorm_kernel<<<LSEQ, 256>>>(x, D_MODEL, norm_ws, nullptr, 0,
                                  u_hi, u_lo, D_MODEL);
    // (2) cvt in_ws -> fp16
    {
        int n4 = N_LAYER * D_IN_PROJ * D_MODEL / 4;
        cvt_half_kernel<<<(n4 + 255) / 256, 256>>>(
            (const float4*)in_ws, (__half2*)inw_h, n4);
    }
    // (3) in_proj layer 0
    gemm_mma<128, 2, 32><<<dim3(LSEQ / BM, (D_IN_PROJ + 127) / 128), 256>>>(
        u_hi, u_lo, inw_h, nullptr, zx, LSEQ, D_IN_PROJ, D_MODEL, D_MODEL, 0);
    // (4) conv+dt layer 0
    convdt_kernel<<<(LSEQ * (CONV_DIM + NHEADS) + 255) / 256, 256>>>(
        zx, conv_ws, conv_bs, dt_biases, xbc, dtb);
    // (5) SSD layer 0
    ssd_kernel<<<256, 128>>>(xbc, dtb, A_logs, Ds, y);
    // (6) cvt out_ws -> fp16
    {
        int n4 = N_LAYER * D_MODEL * D_INNER / 4;
        cvt_half_kernel<<<(n4 + 255) / 256, 256>>>(
            (const float4*)out_ws, (__half2*)outw_h, n4);
    }
    // (7) cvt emb -> fp16
    {
        int n4 = VOCAB * D_MODEL / 4;
        cvt_half_kernel<<<(n4 + 255) / 256, 256>>>(
            (const float4*)emb, (__half2*)emb_h, n4);
    }

    for (int i = 0; i < N_LAYER; ++i) {
        if (i > 0) {
            rmsnorm_kernel<<<LSEQ, 256>>>(
                x, D_MODEL, norm_ws + (size_t)i * D_MODEL, nullptr, 0,
                u_hi, u_lo, D_MODEL);
            gemm_mma<128, 2, 32><<<dim3(LSEQ / BM, (D_IN_PROJ + 127) / 128), 256>>>(
                u_hi, u_lo, inw_h + (size_t)i * D_IN_PROJ * D_MODEL,
                nullptr, zx, LSEQ, D_IN_PROJ, D_MODEL, D_MODEL, 0);
            convdt_kernel<<<(LSEQ * (CONV_DIM + NHEADS) + 255) / 256, 256>>>(
                zx, conv_ws + (size_t)i * CONV_DIM * D_CONV,
                conv_bs + (size_t)i * CONV_DIM,
                dt_biases + (size_t)i * NHEADS, xbc, dtb);
            ssd_kernel<<<256, 128>>>(
                xbc, dtb, A_logs + (size_t)i * NHEADS, Ds + (size_t)i * NHEADS, y);
        }
        rmsnorm_kernel<<<LSEQ, 256>>>(
            y, D_INNER, gnorm_ws + (size_t)i * D_INNER,
            zx, D_IN_PROJ, t2_hi, t2_lo, D_INNER);
        // out_proj: split-K (z=4 x K=512), BNT=128 high-rate tiles -> partials
        gemm_mma<128, 2, 64><<<dim3(LSEQ / BM, D_MODEL / 128, 4), 256>>>(
            t2_hi, t2_lo, outw_h + (size_t)i * D_MODEL * D_INNER,
            nullptr, part, LSEQ, D_MODEL, 512, D_INNER, 512);
        // x += sum of 4 partials (deterministic)
        reduce4_kernel<<<(LSEQ * D_MODEL / 4 + 255) / 256, 256>>>(
            (const float4*)part, (float4*)x, LSEQ * D_MODEL / 4);
    }

    // final norm + fp16 1-pass logits
    rmsnorm_kernel<<<LSEQ, 256>>>(x, D_MODEL, norm_f_w, nullptr, 0,
                                  u_hi, u_lo, D_MODEL);
    gemm_mma<128, 1, 64><<<dim3(LSEQ / BM, (VOCAB + 127) / 128), 256>>>(
        u_hi, u_hi, emb_h, nullptr, out, LSEQ, VOCAB, D_MODEL, D_MODEL, 0);
}

// round 13
// speedup vs baseline: 2.4673x; 1.3328x over previous
#include <cuda_runtime.h>
#include <cuda_bf16.h>
#include <cuda_fp16.h>
#include <cstdint>

#define N_LAYER  4
#define D_MODEL  1024
#define D_STATE  128
#define D_CONV   4
#define HEADDIM  64
#define NHEADS   32
#define D_INNER  2048
#define CONV_DIM 2304         // D_INNER + 2*D_STATE
#define D_IN_PROJ 4384        // 2*D_INNER + 2*D_STATE + NHEADS
#define LSEQ     1024
#define VOCAB    50288
#define EPS      1e-5f

// ---------------- scratch (static device globals; no allocation) -------------
__device__ float g_x  [LSEQ * D_MODEL];
__device__ float g_zx [LSEQ * D_IN_PROJ];
__device__ float g_xbc[LSEQ * CONV_DIM];
__device__ float g_dt [LSEQ * NHEADS];
__device__ float g_y  [LSEQ * D_INNER];
__device__ float g_part[4 * LSEQ * D_MODEL];   // split-K partials (16 MB)

// fp16 storage (raw 16-bit)
__device__ unsigned short g_emb_h [VOCAB * D_MODEL];
__device__ unsigned short g_inw_h [N_LAYER * D_IN_PROJ * D_MODEL];
__device__ unsigned short g_outw_h[N_LAYER * D_MODEL * D_INNER];
__device__ unsigned short g_u_hi  [LSEQ * D_MODEL];
__device__ unsigned short g_u_lo  [LSEQ * D_MODEL];
__device__ unsigned short g_t2_hi [LSEQ * D_INNER];
__device__ unsigned short g_t2_lo [LSEQ * D_INNER];

// ---------------- fp32 -> fp16 (single) ---------------------------------------
__global__ void cvt_half_kernel(const float4* __restrict__ in,
                                __half2* __restrict__ out, int n4) {
    int i = blockIdx.x * blockDim.x + threadIdx.x;
    if (i >= n4) return;
    float4 v = in[i];
    out[2 * i]     = __floats2half2_rn(v.x, v.y);
    out[2 * i + 1] = __floats2half2_rn(v.z, v.w);
}

// ---------------- embedding gather ------------------------------------------
__global__ void embed_kernel(const int* __restrict__ ids,
                             const float* __restrict__ emb,
                             float* __restrict__ x) {
    int idx = blockIdx.x * blockDim.x + threadIdx.x;
    if (idx >= LSEQ * D_MODEL) return;
    int t = idx >> 10;
    int d = idx & 1023;
    x[idx] = emb[(size_t)ids[t] * D_MODEL + d];
}

// ---------------- rmsnorm (optionally gated); outputs fp16 hi/lo -------------
__global__ void rmsnorm_kernel(const float* __restrict__ x, int xs,
                               const float* __restrict__ w,
                               const float* z, int zs,
                               unsigned short* __restrict__ out_hi,
                               unsigned short* __restrict__ out_lo, int D) {
    __shared__ float buf[2048];
    __shared__ float red[8];
    __shared__ float s_scale;
    int t = blockIdx.x;
    int tid = threadIdx.x;

    float ss = 0.f;
    for (int c = tid; c < D; c += blockDim.x) {
        float v = x[(size_t)t * xs + c];
        if (z) {
            float zz = z[(size_t)t * zs + c];
            v *= zz / (1.f + expf(-zz));
        }
        buf[c] = v;
        ss += v * v;
    }
    #pragma unroll
    for (int o = 16; o; o >>= 1) ss += __shfl_xor_sync(0xffffffffu, ss, o);
    if ((tid & 31) == 0) red[tid >> 5] = ss;
    __syncthreads();
    if (tid < 32) {
        float v = (tid < 8) ? red[tid] : 0.f;
        #pragma unroll
        for (int o = 4; o; o >>= 1) v += __shfl_xor_sync(0xffffffffu, v, o);
        if (tid == 0) s_scale = rsqrtf(v / (float)D + EPS);
    }
    __syncthreads();
    float sc = s_scale;
    for (int c = tid; c < D; c += blockDim.x) {
        float v = buf[c] * sc * w[c];
        __half h = __float2half_rn(v);
        __half l = __float2half_rn(v - __half2float(h));
        out_hi[(size_t)t * D + c] = *(unsigned short*)&h;
        out_lo[(size_t)t * D + c] = *(unsigned short*)&l;
    }
}

// ---- fused depthwise conv+silu (c < CONV_DIM) and dt softplus (else) --------
__global__ void convdt_kernel(const float* __restrict__ zx,
                              const float* __restrict__ w,
                              const float* __restrict__ b,
                              const float* __restrict__ dt_bias,
                              float* __restrict__ xbc,
                              float* __restrict__ dt) {
    int idx = blockIdx.x * blockDim.x + threadIdx.x;
    if (idx >= LSEQ * (CONV_DIM + NHEADS)) return;
    int t = idx / (CONV_DIM + NHEADS);
    int c = idx - t * (CONV_DIM + NHEADS);
    if (c < CONV_DIM) {
        float acc = b[c];
        const float* wc = w + c * 4;
        #pragma unroll
        for (int j = 0; j < 4; ++j) {
            int tt = t - 3 + j;
            if (tt >= 0) acc += zx[(size_t)tt * D_IN_PROJ + D_INNER + c] * wc[j];
        }
        xbc[(size_t)t * CONV_DIM + c] = acc / (1.f + expf(-acc));
    } else {
        int h = c - CONV_DIM;
        float v = zx[(size_t)t * D_IN_PROJ + (D_INNER + CONV_DIM) + h] + dt_bias[h];
        dt[t * NHEADS + h] = (v > 20.f) ? v : log1pf(expf(v));
    }
}

// ---- split-K reduction: x += p0 + p1 + p2 + p3 ------------------------------
__global__ void reduce4_kernel(const float4* __restrict__ p,
                               float4* __restrict__ x, int mn4) {
    int i = blockIdx.x * blockDim.x + threadIdx.x;
    if (i >= mn4) return;
    float4 a = p[i];
    float4 b = p[i + mn4];
    float4 c = p[i + 2 * mn4];
    float4 d = p[i + 3 * mn4];
    float4 v = x[i];
    v.x += (a.x + b.x) + (c.x + d.x);
    v.y += (a.y + b.y) + (c.y + d.y);
    v.z += (a.z + b.z) + (c.z + d.z);
    v.w += (a.w + b.w) + (c.w + d.w);
    x[i] = v;
}

__device__ __forceinline__ uint32_t smem_u32(const void* p) {
    return (uint32_t)__cvta_generic_to_shared(p);
}
__device__ __forceinline__ void cpa(uint32_t dst, const void* src, int bytes) {
    if (bytes == 16)
        asm volatile("cp.async.ca.shared.global [%0], [%1], 16;"
                     :: "r"(dst), "l"(src));
    else
        asm volatile("cp.async.ca.shared.global [%0], [%1], 4;"
                     :: "r"(dst), "l"(src));
}

// =============================================================================
// SSD scan, cp.async staged. Block = 4 warps = one head, 8 channels
// (pbase..pbase+7). Stage 16 timesteps of B/C/x/dt into smem (double buffer);
// compute phase reads only smem; partial-dot reduction every 16 steps (no SHFL).
// Dynamic smem: 2*16*128 (B) + 2*16*128 (C) + 2*16*8 (x) + 2*16 (dt)
//               + 4*2*16*33 (P)  floats  = 50,816 bytes.
// =============================================================================
#define TB 16
#define SSD_SMEM 50816
__global__ __launch_bounds__(128) void ssd_kernel(
    const float* __restrict__ xbc,
    const float* __restrict__ dt,
    const float* __restrict__ A_log,
    const float* __restrict__ D_p,
    float* __restrict__ y) {
    extern __shared__ float sm[];
    float* sB  = sm;                       // [2][TB][128]
    float* sC  = sB + 2 * TB * 128;        // [2][TB][128]
    float* sx  = sC + 2 * TB * 128;        // [2][TB][8]
    float* sdt = sx + 2 * TB * 8;          // [2][TB]
    float* sPa = sdt + 2 * TB;             // [4][2*TB*33]

    int tid  = threadIdx.x;
    int wib  = tid >> 5;
    int lane = tid & 31;
    int h     = blockIdx.x >> 3;           // head
    int pbase = (blockIdx.x & 7) * 8;      // first channel of this block
    int p0    = pbase + wib * 2;           // this warp's channel pair

    float* P = sPa + wib * (2 * TB * 33);

    // ---- cp.async stage of TB rows starting at t0 into buffer s ----
    #define SSD_STAGE(t0, s) do {                                              \
        const float* base = xbc + (size_t)(t0) * CONV_DIM;                     \
        uint32_t dB = smem_u32(sB + (s) * TB * 128);                           \
        uint32_t dC = smem_u32(sC + (s) * TB * 128);                           \
        _Pragma("unroll")                                                      \
        for (int c = 0; c < 4; ++c) {                                          \
            int ch  = tid + c * 128;        /* 0..511 */                       \
            int row = ch >> 5;                                                 \
            int col = (ch & 31) * 4;                                           \
            const float* rp = base + (size_t)row * CONV_DIM;                   \
            cpa(dB + (uint32_t)(row * 128 + col) * 4, rp + D_INNER + col, 16); \
            cpa(dC + (uint32_t)(row * 128 + col) * 4,                          \
                rp + D_INNER + D_STATE + col, 16);                             \
        }                                                                      \
        if (tid < 32) {                                                        \
            int row = tid >> 1, col = (tid & 1) * 4;                           \
            cpa(smem_u32(sx + (s) * TB * 8 + row * 8 + col),                   \
                base + (size_t)row * CONV_DIM + h * HEADDIM + pbase + col, 16);\
        }                                                                      \
        if (tid < TB)                                                          \
            cpa(smem_u32(sdt + (s) * TB + tid),                                \
                dt + (size_t)(t0 + tid) * NHEADS + h, 4);                      \
    } while (0)

    float Ah = -expf(A_log[h]);
    float Dh = D_p[h];
    float dsel = (lane == 0) ? Dh : 0.f;

    float a0 = 0.f, a1 = 0.f, a2 = 0.f, a3 = 0.f;
    float b0 = 0.f, b1 = 0.f, b2 = 0.f, b3 = 0.f;

    int rch = lane >> 4;
    int rtt = lane & 15;
    float* rrow = P + (rch * TB + rtt) * 33;

    SSD_STAGE(0, 0);
    asm volatile("cp.async.commit_group;");
    asm volatile("cp.async.wait_group 0;");
    __syncthreads();

    for (int t0 = 0; t0 < LSEQ; t0 += TB) {
        int cur = (t0 >> 4) & 1;
        if (t0 + TB < LSEQ) {
            SSD_STAGE(t0 + TB, cur ^ 1);
        }
        asm volatile("cp.async.commit_group;");

        const float* bB = sB + cur * TB * 128;
        const float* bC = sC + cur * TB * 128;
        const float* bx = sx + cur * TB * 8;
        const float* bd = sdt + cur * TB;

        #pragma unroll
        for (int tt = 0; tt < TB; ++tt) {
            float dtv = bd[tt];
            float e   = __expf(Ah * dtv);
            float4 Bv = *(const float4*)(bB + tt * 128 + lane * 4);
            float4 Cv = *(const float4*)(bC + tt * 128 + lane * 4);
            float x0  = bx[tt * 8 + wib * 2];
            float x1  = bx[tt * 8 + wib * 2 + 1];
            float xd0 = x0 * dtv, xd1 = x1 * dtv;

            a0 = e * a0 + Bv.x * xd0;
            a1 = e * a1 + Bv.y * xd0;
            a2 = e * a2 + Bv.z * xd0;
            a3 = e * a3 + Bv.w * xd0;
            b0 = e * b0 + Bv.x * xd1;
            b1 = e * b1 + Bv.y * xd1;
            b2 = e * b2 + Bv.z * xd1;
            b3 = e * b3 + Bv.w * xd1;

            P[(0 * TB + tt) * 33 + lane] =
                Cv.x * a0 + Cv.y * a1 + Cv.z * a2 + Cv.w * a3 + x0 * dsel;
            P[(1 * TB + tt) * 33 + lane] =
                Cv.x * b0 + Cv.y * b1 + Cv.z * b2 + Cv.w * b3 + x1 * dsel;
        }
        __syncwarp();
        {
            float s0 = 0.f, s1 = 0.f;
            #pragma unroll
            for (int j = 0; j < 32; j += 2) {
                s0 += rrow[j];
                s1 += rrow[j + 1];
            }
            y[(size_t)(t0 + rtt) * D_INNER + h * HEADDIM + p0 + rch] = s0 + s1;
        }
        asm volatile("cp.async.wait_group 0;");
        __syncthreads();
    }
}

// =============================================================================
// fp16 split-precision tensor-core GEMM (NT): C[m,n] = sum_k A[m,k]*B[n,k]
// NPASS: 2 = Ahi*B + Alo*B; 1 = Ahi*B.  BNT: 128/64/32. BM=128, 256 threads.
// lda = row stride; K = extent per z-slice; kof = col offset per blockIdx.z.
// =============================================================================
#define BM 128

#define LDSM4(R, addr) asm volatile( \
    "ldmatrix.sync.aligned.m8n8.x4.shared.b16 {%0,%1,%2,%3}, [%4];" \
    : "=r"((R)[0]),"=r"((R)[1]),"=r"((R)[2]),"=r"((R)[3]) : "r"(addr))
#define LDSM2(R, addr) asm volatile( \
    "ldmatrix.sync.aligned.m8n8.x2.shared.b16 {%0,%1}, [%2];" \
    : "=r"((R)[0]),"=r"((R)[1]) : "r"(addr))

__device__ __forceinline__ void mma_f16(float* acc, const uint32_t* a,
                                        const uint32_t* b) {
    asm volatile(
        "mma.sync.aligned.m16n8k16.row.col.f32.f16.f16.f32 "
        "{%0,%1,%2,%3},{%4,%5,%6,%7},{%8,%9},{%0,%1,%2,%3};"
        : "+f"(acc[0]), "+f"(acc[1]), "+f"(acc[2]), "+f"(acc[3])
        : "r"(a[0]), "r"(a[1]), "r"(a[2]), "r"(a[3]), "r"(b[0]), "r"(b[1]));
}

template<int BNT, int NPASS, int BK>
__global__ __launch_bounds__(256) void gemm_mma(
    const unsigned short* __restrict__ Ahi, const unsigned short* __restrict__ Alo,
    const unsigned short* __restrict__ Bh,
    const float* add, float* __restrict__ C,
    int M, int N, int K, int lda, int kof) {
    constexpr int NI   = BNT / 16;
    constexpr int LDSB = BK + 8;
    constexpr int CHB  = (BNT * BK) / 2048;
    __shared__ unsigned short sAhi[BM * LDSB];
    __shared__ unsigned short sAlo[(NPASS >= 2 ? BM : 8) * LDSB];
    __shared__ unsigned short sBh [BNT * LDSB];

    int z = blockIdx.z;
    Ahi += (size_t)z * kof;
    Alo += (size_t)z * kof;
    Bh  += (size_t)z * kof;
    C   += (size_t)z * M * (size_t)N;

    int tid  = threadIdx.x;
    int wid  = tid >> 5, lane = tid & 31;
    int wm   = wid & 3;
    int wn   = wid >> 2;
    int bm   = blockIdx.x * BM;
    int bn   = blockIdx.y * BNT;

    float acc[2][NI][4];
    #pragma unroll
    for (int i = 0; i < 2; ++i)
        #pragma unroll
        for (int j = 0; j < NI; ++j)
            #pragma unroll
            for (int q = 0; q < 4; ++q) acc[i][j][q] = 0.f;

    int lrA = tid >> 1;
    int lkA = (tid & 1) * (BK / 2);
    constexpr int TPR = 256 / BNT;
    int lrB = tid / TPR;
    int lkB = (tid % TPR) * (CHB * 8);
    int brow  = bn + lrB;
    int browc = (brow < N) ? brow : 0;

    int mrow      = wm * 32 + (lane & 15);
    int acol_half = ((lane >> 4) << 3);
    int nrow_base = wn * (BNT / 2) + (lane & 7);
    int bcol_half = ((lane >> 3) & 1) << 3;

    for (int k0 = 0; k0 < K; k0 += BK) {
        {
            const unsigned short* pa0 = Ahi + (size_t)(bm + lrA) * lda + k0 + lkA;
            #pragma unroll
            for (int c = 0; c < BK / 16; ++c)
                *(uint4*)&sAhi[lrA * LDSB + lkA + c * 8] = *(const uint4*)(pa0 + c * 8);
            if (NPASS >= 2) {
                const unsigned short* pa1 = Alo + (size_t)(bm + lrA) * lda + k0 + lkA;
                #pragma unroll
                for (int c = 0; c < BK / 16; ++c)
                    *(uint4*)&sAlo[lrA * LDSB + lkA + c * 8] = *(const uint4*)(pa1 + c * 8);
            }
            const unsigned short* pb0 = Bh + (size_t)browc * lda + k0 + lkB;
            #pragma unroll
            for (int c = 0; c < CHB; ++c)
                *(uint4*)&sBh[lrB * LDSB + lkB + c * 8] = *(const uint4*)(pb0 + c * 8);
        }
        __syncthreads();

        #pragma unroll
        for (int ks = 0; ks < BK / 16; ++ks) {
            int kb = ks * 16;
            uint32_t ahi[2][4], alo[2][4];
            #pragma unroll
            for (int mi = 0; mi < 2; ++mi) {
                int off = (mrow + mi * 16) * LDSB + kb + acol_half;
                LDSM4(ahi[mi], smem_u32(&sAhi[off]));
                if (NPASS >= 2) LDSM4(alo[mi], smem_u32(&sAlo[off]));
            }
            uint32_t bh[NI][2];
            #pragma unroll
            for (int ni = 0; ni < NI; ++ni) {
                int off = (nrow_base + ni * 8) * LDSB + kb + bcol_half;
                LDSM2(bh[ni], smem_u32(&sBh[off]));
            }
            #pragma unroll
            for (int mi = 0; mi < 2; ++mi)
                #pragma unroll
                for (int ni = 0; ni < NI; ++ni) {
                    mma_f16(acc[mi][ni], ahi[mi], bh[ni]);
                    if (NPASS >= 2) mma_f16(acc[mi][ni], alo[mi], bh[ni]);
                }
        }
        __syncthreads();
    }

    // --- epilogue ---
    int g = lane >> 2, t4 = lane & 3;
    #pragma unroll
    for (int mi = 0; mi < 2; ++mi) {
        int r0 = bm + wm * 32 + mi * 16 + g;
        #pragma unroll
        for (int ni = 0; ni < NI; ++ni) {
            int col = bn + wn * (BNT / 2) + ni * 8 + t4 * 2;
            if (col < N) {
                float2 v0 = make_float2(acc[mi][ni][0], acc[mi][ni][1]);
                float2 v1 = make_float2(acc[mi][ni][2], acc[mi][ni][3]);
                if (add) {
                    float2 a0 = *(const float2*)(add + (size_t)r0 * N + col);
                    float2 a1 = *(const float2*)(add + (size_t)(r0 + 8) * N + col);
                    v0.x += a0.x; v0.y += a0.y;
                    v1.x += a1.x; v1.y += a1.y;
                }
                *(float2*)(C + (size_t)r0 * N + col)       = v0;
                *(float2*)(C + (size_t)(r0 + 8) * N + col) = v1;
            }
        }
    }
}

// ---------------- orchestration ----------------------------------------------
extern "C" void kernel_launch(void* const* d_in, const int* in_sizes, int n_in,
                              void* d_out, int out_size) {
    const int*   ids       = (const int*)  d_in[0];
    const float* emb       = (const float*)d_in[1];
    const float* norm_ws   = (const float*)d_in[2];
    const float* in_ws     = (const float*)d_in[3];
    const float* conv_ws   = (const float*)d_in[4];
    const float* conv_bs   = (const float*)d_in[5];
    const float* dt_biases = (const float*)d_in[6];
    const float* A_logs    = (const float*)d_in[7];
    const float* Ds        = (const float*)d_in[8];
    const float* gnorm_ws  = (const float*)d_in[9];
    const float* out_ws    = (const float*)d_in[10];
    const float* norm_f_w  = (const float*)d_in[11];
    float* out = (float*)d_out;

    float *x, *zx, *xbc, *dtb, *y, *part;
    cudaGetSymbolAddress((void**)&x,    g_x);
    cudaGetSymbolAddress((void**)&zx,   g_zx);
    cudaGetSymbolAddress((void**)&xbc,  g_xbc);
    cudaGetSymbolAddress((void**)&dtb,  g_dt);
    cudaGetSymbolAddress((void**)&y,    g_y);
    cudaGetSymbolAddress((void**)&part, g_part);

    unsigned short *emb_h, *inw_h, *outw_h, *u_hi, *u_lo, *t2_hi, *t2_lo;
    cudaGetSymbolAddress((void**)&emb_h,  g_emb_h);
    cudaGetSymbolAddress((void**)&inw_h,  g_inw_h);
    cudaGetSymbolAddress((void**)&outw_h, g_outw_h);
    cudaGetSymbolAddress((void**)&u_hi,   g_u_hi);
    cudaGetSymbolAddress((void**)&u_lo,   g_u_lo);
    cudaGetSymbolAddress((void**)&t2_hi,  g_t2_hi);
    cudaGetSymbolAddress((void**)&t2_lo,  g_t2_lo);

    cudaFuncSetAttribute(ssd_kernel,
                         cudaFuncAttributeMaxDynamicSharedMemorySize, SSD_SMEM);

    // (0) embed
    embed_kernel<<<(LSEQ * D_MODEL + 255) / 256, 256>>>(ids, emb, x);
    // (1) pre-norm layer 0
    rmsnorm_kernel<<<LSEQ, 256>>>(x, D_MODEL, norm_ws, nullptr, 0,
                                  u_hi, u_lo, D_MODEL);
    // (2) cvt in_ws -> fp16
    {
        int n4 = N_LAYER * D_IN_PROJ * D_MODEL / 4;
        cvt_half_kernel<<<(n4 + 255) / 256, 256>>>(
            (const float4*)in_ws, (__half2*)inw_h, n4);
    }
    // (3) in_proj layer 0
    gemm_mma<128, 2, 32><<<dim3(LSEQ / BM, (D_IN_PROJ + 127) / 128), 256>>>(
        u_hi, u_lo, inw_h, nullptr, zx, LSEQ, D_IN_PROJ, D_MODEL, D_MODEL, 0);
    // (4) conv+dt layer 0
    convdt_kernel<<<(LSEQ * (CONV_DIM + NHEADS) + 255) / 256, 256>>>(
        zx, conv_ws, conv_bs, dt_biases, xbc, dtb);
    // (5) SSD layer 0  <-- profiled slot
    ssd_kernel<<<256, 128, SSD_SMEM>>>(xbc, dtb, A_logs, Ds, y);
    // (6) cvt out_ws -> fp16
    {
        int n4 = N_LAYER * D_MODEL * D_INNER / 4;
        cvt_half_kernel<<<(n4 + 255) / 256, 256>>>(
            (const float4*)out_ws, (__half2*)outw_h, n4);
    }
    // (7) cvt emb -> fp16
    {
        int n4 = VOCAB * D_MODEL / 4;
        cvt_half_kernel<<<(n4 + 255) / 256, 256>>>(
            (const float4*)emb, (__half2*)emb_h, n4);
    }

    for (int i = 0; i < N_LAYER; ++i) {
        if (i > 0) {
            rmsnorm_kernel<<<LSEQ, 256>>>(
                x, D_MODEL, norm_ws + (size_t)i * D_MODEL, nullptr, 0,
                u_hi, u_lo, D_MODEL);
            gemm_mma<128, 2, 32><<<dim3(LSEQ / BM, (D_IN_PROJ + 127) / 128), 256>>>(
                u_hi, u_lo, inw_h + (size_t)i * D_IN_PROJ * D_MODEL,
                nullptr, zx, LSEQ, D_IN_PROJ, D_MODEL, D_MODEL, 0);
            convdt_kernel<<<(LSEQ * (CONV_DIM + NHEADS) + 255) / 256, 256>>>(
                zx, conv_ws + (size_t)i * CONV_DIM * D_CONV,
                conv_bs + (size_t)i * CONV_DIM,
                dt_biases + (size_t)i * NHEADS, xbc, dtb);
            ssd_kernel<<<256, 128, SSD_SMEM>>>(
                xbc, dtb, A_logs + (size_t)i * NHEADS, Ds + (size_t)i * NHEADS, y);
        }
        rmsnorm_kernel<<<LSEQ, 256>>>(
            y, D_INNER, gnorm_ws + (size_t)i * D_INNER,
            zx, D_IN_PROJ, t2_hi, t2_lo, D_INNER);
        // out_proj: split-K (z=4 x K=512) -> partials
        gemm_mma<128, 2, 64><<<dim3(LSEQ / BM, D_MODEL / 128, 4), 256>>>(
            t2_hi, t2_lo, outw_h + (size_t)i * D_MODEL * D_INNER,
            nullptr, part, LSEQ, D_MODEL, 512, D_INNER, 512);
        reduce4_kernel<<<(LSEQ * D_MODEL / 4 + 255) / 256, 256>>>(
            (const float4*)part, (float4*)x, LSEQ * D_MODEL / 4);
    }

    // final norm + fp16 1-pass logits
    rmsnorm_kernel<<<LSEQ, 256>>>(x, D_MODEL, norm_f_w, nullptr, 0,
                                  u_hi, u_lo, D_MODEL);
    gemm_mma<128, 1, 64><<<dim3(LSEQ / BM, (VOCAB + 127) / 128), 256>>>(
        u_hi, u_hi, emb_h, nullptr, out, LSEQ, VOCAB, D_MODEL, D_MODEL, 0);
}

// round 14
// speedup vs baseline: 2.5969x; 1.0525x over previous
#include <cuda_runtime.h>
#include <cuda_bf16.h>
#include <cuda_fp16.h>
#include <cstdint>

#define N_LAYER  4
#define D_MODEL  1024
#define D_STATE  128
#define D_CONV   4
#define HEADDIM  64
#define NHEADS   32
#define D_INNER  2048
#define CONV_DIM 2304         // D_INNER + 2*D_STATE
#define D_IN_PROJ 4384        // 2*D_INNER + 2*D_STATE + NHEADS
#define LSEQ     1024
#define VOCAB    50288
#define EPS      1e-5f

// ---------------- scratch (static device globals; no allocation) -------------
__device__ float g_x  [LSEQ * D_MODEL];
__device__ float g_zx [LSEQ * D_IN_PROJ];
__device__ float g_xbc[LSEQ * CONV_DIM];
__device__ float g_dt [LSEQ * NHEADS];
__device__ float g_y  [LSEQ * D_INNER];
__device__ float g_part[4 * LSEQ * D_MODEL];   // split-K partials (16 MB)

// fp16 storage (raw 16-bit)
__device__ unsigned short g_emb_h [VOCAB * D_MODEL];
__device__ unsigned short g_inw_h [N_LAYER * D_IN_PROJ * D_MODEL];
__device__ unsigned short g_outw_h[N_LAYER * D_MODEL * D_INNER];
__device__ unsigned short g_u_hi  [LSEQ * D_MODEL];
__device__ unsigned short g_u_lo  [LSEQ * D_MODEL];
__device__ unsigned short g_t2_hi [LSEQ * D_INNER];
__device__ unsigned short g_t2_lo [LSEQ * D_INNER];

// ---------------- fp32 -> fp16 (single) ---------------------------------------
__global__ void cvt_half_kernel(const float4* __restrict__ in,
                                __half2* __restrict__ out, int n4) {
    int i = blockIdx.x * blockDim.x + threadIdx.x;
    if (i >= n4) return;
    float4 v = in[i];
    out[2 * i]     = __floats2half2_rn(v.x, v.y);
    out[2 * i + 1] = __floats2half2_rn(v.z, v.w);
}

// ---------------- embedding gather ------------------------------------------
__global__ void embed_kernel(const int* __restrict__ ids,
                             const float* __restrict__ emb,
                             float* __restrict__ x) {
    int idx = blockIdx.x * blockDim.x + threadIdx.x;
    if (idx >= LSEQ * D_MODEL) return;
    int t = idx >> 10;
    int d = idx & 1023;
    x[idx] = emb[(size_t)ids[t] * D_MODEL + d];
}

// ---------------- rmsnorm (optionally gated); outputs fp16 hi/lo -------------
__global__ void rmsnorm_kernel(const float* __restrict__ x, int xs,
                               const float* __restrict__ w,
                               const float* z, int zs,
                               unsigned short* __restrict__ out_hi,
                               unsigned short* __restrict__ out_lo, int D) {
    __shared__ float buf[2048];
    __shared__ float red[8];
    __shared__ float s_scale;
    int t = blockIdx.x;
    int tid = threadIdx.x;

    float ss = 0.f;
    for (int c = tid; c < D; c += blockDim.x) {
        float v = x[(size_t)t * xs + c];
        if (z) {
            float zz = z[(size_t)t * zs + c];
            v *= zz / (1.f + expf(-zz));
        }
        buf[c] = v;
        ss += v * v;
    }
    #pragma unroll
    for (int o = 16; o; o >>= 1) ss += __shfl_xor_sync(0xffffffffu, ss, o);
    if ((tid & 31) == 0) red[tid >> 5] = ss;
    __syncthreads();
    if (tid < 32) {
        float v = (tid < 8) ? red[tid] : 0.f;
        #pragma unroll
        for (int o = 4; o; o >>= 1) v += __shfl_xor_sync(0xffffffffu, v, o);
        if (tid == 0) s_scale = rsqrtf(v / (float)D + EPS);
    }
    __syncthreads();
    float sc = s_scale;
    for (int c = tid; c < D; c += blockDim.x) {
        float v = buf[c] * sc * w[c];
        __half h = __float2half_rn(v);
        __half l = __float2half_rn(v - __half2float(h));
        out_hi[(size_t)t * D + c] = *(unsigned short*)&h;
        out_lo[(size_t)t * D + c] = *(unsigned short*)&l;
    }
}

// ---- fused depthwise conv+silu (c < CONV_DIM) and dt softplus (else) --------
__global__ void convdt_kernel(const float* __restrict__ zx,
                              const float* __restrict__ w,
                              const float* __restrict__ b,
                              const float* __restrict__ dt_bias,
                              float* __restrict__ xbc,
                              float* __restrict__ dt) {
    int idx = blockIdx.x * blockDim.x + threadIdx.x;
    if (idx >= LSEQ * (CONV_DIM + NHEADS)) return;
    int t = idx / (CONV_DIM + NHEADS);
    int c = idx - t * (CONV_DIM + NHEADS);
    if (c < CONV_DIM) {
        float acc = b[c];
        const float* wc = w + c * 4;
        #pragma unroll
        for (int j = 0; j < 4; ++j) {
            int tt = t - 3 + j;
            if (tt >= 0) acc += zx[(size_t)tt * D_IN_PROJ + D_INNER + c] * wc[j];
        }
        xbc[(size_t)t * CONV_DIM + c] = acc / (1.f + expf(-acc));
    } else {
        int h = c - CONV_DIM;
        float v = zx[(size_t)t * D_IN_PROJ + (D_INNER + CONV_DIM) + h] + dt_bias[h];
        dt[t * NHEADS + h] = (v > 20.f) ? v : log1pf(expf(v));
    }
}

// ---- split-K reduction: x += p0 + p1 + p2 + p3 ------------------------------
__global__ void reduce4_kernel(const float4* __restrict__ p,
                               float4* __restrict__ x, int mn4) {
    int i = blockIdx.x * blockDim.x + threadIdx.x;
    if (i >= mn4) return;
    float4 a = p[i];
    float4 b = p[i + mn4];
    float4 c = p[i + 2 * mn4];
    float4 d = p[i + 3 * mn4];
    float4 v = x[i];
    v.x += (a.x + b.x) + (c.x + d.x);
    v.y += (a.y + b.y) + (c.y + d.y);
    v.z += (a.z + b.z) + (c.z + d.z);
    v.w += (a.w + b.w) + (c.w + d.w);
    x[i] = v;
}

__device__ __forceinline__ uint32_t smem_u32(const void* p) {
    return (uint32_t)__cvta_generic_to_shared(p);
}
__device__ __forceinline__ void cpa(uint32_t dst, const void* src, int bytes) {
    if (bytes == 16)
        asm volatile("cp.async.ca.shared.global [%0], [%1], 16;"
                     :: "r"(dst), "l"(src));
    else
        asm volatile("cp.async.ca.shared.global [%0], [%1], 4;"
                     :: "r"(dst), "l"(src));
}

// =============================================================================
// SSD scan, cp.async staged (proven R13 version, unchanged).
// =============================================================================
#define TB 16
#define SSD_SMEM 50816
__global__ __launch_bounds__(128) void ssd_kernel(
    const float* __restrict__ xbc,
    const float* __restrict__ dt,
    const float* __restrict__ A_log,
    const float* __restrict__ D_p,
    float* __restrict__ y) {
    extern __shared__ float sm[];
    float* sB  = sm;                       // [2][TB][128]
    float* sC  = sB + 2 * TB * 128;        // [2][TB][128]
    float* sx  = sC + 2 * TB * 128;        // [2][TB][8]
    float* sdt = sx + 2 * TB * 8;          // [2][TB]
    float* sPa = sdt + 2 * TB;             // [4][2*TB*33]

    int tid  = threadIdx.x;
    int wib  = tid >> 5;
    int lane = tid & 31;
    int h     = blockIdx.x >> 3;
    int pbase = (blockIdx.x & 7) * 8;
    int p0    = pbase + wib * 2;

    float* P = sPa + wib * (2 * TB * 33);

    #define SSD_STAGE(t0, s) do {                                              \
        const float* base = xbc + (size_t)(t0) * CONV_DIM;                     \
        uint32_t dB = smem_u32(sB + (s) * TB * 128);                           \
        uint32_t dC = smem_u32(sC + (s) * TB * 128);                           \
        _Pragma("unroll")                                                      \
        for (int c = 0; c < 4; ++c) {                                          \
            int ch  = tid + c * 128;                                           \
            int row = ch >> 5;                                                 \
            int col = (ch & 31) * 4;                                           \
            const float* rp = base + (size_t)row * CONV_DIM;                   \
            cpa(dB + (uint32_t)(row * 128 + col) * 4, rp + D_INNER + col, 16); \
            cpa(dC + (uint32_t)(row * 128 + col) * 4,                          \
                rp + D_INNER + D_STATE + col, 16);                             \
        }                                                                      \
        if (tid < 32) {                                                        \
            int row = tid >> 1, col = (tid & 1) * 4;                           \
            cpa(smem_u32(sx + (s) * TB * 8 + row * 8 + col),                   \
                base + (size_t)row * CONV_DIM + h * HEADDIM + pbase + col, 16);\
        }                                                                      \
        if (tid < TB)                                                          \
            cpa(smem_u32(sdt + (s) * TB + tid),                                \
                dt + (size_t)(t0 + tid) * NHEADS + h, 4);                      \
    } while (0)

    float Ah = -expf(A_log[h]);
    float Dh = D_p[h];
    float dsel = (lane == 0) ? Dh : 0.f;

    float a0 = 0.f, a1 = 0.f, a2 = 0.f, a3 = 0.f;
    float b0 = 0.f, b1 = 0.f, b2 = 0.f, b3 = 0.f;

    int rch = lane >> 4;
    int rtt = lane & 15;
    float* rrow = P + (rch * TB + rtt) * 33;

    SSD_STAGE(0, 0);
    asm volatile("cp.async.commit_group;");
    asm volatile("cp.async.wait_group 0;");
    __syncthreads();

    for (int t0 = 0; t0 < LSEQ; t0 += TB) {
        int cur = (t0 >> 4) & 1;
        if (t0 + TB < LSEQ) {
            SSD_STAGE(t0 + TB, cur ^ 1);
        }
        asm volatile("cp.async.commit_group;");

        const float* bB = sB + cur * TB * 128;
        const float* bC = sC + cur * TB * 128;
        const float* bx = sx + cur * TB * 8;
        const float* bd = sdt + cur * TB;

        #pragma unroll
        for (int tt = 0; tt < TB; ++tt) {
            float dtv = bd[tt];
            float e   = __expf(Ah * dtv);
            float4 Bv = *(const float4*)(bB + tt * 128 + lane * 4);
            float4 Cv = *(const float4*)(bC + tt * 128 + lane * 4);
            float x0  = bx[tt * 8 + wib * 2];
            float x1  = bx[tt * 8 + wib * 2 + 1];
            float xd0 = x0 * dtv, xd1 = x1 * dtv;

            a0 = e * a0 + Bv.x * xd0;
            a1 = e * a1 + Bv.y * xd0;
            a2 = e * a2 + Bv.z * xd0;
            a3 = e * a3 + Bv.w * xd0;
            b0 = e * b0 + Bv.x * xd1;
            b1 = e * b1 + Bv.y * xd1;
            b2 = e * b2 + Bv.z * xd1;
            b3 = e * b3 + Bv.w * xd1;

            P[(0 * TB + tt) * 33 + lane] =
                Cv.x * a0 + Cv.y * a1 + Cv.z * a2 + Cv.w * a3 + x0 * dsel;
            P[(1 * TB + tt) * 33 + lane] =
                Cv.x * b0 + Cv.y * b1 + Cv.z * b2 + Cv.w * b3 + x1 * dsel;
        }
        __syncwarp();
        {
            float s0 = 0.f, s1 = 0.f;
            #pragma unroll
            for (int j = 0; j < 32; j += 2) {
                s0 += rrow[j];
                s1 += rrow[j + 1];
            }
            y[(size_t)(t0 + rtt) * D_INNER + h * HEADDIM + p0 + rch] = s0 + s1;
        }
        asm volatile("cp.async.wait_group 0;");
        __syncthreads();
    }
}

// =============================================================================
// fp16 split-precision tensor-core GEMM (NT), 2-stage cp.async double buffer.
// Addressing identical to the proven single-buffer kernel; only the staging
// mechanism changed (cp.async into stage s, overlapped one tile ahead).
// =============================================================================
#define BM 128

#define LDSM4(R, addr) asm volatile( \
    "ldmatrix.sync.aligned.m8n8.x4.shared.b16 {%0,%1,%2,%3}, [%4];" \
    : "=r"((R)[0]),"=r"((R)[1]),"=r"((R)[2]),"=r"((R)[3]) : "r"(addr))
#define LDSM2(R, addr) asm volatile( \
    "ldmatrix.sync.aligned.m8n8.x2.shared.b16 {%0,%1}, [%2];" \
    : "=r"((R)[0]),"=r"((R)[1]) : "r"(addr))

__device__ __forceinline__ void mma_f16(float* acc, const uint32_t* a,
                                        const uint32_t* b) {
    asm volatile(
        "mma.sync.aligned.m16n8k16.row.col.f32.f16.f16.f32 "
        "{%0,%1,%2,%3},{%4,%5,%6,%7},{%8,%9},{%0,%1,%2,%3};"
        : "+f"(acc[0]), "+f"(acc[1]), "+f"(acc[2]), "+f"(acc[3])
        : "r"(a[0]), "r"(a[1]), "r"(a[2]), "r"(a[3]), "r"(b[0]), "r"(b[1]));
}

template<int BNT, int NPASS, int BK>
__global__ __launch_bounds__(256) void gemm_mma(
    const unsigned short* __restrict__ Ahi, const unsigned short* __restrict__ Alo,
    const unsigned short* __restrict__ Bh,
    const float* add, float* __restrict__ C,
    int M, int N, int K, int lda, int kof) {
    constexpr int NI    = BNT / 16;
    constexpr int LDSB  = BK + 8;
    constexpr int CHB   = (BNT * BK) / 2048;
    constexpr int A_E   = BM * LDSB;
    constexpr int ALO_E = (NPASS >= 2 ? BM : 0) * LDSB;
    constexpr int B_E   = BNT * LDSB;
    constexpr int STAGE_E = A_E + ALO_E + B_E;

    extern __shared__ unsigned short gsm[];

    int z = blockIdx.z;
    Ahi += (size_t)z * kof;
    Alo += (size_t)z * kof;
    Bh  += (size_t)z * kof;
    C   += (size_t)z * M * (size_t)N;

    int tid  = threadIdx.x;
    int wid  = tid >> 5, lane = tid & 31;
    int wm   = wid & 3;
    int wn   = wid >> 2;
    int bm   = blockIdx.x * BM;
    int bn   = blockIdx.y * BNT;

    float acc[2][NI][4];
    #pragma unroll
    for (int i = 0; i < 2; ++i)
        #pragma unroll
        for (int j = 0; j < NI; ++j)
            #pragma unroll
            for (int q = 0; q < 4; ++q) acc[i][j][q] = 0.f;

    int lrA = tid >> 1;
    int lkA = (tid & 1) * (BK / 2);
    constexpr int TPR = 256 / BNT;
    int lrB = tid / TPR;
    int lkB = (tid % TPR) * (CHB * 8);
    int brow  = bn + lrB;
    int browc = (brow < N) ? brow : 0;

    const unsigned short* pAh = Ahi + (size_t)(bm + lrA) * lda + lkA;
    const unsigned short* pAl = Alo + (size_t)(bm + lrA) * lda + lkA;
    const unsigned short* pB  = Bh  + (size_t)browc * lda + lkB;

    // issue tile kt's loads into stage s
    #define G_ISSUE(kt, s) do {                                                \
        unsigned short* st = gsm + (s) * STAGE_E;                              \
        int ke = (kt) * BK;                                                    \
        _Pragma("unroll")                                                      \
        for (int c = 0; c < BK / 16; ++c)                                      \
            cpa(smem_u32(&st[lrA * LDSB + lkA + c * 8]),                       \
                pAh + ke + c * 8, 16);                                         \
        if (NPASS >= 2) {                                                      \
            _Pragma("unroll")                                                  \
            for (int c = 0; c < BK / 16; ++c)                                  \
                cpa(smem_u32(&st[A_E + lrA * LDSB + lkA + c * 8]),             \
                    pAl + ke + c * 8, 16);                                     \
        }                                                                      \
        _Pragma("unroll")                                                      \
        for (int c = 0; c < CHB; ++c)                                          \
            cpa(smem_u32(&st[A_E + ALO_E + lrB * LDSB + lkB + c * 8]),         \
                pB + ke + c * 8, 16);                                          \
    } while (0)

    int mrow      = wm * 32 + (lane & 15);
    int acol_half = ((lane >> 4) << 3);
    int nrow_base = wn * (BNT / 2) + (lane & 7);
    int bcol_half = ((lane >> 3) & 1) << 3;

    int T = K / BK;
    G_ISSUE(0, 0);
    asm volatile("cp.async.commit_group;");
    if (T > 1) {
        G_ISSUE(1, 1);
        asm volatile("cp.async.commit_group;");
    }

    for (int it = 0; it < T; ++it) {
        if (it + 1 < T) asm volatile("cp.async.wait_group 1;");
        else            asm volatile("cp.async.wait_group 0;");
        __syncthreads();

        unsigned short* st = gsm + (it & 1) * STAGE_E;
        unsigned short* sAhi = st;
        unsigned short* sAlo = st + A_E;
        unsigned short* sBh  = st + A_E + ALO_E;

        #pragma unroll
        for (int ks = 0; ks < BK / 16; ++ks) {
            int kb = ks * 16;
            uint32_t ahi[2][4], alo[2][4];
            #pragma unroll
            for (int mi = 0; mi < 2; ++mi) {
                int off = (mrow + mi * 16) * LDSB + kb + acol_half;
                LDSM4(ahi[mi], smem_u32(&sAhi[off]));
                if (NPASS >= 2) LDSM4(alo[mi], smem_u32(&sAlo[off]));
            }
            uint32_t bh[NI][2];
            #pragma unroll
            for (int ni = 0; ni < NI; ++ni) {
                int off = (nrow_base + ni * 8) * LDSB + kb + bcol_half;
                LDSM2(bh[ni], smem_u32(&sBh[off]));
            }
            #pragma unroll
            for (int mi = 0; mi < 2; ++mi)
                #pragma unroll
                for (int ni = 0; ni < NI; ++ni) {
                    mma_f16(acc[mi][ni], ahi[mi], bh[ni]);
                    if (NPASS >= 2) mma_f16(acc[mi][ni], alo[mi], bh[ni]);
                }
        }
        __syncthreads();
        if (it + 2 < T) {
            G_ISSUE(it + 2, it & 1);
            asm volatile("cp.async.commit_group;");
        }
    }

    // --- epilogue ---
    int g = lane >> 2, t4 = lane & 3;
    #pragma unroll
    for (int mi = 0; mi < 2; ++mi) {
        int r0 = bm + wm * 32 + mi * 16 + g;
        #pragma unroll
        for (int ni = 0; ni < NI; ++ni) {
            int col = bn + wn * (BNT / 2) + ni * 8 + t4 * 2;
            if (col < N) {
                float2 v0 = make_float2(acc[mi][ni][0], acc[mi][ni][1]);
                float2 v1 = make_float2(acc[mi][ni][2], acc[mi][ni][3]);
                if (add) {
                    float2 a0 = *(const float2*)(add + (size_t)r0 * N + col);
                    float2 a1 = *(const float2*)(add + (size_t)(r0 + 8) * N + col);
                    v0.x += a0.x; v0.y += a0.y;
                    v1.x += a1.x; v1.y += a1.y;
                }
                *(float2*)(C + (size_t)r0 * N + col)       = v0;
                *(float2*)(C + (size_t)(r0 + 8) * N + col) = v1;
            }
        }
    }
}

template<int BNT, int NPASS, int BK>
constexpr int gemm_smem() {
    return 2 * (BM * (BK + 8) + (NPASS >= 2 ? BM : 0) * (BK + 8) +
                BNT * (BK + 8)) * 2;
}

// ---------------- orchestration ----------------------------------------------
extern "C" void kernel_launch(void* const* d_in, const int* in_sizes, int n_in,
                              void* d_out, int out_size) {
    const int*   ids       = (const int*)  d_in[0];
    const float* emb       = (const float*)d_in[1];
    const float* norm_ws   = (const float*)d_in[2];
    const float* in_ws     = (const float*)d_in[3];
    const float* conv_ws   = (const float*)d_in[4];
    const float* conv_bs   = (const float*)d_in[5];
    const float* dt_biases = (const float*)d_in[6];
    const float* A_logs    = (const float*)d_in[7];
    const float* Ds        = (const float*)d_in[8];
    const float* gnorm_ws  = (const float*)d_in[9];
    const float* out_ws    = (const float*)d_in[10];
    const float* norm_f_w  = (const float*)d_in[11];
    float* out = (float*)d_out;

    float *x, *zx, *xbc, *dtb, *y, *part;
    cudaGetSymbolAddress((void**)&x,    g_x);
    cudaGetSymbolAddress((void**)&zx,   g_zx);
    cudaGetSymbolAddress((void**)&xbc,  g_xbc);
    cudaGetSymbolAddress((void**)&dtb,  g_dt);
    cudaGetSymbolAddress((void**)&y,    g_y);
    cudaGetSymbolAddress((void**)&part, g_part);

    unsigned short *emb_h, *inw_h, *outw_h, *u_hi, *u_lo, *t2_hi, *t2_lo;
    cudaGetSymbolAddress((void**)&emb_h,  g_emb_h);
    cudaGetSymbolAddress((void**)&inw_h,  g_inw_h);
    cudaGetSymbolAddress((void**)&outw_h, g_outw_h);
    cudaGetSymbolAddress((void**)&u_hi,   g_u_hi);
    cudaGetSymbolAddress((void**)&u_lo,   g_u_lo);
    cudaGetSymbolAddress((void**)&t2_hi,  g_t2_hi);
    cudaGetSymbolAddress((void**)&t2_lo,  g_t2_lo);

    constexpr int SM_IN  = gemm_smem<128, 2, 32>();   // 61,440 B
    constexpr int SM_OUT = gemm_smem<128, 2, 32>();   // 61,440 B
    constexpr int SM_LG  = gemm_smem<128, 1, 64>();   // 73,728 B
    cudaFuncSetAttribute(ssd_kernel,
                         cudaFuncAttributeMaxDynamicSharedMemorySize, SSD_SMEM);
    cudaFuncSetAttribute((const void*)gemm_mma<128, 2, 32>,
                         cudaFuncAttributeMaxDynamicSharedMemorySize, SM_IN);
    cudaFuncSetAttribute((const void*)gemm_mma<128, 1, 64>,
                         cudaFuncAttributeMaxDynamicSharedMemorySize, SM_LG);

    // (0) embed
    embed_kernel<<<(LSEQ * D_MODEL + 255) / 256, 256>>>(ids, emb, x);
    // (1) pre-norm layer 0
    rmsnorm_kernel<<<LSEQ, 256>>>(x, D_MODEL, norm_ws, nullptr, 0,
                                  u_hi, u_lo, D_MODEL);
    // (2) cvt in_ws -> fp16
    {
        int n4 = N_LAYER * D_IN_PROJ * D_MODEL / 4;
        cvt_half_kernel<<<(n4 + 255) / 256, 256>>>(
            (const float4*)in_ws, (__half2*)inw_h, n4);
    }
    // (3) in_proj layer 0  <-- profiled slot
    gemm_mma<128, 2, 32><<<dim3(LSEQ / BM, (D_IN_PROJ + 127) / 128), 256, SM_IN>>>(
        u_hi, u_lo, inw_h, nullptr, zx, LSEQ, D_IN_PROJ, D_MODEL, D_MODEL, 0);
    // (4) conv+dt layer 0
    convdt_kernel<<<(LSEQ * (CONV_DIM + NHEADS) + 255) / 256, 256>>>(
        zx, conv_ws, conv_bs, dt_biases, xbc, dtb);
    // (5) SSD layer 0
    ssd_kernel<<<256, 128, SSD_SMEM>>>(xbc, dtb, A_logs, Ds, y);
    // (6) cvt out_ws -> fp16
    {
        int n4 = N_LAYER * D_MODEL * D_INNER / 4;
        cvt_half_kernel<<<(n4 + 255) / 256, 256>>>(
            (const float4*)out_ws, (__half2*)outw_h, n4);
    }
    // (7) cvt emb -> fp16
    {
        int n4 = VOCAB * D_MODEL / 4;
        cvt_half_kernel<<<(n4 + 255) / 256, 256>>>(
            (const float4*)emb, (__half2*)emb_h, n4);
    }

    for (int i = 0; i < N_LAYER; ++i) {
        if (i > 0) {
            rmsnorm_kernel<<<LSEQ, 256>>>(
                x, D_MODEL, norm_ws + (size_t)i * D_MODEL, nullptr, 0,
                u_hi, u_lo, D_MODEL);
            gemm_mma<128, 2, 32><<<dim3(LSEQ / BM, (D_IN_PROJ + 127) / 128), 256, SM_IN>>>(
                u_hi, u_lo, inw_h + (size_t)i * D_IN_PROJ * D_MODEL,
                nullptr, zx, LSEQ, D_IN_PROJ, D_MODEL, D_MODEL, 0);
            convdt_kernel<<<(LSEQ * (CONV_DIM + NHEADS) + 255) / 256, 256>>>(
                zx, conv_ws + (size_t)i * CONV_DIM * D_CONV,
                conv_bs + (size_t)i * CONV_DIM,
                dt_biases + (size_t)i * NHEADS, xbc, dtb);
            ssd_kernel<<<256, 128, SSD_SMEM>>>(
                xbc, dtb, A_logs + (size_t)i * NHEADS, Ds + (size_t)i * NHEADS, y);
        }
        rmsnorm_kernel<<<LSEQ, 256>>>(
            y, D_INNER, gnorm_ws + (size_t)i * D_INNER,
            zx, D_IN_PROJ, t2_hi, t2_lo, D_INNER);
        // out_proj: split-K (z=4 x K=512), BK=32 double-buffered -> partials
        gemm_mma<128, 2, 32><<<dim3(LSEQ / BM, D_MODEL / 128, 4), 256, SM_OUT>>>(
            t2_hi, t2_lo, outw_h + (size_t)i * D_MODEL * D_INNER,
            nullptr, part, LSEQ, D_MODEL, 512, D_INNER, 512);
        reduce4_kernel<<<(LSEQ * D_MODEL / 4 + 255) / 256, 256>>>(
            (const float4*)part, (float4*)x, LSEQ * D_MODEL / 4);
    }

    // final norm + fp16 1-pass logits (BK=64, double-buffered)
    rmsnorm_kernel<<<LSEQ, 256>>>(x, D_MODEL, norm_f_w, nullptr, 0,
                                  u_hi, u_lo, D_MODEL);
    gemm_mma<128, 1, 64><<<dim3(LSEQ / BM, (VOCAB + 127) / 128), 256, SM_LG>>>(
        u_hi, u_hi, emb_h, nullptr, out, LSEQ, VOCAB, D_MODEL, D_MODEL, 0);
}

// round 16
// speedup vs baseline: 2.8208x; 1.0863x over previous
#include <cuda_runtime.h>
#include <cuda_bf16.h>
#include <cuda_fp16.h>
#include <cstdint>

#define N_LAYER  4
#define D_MODEL  1024
#define D_STATE  128
#define D_CONV   4
#define HEADDIM  64
#define NHEADS   32
#define D_INNER  2048
#define CONV_DIM 2304         // D_INNER + 2*D_STATE
#define D_IN_PROJ 4384        // 2*D_INNER + 2*D_STATE + NHEADS
#define LSEQ     1024
#define VOCAB    50288
#define EPS      1e-5f

// ---------------- scratch (static device globals; no allocation) -------------
__device__ float g_x  [LSEQ * D_MODEL];
__device__ float g_zx [LSEQ * D_IN_PROJ];
__device__ float g_xbc[LSEQ * CONV_DIM];
__device__ float g_dt [LSEQ * NHEADS];
__device__ float g_y  [LSEQ * D_INNER];
__device__ float g_part[4 * LSEQ * D_MODEL];   // split-K partials (16 MB)

// fp16 storage (raw 16-bit)
__device__ unsigned short g_emb_h [VOCAB * D_MODEL];
__device__ unsigned short g_inw_h [N_LAYER * D_IN_PROJ * D_MODEL];
__device__ unsigned short g_outw_h[N_LAYER * D_MODEL * D_INNER];
__device__ unsigned short g_u_hi  [LSEQ * D_MODEL];
__device__ unsigned short g_u_lo  [LSEQ * D_MODEL];
__device__ unsigned short g_t2_hi [LSEQ * D_INNER];
__device__ unsigned short g_t2_lo [LSEQ * D_INNER];

// ---------------- fp32 -> fp16 (single) ---------------------------------------
__global__ void cvt_half_kernel(const float4* __restrict__ in,
                                __half2* __restrict__ out, int n4) {
    int i = blockIdx.x * blockDim.x + threadIdx.x;
    if (i >= n4) return;
    float4 v = in[i];
    out[2 * i]     = __floats2half2_rn(v.x, v.y);
    out[2 * i + 1] = __floats2half2_rn(v.z, v.w);
}

// ---------------- embedding gather ------------------------------------------
__global__ void embed_kernel(const int* __restrict__ ids,
                             const float* __restrict__ emb,
                             float* __restrict__ x) {
    int idx = blockIdx.x * blockDim.x + threadIdx.x;
    if (idx >= LSEQ * D_MODEL) return;
    int t = idx >> 10;
    int d = idx & 1023;
    x[idx] = emb[(size_t)ids[t] * D_MODEL + d];
}

// ---------------- rmsnorm (optionally gated); outputs fp16 hi/lo -------------
__global__ void rmsnorm_kernel(const float* __restrict__ x, int xs,
                               const float* __restrict__ w,
                               const float* z, int zs,
                               unsigned short* __restrict__ out_hi,
                               unsigned short* __restrict__ out_lo, int D) {
    __shared__ float buf[2048];
    __shared__ float red[8];
    __shared__ float s_scale;
    int t = blockIdx.x;
    int tid = threadIdx.x;

    float ss = 0.f;
    for (int c = tid; c < D; c += blockDim.x) {
        float v = x[(size_t)t * xs + c];
        if (z) {
            float zz = z[(size_t)t * zs + c];
            v *= zz / (1.f + expf(-zz));
        }
        buf[c] = v;
        ss += v * v;
    }
    #pragma unroll
    for (int o = 16; o; o >>= 1) ss += __shfl_xor_sync(0xffffffffu, ss, o);
    if ((tid & 31) == 0) red[tid >> 5] = ss;
    __syncthreads();
    if (tid < 32) {
        float v = (tid < 8) ? red[tid] : 0.f;
        #pragma unroll
        for (int o = 4; o; o >>= 1) v += __shfl_xor_sync(0xffffffffu, v, o);
        if (tid == 0) s_scale = rsqrtf(v / (float)D + EPS);
    }
    __syncthreads();
    float sc = s_scale;
    for (int c = tid; c < D; c += blockDim.x) {
        float v = buf[c] * sc * w[c];
        __half h = __float2half_rn(v);
        __half l = __float2half_rn(v - __half2float(h));
        out_hi[(size_t)t * D + c] = *(unsigned short*)&h;
        out_lo[(size_t)t * D + c] = *(unsigned short*)&l;
    }
}

// ---- fused depthwise conv+silu (c < CONV_DIM) and dt softplus (else) --------
__global__ void convdt_kernel(const float* __restrict__ zx,
                              const float* __restrict__ w,
                              const float* __restrict__ b,
                              const float* __restrict__ dt_bias,
                              float* __restrict__ xbc,
                              float* __restrict__ dt) {
    int idx = blockIdx.x * blockDim.x + threadIdx.x;
    if (idx >= LSEQ * (CONV_DIM + NHEADS)) return;
    int t = idx / (CONV_DIM + NHEADS);
    int c = idx - t * (CONV_DIM + NHEADS);
    if (c < CONV_DIM) {
        float acc = b[c];
        const float* wc = w + c * 4;
        #pragma unroll
        for (int j = 0; j < 4; ++j) {
            int tt = t - 3 + j;
            if (tt >= 0) acc += zx[(size_t)tt * D_IN_PROJ + D_INNER + c] * wc[j];
        }
        xbc[(size_t)t * CONV_DIM + c] = acc / (1.f + expf(-acc));
    } else {
        int h = c - CONV_DIM;
        float v = zx[(size_t)t * D_IN_PROJ + (D_INNER + CONV_DIM) + h] + dt_bias[h];
        dt[t * NHEADS + h] = (v > 20.f) ? v : log1pf(expf(v));
    }
}

// ---- split-K reduction: x += p0 + p1 + p2 + p3 ------------------------------
__global__ void reduce4_kernel(const float4* __restrict__ p,
                               float4* __restrict__ x, int mn4) {
    int i = blockIdx.x * blockDim.x + threadIdx.x;
    if (i >= mn4) return;
    float4 a = p[i];
    float4 b = p[i + mn4];
    float4 c = p[i + 2 * mn4];
    float4 d = p[i + 3 * mn4];
    float4 v = x[i];
    v.x += (a.x + b.x) + (c.x + d.x);
    v.y += (a.y + b.y) + (c.y + d.y);
    v.z += (a.z + b.z) + (c.z + d.z);
    v.w += (a.w + b.w) + (c.w + d.w);
    x[i] = v;
}

__device__ __forceinline__ uint32_t smem_u32(const void* p) {
    return (uint32_t)__cvta_generic_to_shared(p);
}
__device__ __forceinline__ void cpa(uint32_t dst, const void* src, int bytes) {
    if (bytes == 16)
        asm volatile("cp.async.ca.shared.global [%0], [%1], 16;"
                     :: "r"(dst), "l"(src));
    else
        asm volatile("cp.async.ca.shared.global [%0], [%1], 4;"
                     :: "r"(dst), "l"(src));
}

// =============================================================================
// SSD scan, cp.async staged (proven R13 version, unchanged).
// =============================================================================
#define TB 16
#define SSD_SMEM 50816
__global__ __launch_bounds__(128) void ssd_kernel(
    const float* __restrict__ xbc,
    const float* __restrict__ dt,
    const float* __restrict__ A_log,
    const float* __restrict__ D_p,
    float* __restrict__ y) {
    extern __shared__ float sm[];
    float* sB  = sm;                       // [2][TB][128]
    float* sC  = sB + 2 * TB * 128;        // [2][TB][128]
    float* sx  = sC + 2 * TB * 128;        // [2][TB][8]
    float* sdt = sx + 2 * TB * 8;          // [2][TB]
    float* sPa = sdt + 2 * TB;             // [4][2*TB*33]

    int tid  = threadIdx.x;
    int wib  = tid >> 5;
    int lane = tid & 31;
    int h     = blockIdx.x >> 3;
    int pbase = (blockIdx.x & 7) * 8;
    int p0    = pbase + wib * 2;

    float* P = sPa + wib * (2 * TB * 33);

    #define SSD_STAGE(t0, s) do {                                              \
        const float* base = xbc + (size_t)(t0) * CONV_DIM;                     \
        uint32_t dB = smem_u32(sB + (s) * TB * 128);                           \
        uint32_t dC = smem_u32(sC + (s) * TB * 128);                           \
        _Pragma("unroll")                                                      \
        for (int c = 0; c < 4; ++c) {                                          \
            int ch  = tid + c * 128;                                           \
            int row = ch >> 5;                                                 \
            int col = (ch & 31) * 4;                                           \
            const float* rp = base + (size_t)row * CONV_DIM;                   \
            cpa(dB + (uint32_t)(row * 128 + col) * 4, rp + D_INNER + col, 16); \
            cpa(dC + (uint32_t)(row * 128 + col) * 4,                          \
                rp + D_INNER + D_STATE + col, 16);                             \
        }                                                                      \
        if (tid < 32) {                                                        \
            int row = tid >> 1, col = (tid & 1) * 4;                           \
            cpa(smem_u32(sx + (s) * TB * 8 + row * 8 + col),                   \
                base + (size_t)row * CONV_DIM + h * HEADDIM + pbase + col, 16);\
        }                                                                      \
        if (tid < TB)                                                          \
            cpa(smem_u32(sdt + (s) * TB + tid),                                \
                dt + (size_t)(t0 + tid) * NHEADS + h, 4);                      \
    } while (0)

    float Ah = -expf(A_log[h]);
    float Dh = D_p[h];
    float dsel = (lane == 0) ? Dh : 0.f;

    float a0 = 0.f, a1 = 0.f, a2 = 0.f, a3 = 0.f;
    float b0 = 0.f, b1 = 0.f, b2 = 0.f, b3 = 0.f;

    int rch = lane >> 4;
    int rtt = lane & 15;
    float* rrow = P + (rch * TB + rtt) * 33;

    SSD_STAGE(0, 0);
    asm volatile("cp.async.commit_group;");
    asm volatile("cp.async.wait_group 0;");
    __syncthreads();

    for (int t0 = 0; t0 < LSEQ; t0 += TB) {
        int cur = (t0 >> 4) & 1;
        if (t0 + TB < LSEQ) {
            SSD_STAGE(t0 + TB, cur ^ 1);
        }
        asm volatile("cp.async.commit_group;");

        const float* bB = sB + cur * TB * 128;
        const float* bC = sC + cur * TB * 128;
        const float* bx = sx + cur * TB * 8;
        const float* bd = sdt + cur * TB;

        #pragma unroll
        for (int tt = 0; tt < TB; ++tt) {
            float dtv = bd[tt];
            float e   = __expf(Ah * dtv);
            float4 Bv = *(const float4*)(bB + tt * 128 + lane * 4);
            float4 Cv = *(const float4*)(bC + tt * 128 + lane * 4);
            float x0  = bx[tt * 8 + wib * 2];
            float x1  = bx[tt * 8 + wib * 2 + 1];
            float xd0 = x0 * dtv, xd1 = x1 * dtv;

            a0 = e * a0 + Bv.x * xd0;
            a1 = e * a1 + Bv.y * xd0;
            a2 = e * a2 + Bv.z * xd0;
            a3 = e * a3 + Bv.w * xd0;
            b0 = e * b0 + Bv.x * xd1;
            b1 = e * b1 + Bv.y * xd1;
            b2 = e * b2 + Bv.z * xd1;
            b3 = e * b3 + Bv.w * xd1;

            P[(0 * TB + tt) * 33 + lane] =
                Cv.x * a0 + Cv.y * a1 + Cv.z * a2 + Cv.w * a3 + x0 * dsel;
            P[(1 * TB + tt) * 33 + lane] =
                Cv.x * b0 + Cv.y * b1 + Cv.z * b2 + Cv.w * b3 + x1 * dsel;
        }
        __syncwarp();
        {
            float s0 = 0.f, s1 = 0.f;
            #pragma unroll
            for (int j = 0; j < 32; j += 2) {
                s0 += rrow[j];
                s1 += rrow[j + 1];
            }
            y[(size_t)(t0 + rtt) * D_INNER + h * HEADDIM + p0 + rch] = s0 + s1;
        }
        asm volatile("cp.async.wait_group 0;");
        __syncthreads();
    }
}

// =============================================================================
// fp16 split-precision tensor-core GEMM (NT), 2-stage cp.async double buffer,
// B fragments via ldmatrix.x4 (2 n-tiles per instruction).
// =============================================================================
#define BM 128

#define LDSM4(R, addr) asm volatile( \
    "ldmatrix.sync.aligned.m8n8.x4.shared.b16 {%0,%1,%2,%3}, [%4];" \
    : "=r"((R)[0]),"=r"((R)[1]),"=r"((R)[2]),"=r"((R)[3]) : "r"(addr))

__device__ __forceinline__ void mma_f16(float* acc, const uint32_t* a,
                                        const uint32_t* b) {
    asm volatile(
        "mma.sync.aligned.m16n8k16.row.col.f32.f16.f16.f32 "
        "{%0,%1,%2,%3},{%4,%5,%6,%7},{%8,%9},{%0,%1,%2,%3};"
        : "+f"(acc[0]), "+f"(acc[1]), "+f"(acc[2]), "+f"(acc[3])
        : "r"(a[0]), "r"(a[1]), "r"(a[2]), "r"(a[3]), "r"(b[0]), "r"(b[1]));
}

template<int BNT, int NPASS, int BK>
__global__ __launch_bounds__(256) void gemm_mma(
    const unsigned short* __restrict__ Ahi, const unsigned short* __restrict__ Alo,
    const unsigned short* __restrict__ Bh,
    const float* add, float* __restrict__ C,
    int M, int N, int K, int lda, int kof) {
    constexpr int NI    = BNT / 16;
    constexpr int LDSB  = BK + 8;
    constexpr int CHB   = (BNT * BK) / 2048;
    constexpr int A_E   = BM * LDSB;
    constexpr int ALO_E = (NPASS >= 2 ? BM : 0) * LDSB;
    constexpr int B_E   = BNT * LDSB;
    constexpr int STAGE_E = A_E + ALO_E + B_E;

    extern __shared__ unsigned short gsm[];

    int z = blockIdx.z;
    Ahi += (size_t)z * kof;
    Alo += (size_t)z * kof;
    Bh  += (size_t)z * kof;
    C   += (size_t)z * M * (size_t)N;

    int tid  = threadIdx.x;
    int wid  = tid >> 5, lane = tid & 31;
    int wm   = wid & 3;
    int wn   = wid >> 2;
    int bm   = blockIdx.x * BM;
    int bn   = blockIdx.y * BNT;

    float acc[2][NI][4];
    #pragma unroll
    for (int i = 0; i < 2; ++i)
        #pragma unroll
        for (int j = 0; j < NI; ++j)
            #pragma unroll
            for (int q = 0; q < 4; ++q) acc[i][j][q] = 0.f;

    int lrA = tid >> 1;
    int lkA = (tid & 1) * (BK / 2);
    constexpr int TPR = 256 / BNT;
    int lrB = tid / TPR;
    int lkB = (tid % TPR) * (CHB * 8);
    int brow  = bn + lrB;
    int browc = (brow < N) ? brow : 0;

    const unsigned short* pAh = Ahi + (size_t)(bm + lrA) * lda + lkA;
    const unsigned short* pAl = Alo + (size_t)(bm + lrA) * lda + lkA;
    const unsigned short* pB  = Bh  + (size_t)browc * lda + lkB;

    // issue tile kt's loads into stage s
    #define G_ISSUE(kt, s) do {                                                \
        unsigned short* st = gsm + (s) * STAGE_E;                              \
        int ke = (kt) * BK;                                                    \
        _Pragma("unroll")                                                      \
        for (int c = 0; c < BK / 16; ++c)                                      \
            cpa(smem_u32(&st[lrA * LDSB + lkA + c * 8]),                       \
                pAh + ke + c * 8, 16);                                         \
        if (NPASS >= 2) {                                                      \
            _Pragma("unroll")                                                  \
            for (int c = 0; c < BK / 16; ++c)                                  \
                cpa(smem_u32(&st[A_E + lrA * LDSB + lkA + c * 8]),             \
                    pAl + ke + c * 8, 16);                                     \
        }                                                                      \
        _Pragma("unroll")                                                      \
        for (int c = 0; c < CHB; ++c)                                          \
            cpa(smem_u32(&st[A_E + ALO_E + lrB * LDSB + lkB + c * 8]),         \
                pB + ke + c * 8, 16);                                          \
    } while (0)

    int mrow      = wm * 32 + (lane & 15);
    int acol_half = ((lane >> 4) << 3);
    // B x4 mapping: lanes 0-7 (r,kb), 8-15 (r,kb+8), 16-23 (r+8,kb), 24-31 (r+8,kb+8)
    int brow4     = wn * (BNT / 2) + (lane & 7) + ((lane >> 4) << 3);
    int bcol_half = ((lane >> 3) & 1) << 3;

    int T = K / BK;
    G_ISSUE(0, 0);
    asm volatile("cp.async.commit_group;");
    if (T > 1) {
        G_ISSUE(1, 1);
        asm volatile("cp.async.commit_group;");
    }

    for (int it = 0; it < T; ++it) {
        if (it + 1 < T) asm volatile("cp.async.wait_group 1;");
        else            asm volatile("cp.async.wait_group 0;");
        __syncthreads();

        unsigned short* st = gsm + (it & 1) * STAGE_E;
        unsigned short* sAhi = st;
        unsigned short* sAlo = st + A_E;
        unsigned short* sBh  = st + A_E + ALO_E;

        #pragma unroll
        for (int ks = 0; ks < BK / 16; ++ks) {
            int kb = ks * 16;
            uint32_t ahi[2][4], alo[2][4];
            #pragma unroll
            for (int mi = 0; mi < 2; ++mi) {
                int off = (mrow + mi * 16) * LDSB + kb + acol_half;
                LDSM4(ahi[mi], smem_u32(&sAhi[off]));
                if (NPASS >= 2) LDSM4(alo[mi], smem_u32(&sAlo[off]));
            }
            uint32_t bh[NI][2];
            #pragma unroll
            for (int n2 = 0; n2 < NI / 2; ++n2) {
                int off = (brow4 + n2 * 16) * LDSB + kb + bcol_half;
                uint32_t r4[4];
                LDSM4(r4, smem_u32(&sBh[off]));
                bh[2 * n2][0]     = r4[0]; bh[2 * n2][1]     = r4[1];
                bh[2 * n2 + 1][0] = r4[2]; bh[2 * n2 + 1][1] = r4[3];
            }
            #pragma unroll
            for (int mi = 0; mi < 2; ++mi)
                #pragma unroll
                for (int ni = 0; ni < NI; ++ni) {
                    mma_f16(acc[mi][ni], ahi[mi], bh[ni]);
                    if (NPASS >= 2) mma_f16(acc[mi][ni], alo[mi], bh[ni]);
                }
        }
        __syncthreads();
        if (it + 2 < T) {
            G_ISSUE(it + 2, it & 1);
            asm volatile("cp.async.commit_group;");
        }
    }

    // --- epilogue ---
    int g = lane >> 2, t4 = lane & 3;
    #pragma unroll
    for (int mi = 0; mi < 2; ++mi) {
        int r0 = bm + wm * 32 + mi * 16 + g;
        #pragma unroll
        for (int ni = 0; ni < NI; ++ni) {
            int col = bn + wn * (BNT / 2) + ni * 8 + t4 * 2;
            if (col < N) {
                float2 v0 = make_float2(acc[mi][ni][0], acc[mi][ni][1]);
                float2 v1 = make_float2(acc[mi][ni][2], acc[mi][ni][3]);
                if (add) {
                    float2 a0 = *(const float2*)(add + (size_t)r0 * N + col);
                    float2 a1 = *(const float2*)(add + (size_t)(r0 + 8) * N + col);
                    v0.x += a0.x; v0.y += a0.y;
                    v1.x += a1.x; v1.y += a1.y;
                }
                *(float2*)(C + (size_t)r0 * N + col)       = v0;
                *(float2*)(C + (size_t)(r0 + 8) * N + col) = v1;
            }
        }
    }
}

template<int BNT, int NPASS, int BK>
constexpr int gemm_smem() {
    return 2 * (BM * (BK + 8) + (NPASS >= 2 ? BM : 0) * (BK + 8) +
                BNT * (BK + 8)) * 2;
}

// ---------------- orchestration ----------------------------------------------
extern "C" void kernel_launch(void* const* d_in, const int* in_sizes, int n_in,
                              void* d_out, int out_size) {
    const int*   ids       = (const int*)  d_in[0];
    const float* emb       = (const float*)d_in[1];
    const float* norm_ws   = (const float*)d_in[2];
    const float* in_ws     = (const float*)d_in[3];
    const float* conv_ws   = (const float*)d_in[4];
    const float* conv_bs   = (const float*)d_in[5];
    const float* dt_biases = (const float*)d_in[6];
    const float* A_logs    = (const float*)d_in[7];
    const float* Ds        = (const float*)d_in[8];
    const float* gnorm_ws  = (const float*)d_in[9];
    const float* out_ws    = (const float*)d_in[10];
    const float* norm_f_w  = (const float*)d_in[11];
    float* out = (float*)d_out;

    float *x, *zx, *xbc, *dtb, *y, *part;
    cudaGetSymbolAddress((void**)&x,    g_x);
    cudaGetSymbolAddress((void**)&zx,   g_zx);
    cudaGetSymbolAddress((void**)&xbc,  g_xbc);
    cudaGetSymbolAddress((void**)&dtb,  g_dt);
    cudaGetSymbolAddress((void**)&y,    g_y);
    cudaGetSymbolAddress((void**)&part, g_part);

    unsigned short *emb_h, *inw_h, *outw_h, *u_hi, *u_lo, *t2_hi, *t2_lo;
    cudaGetSymbolAddress((void**)&emb_h,  g_emb_h);
    cudaGetSymbolAddress((void**)&inw_h,  g_inw_h);
    cudaGetSymbolAddress((void**)&outw_h, g_outw_h);
    cudaGetSymbolAddress((void**)&u_hi,   g_u_hi);
    cudaGetSymbolAddress((void**)&u_lo,   g_u_lo);
    cudaGetSymbolAddress((void**)&t2_hi,  g_t2_hi);
    cudaGetSymbolAddress((void**)&t2_lo,  g_t2_lo);

    constexpr int SM_IN  = gemm_smem<128, 2, 32>();   // 61,440 B
    constexpr int SM_LG  = gemm_smem<128, 1, 64>();   // 73,728 B
    cudaFuncSetAttribute(ssd_kernel,
                         cudaFuncAttributeMaxDynamicSharedMemorySize, SSD_SMEM);
    cudaFuncSetAttribute((const void*)gemm_mma<128, 2, 32>,
                         cudaFuncAttributeMaxDynamicSharedMemorySize, SM_IN);
    cudaFuncSetAttribute((const void*)gemm_mma<128, 1, 64>,
                         cudaFuncAttributeMaxDynamicSharedMemorySize, SM_LG);

    // (0) embed
    embed_kernel<<<(LSEQ * D_MODEL + 255) / 256, 256>>>(ids, emb, x);
    // (1) pre-norm layer 0
    rmsnorm_kernel<<<LSEQ, 256>>>(x, D_MODEL, norm_ws, nullptr, 0,
                                  u_hi, u_lo, D_MODEL);
    // (2) cvt in_ws -> fp16
    {
        int n4 = N_LAYER * D_IN_PROJ * D_MODEL / 4;
        cvt_half_kernel<<<(n4 + 255) / 256, 256>>>(
            (const float4*)in_ws, (__half2*)inw_h, n4);
    }
    // (3) in_proj layer 0  <-- profiled slot
    gemm_mma<128, 2, 32><<<dim3(LSEQ / BM, (D_IN_PROJ + 127) / 128), 256, SM_IN>>>(
        u_hi, u_lo, inw_h, nullptr, zx, LSEQ, D_IN_PROJ, D_MODEL, D_MODEL, 0);
    // (4) conv+dt layer 0
    convdt_kernel<<<(LSEQ * (CONV_DIM + NHEADS) + 255) / 256, 256>>>(
        zx, conv_ws, conv_bs, dt_biases, xbc, dtb);
    // (5) SSD layer 0
    ssd_kernel<<<256, 128, SSD_SMEM>>>(xbc, dtb, A_logs, Ds, y);
    // (6) cvt out_ws -> fp16
    {
        int n4 = N_LAYER * D_MODEL * D_INNER / 4;
        cvt_half_kernel<<<(n4 + 255) / 256, 256>>>(
            (const float4*)out_ws, (__half2*)outw_h, n4);
    }
    // (7) cvt emb -> fp16
    {
        int n4 = VOCAB * D_MODEL / 4;
        cvt_half_kernel<<<(n4 + 255) / 256, 256>>>(
            (const float4*)emb, (__half2*)emb_h, n4);
    }

    for (int i = 0; i < N_LAYER; ++i) {
        if (i > 0) {
            rmsnorm_kernel<<<LSEQ, 256>>>(
                x, D_MODEL, norm_ws + (size_t)i * D_MODEL, nullptr, 0,
                u_hi, u_lo, D_MODEL);
            gemm_mma<128, 2, 32><<<dim3(LSEQ / BM, (D_IN_PROJ + 127) / 128), 256, SM_IN>>>(
                u_hi, u_lo, inw_h + (size_t)i * D_IN_PROJ * D_MODEL,
                nullptr, zx, LSEQ, D_IN_PROJ, D_MODEL, D_MODEL, 0);
            convdt_kernel<<<(LSEQ * (CONV_DIM + NHEADS) + 255) / 256, 256>>>(
                zx, conv_ws + (size_t)i * CONV_DIM * D_CONV,
                conv_bs + (size_t)i * CONV_DIM,
                dt_biases + (size_t)i * NHEADS, xbc, dtb);
            ssd_kernel<<<256, 128, SSD_SMEM>>>(
                xbc, dtb, A_logs + (size_t)i * NHEADS, Ds + (size_t)i * NHEADS, y);
        }
        rmsnorm_kernel<<<LSEQ, 256>>>(
            y, D_INNER, gnorm_ws + (size_t)i * D_INNER,
            zx, D_IN_PROJ, t2_hi, t2_lo, D_INNER);
        // out_proj: split-K (z=4 x K=512), BK=32 double-buffered -> partials
        gemm_mma<128, 2, 32><<<dim3(LSEQ / BM, D_MODEL / 128, 4), 256, SM_IN>>>(
            t2_hi, t2_lo, outw_h + (size_t)i * D_MODEL * D_INNER,
            nullptr, part, LSEQ, D_MODEL, 512, D_INNER, 512);
        reduce4_kernel<<<(LSEQ * D_MODEL / 4 + 255) / 256, 256>>>(
            (const float4*)part, (float4*)x, LSEQ * D_MODEL / 4);
    }

    // final norm + fp16 1-pass logits (BK=64, double-buffered)
    rmsnorm_kernel<<<LSEQ, 256>>>(x, D_MODEL, norm_f_w, nullptr, 0,
                                  u_hi, u_lo, D_MODEL);
    gemm_mma<128, 1, 64><<<dim3(LSEQ / BM, (VOCAB + 127) / 128), 256, SM_LG>>>(
        u_hi, u_hi, emb_h, nullptr, out, LSEQ, VOCAB, D_MODEL, D_MODEL, 0);
}